// round 1
// baseline (speedup 1.0000x reference)
#include <cuda_runtime.h>

// Problem constants
#define NB 2
#define NS 2048
#define ND 1024
#define NH 16
#define DH 64
#define NM (NB*NS)        // 4096 rows (B*S)
#define NQKV (3*ND)       // 3072
#define ATTN_SCALE 0.03125f   // D^-0.5 = 1024^-0.5

typedef unsigned long long u64;

// ---------------- scratch (device globals; no allocations allowed) ----------
__device__ float g_Q[NB*NH*NS*DH];    // [B,H,S,dh]
__device__ float g_K[NB*NH*NS*DH];
__device__ float g_V[NB*NH*NS*DH];
__device__ float g_ctx[(size_t)NM*ND];// [B,S,D] attention context
__device__ int   g_mask_mode;         // 0=uint8, 1=int32, 2=float32

// ---------------- packed f32x2 helpers --------------------------------------
__device__ __forceinline__ u64 pack_dup(float x){
    u64 r; asm("mov.b64 %0, {%1, %1};" : "=l"(r) : "f"(x)); return r;
}
__device__ __forceinline__ float2 unpack2(u64 v){
    float2 r; asm("mov.b64 {%0, %1}, %2;" : "=f"(r.x), "=f"(r.y) : "l"(v)); return r;
}
__device__ __forceinline__ void fma2(u64& c, u64 a, u64 b){
    asm("fma.rn.f32x2 %0, %1, %2, %0;" : "+l"(c) : "l"(a), "l"(b));
}

// ---------------- mask dtype detector ---------------------------------------
// Reads the first 4096 bytes (safe under every candidate dtype: bool buffer is
// exactly 4096 bytes). float32 0/1 words -> mode 2; int32 0/1 words -> mode 1;
// otherwise packed bytes -> mode 0. Deterministic for fixed input.
__global__ void detect_mask_kernel(const unsigned int* __restrict__ w){
    __shared__ int not_f, not_i;
    int t = threadIdx.x;
    if (t == 0){ not_f = 0; not_i = 0; }
    __syncthreads();
    unsigned v = w[t];                 // 1024 threads -> 1024 words = 4096 B
    if (v != 0u && v != 0x3F800000u) atomicExch(&not_f, 1);
    if (v > 1u)                      atomicExch(&not_i, 1);
    __syncthreads();
    if (t == 0) g_mask_mode = (not_f == 0) ? 2 : ((not_i == 0) ? 1 : 0);
}

// ---------------- NT GEMM: C[M,N] = A[M,K] * B[N,K]^T + bias ----------------
// 128x128 block tile, BK=16, 256 threads, 8x8 per-thread tile via fma.rn.f32x2.
// A tile stored in smem as duplicated pairs (As2[k][m] = {a,a}) so the inner
// loop needs ZERO pack instructions: 6 LDS.128 + 32 FMA2 per k-step.
// QKV_EPI=1: A=arg, scatter epilogue into g_Q/g_K/g_V.
// QKV_EPI=0: A=g_ctx, plain store into Cout.
template<int QKV_EPI>
__global__ void __launch_bounds__(256) gemm_nt(
    const float* __restrict__ Aarg, const float* __restrict__ Bmat,
    const float* __restrict__ bias, float* __restrict__ Cout, int Ndim)
{
    const int Kdim = ND; // 1024 for both GEMMs
    const float* A = QKV_EPI ? Aarg : g_ctx;

    __shared__ __align__(16) u64   As2[16][128];  // 16 KB (dup pairs)
    __shared__ __align__(16) float Bs [16][128];  // 8 KB

    const int tid  = threadIdx.x;
    const int tx   = tid & 15, ty = tid >> 4;
    const int rowA = tid >> 2;          // 0..63
    const int c4f  = (tid & 3) * 4;     // k offset 0/4/8/12

    const float* Ab = A    + (size_t)blockIdx.y * 128 * Kdim;
    const float* Bb = Bmat + (size_t)blockIdx.x * 128 * Kdim;

    u64 acc[8][4];
    #pragma unroll
    for (int i = 0; i < 8; i++)
        #pragma unroll
        for (int j = 0; j < 4; j++) acc[i][j] = 0ull;

    float4 pa0, pa1, pb0, pb1;

    // first tile load + smem store
    pa0 = *(const float4*)(Ab + (size_t)rowA       * Kdim + c4f);
    pa1 = *(const float4*)(Ab + (size_t)(rowA + 64)* Kdim + c4f);
    pb0 = *(const float4*)(Bb + (size_t)rowA       * Kdim + c4f);
    pb1 = *(const float4*)(Bb + (size_t)(rowA + 64)* Kdim + c4f);
    As2[c4f+0][rowA]    = pack_dup(pa0.x); As2[c4f+1][rowA]    = pack_dup(pa0.y);
    As2[c4f+2][rowA]    = pack_dup(pa0.z); As2[c4f+3][rowA]    = pack_dup(pa0.w);
    As2[c4f+0][rowA+64] = pack_dup(pa1.x); As2[c4f+1][rowA+64] = pack_dup(pa1.y);
    As2[c4f+2][rowA+64] = pack_dup(pa1.z); As2[c4f+3][rowA+64] = pack_dup(pa1.w);
    Bs[c4f+0][rowA]    = pb0.x; Bs[c4f+1][rowA]    = pb0.y;
    Bs[c4f+2][rowA]    = pb0.z; Bs[c4f+3][rowA]    = pb0.w;
    Bs[c4f+0][rowA+64] = pb1.x; Bs[c4f+1][rowA+64] = pb1.y;
    Bs[c4f+2][rowA+64] = pb1.z; Bs[c4f+3][rowA+64] = pb1.w;
    __syncthreads();

    for (int k0 = 0; k0 < Kdim; k0 += 16) {
        const bool more = (k0 + 16) < Kdim;
        if (more) {  // register prefetch of next tile (hides gmem latency)
            pa0 = *(const float4*)(Ab + (size_t)rowA       * Kdim + k0 + 16 + c4f);
            pa1 = *(const float4*)(Ab + (size_t)(rowA + 64)* Kdim + k0 + 16 + c4f);
            pb0 = *(const float4*)(Bb + (size_t)rowA       * Kdim + k0 + 16 + c4f);
            pb1 = *(const float4*)(Bb + (size_t)(rowA + 64)* Kdim + k0 + 16 + c4f);
        }
        #pragma unroll
        for (int kk = 0; kk < 16; kk++) {
            ulonglong2 a0 = *(const ulonglong2*)&As2[kk][ty*8 + 0];
            ulonglong2 a1 = *(const ulonglong2*)&As2[kk][ty*8 + 2];
            ulonglong2 a2 = *(const ulonglong2*)&As2[kk][ty*8 + 4];
            ulonglong2 a3 = *(const ulonglong2*)&As2[kk][ty*8 + 6];
            ulonglong2 b0 = *(const ulonglong2*)&Bs[kk][tx*8 + 0];
            ulonglong2 b1 = *(const ulonglong2*)&Bs[kk][tx*8 + 4];
            u64 av[8] = {a0.x, a0.y, a1.x, a1.y, a2.x, a2.y, a3.x, a3.y};
            u64 bv[4] = {b0.x, b0.y, b1.x, b1.y};
            #pragma unroll
            for (int i = 0; i < 8; i++) {
                #pragma unroll
                for (int j = 0; j < 4; j++) fma2(acc[i][j], av[i], bv[j]);
            }
        }
        if (more) {
            __syncthreads();
            As2[c4f+0][rowA]    = pack_dup(pa0.x); As2[c4f+1][rowA]    = pack_dup(pa0.y);
            As2[c4f+2][rowA]    = pack_dup(pa0.z); As2[c4f+3][rowA]    = pack_dup(pa0.w);
            As2[c4f+0][rowA+64] = pack_dup(pa1.x); As2[c4f+1][rowA+64] = pack_dup(pa1.y);
            As2[c4f+2][rowA+64] = pack_dup(pa1.z); As2[c4f+3][rowA+64] = pack_dup(pa1.w);
            Bs[c4f+0][rowA]    = pb0.x; Bs[c4f+1][rowA]    = pb0.y;
            Bs[c4f+2][rowA]    = pb0.z; Bs[c4f+3][rowA]    = pb0.w;
            Bs[c4f+0][rowA+64] = pb1.x; Bs[c4f+1][rowA+64] = pb1.y;
            Bs[c4f+2][rowA+64] = pb1.z; Bs[c4f+3][rowA+64] = pb1.w;
            __syncthreads();
        }
    }

    // ---- epilogue ----
    const int n0 = blockIdx.x * 128 + tx * 8;
    float bz[8];
    #pragma unroll
    for (int j = 0; j < 8; j++) bz[j] = bias[n0 + j];

    float* dst = Cout; int h = 0, d0 = 0;
    if (QKV_EPI) {
        // qkv column n -> head n/192, part (n%192)/64 (q/k/v), d = n%64.
        // tx*8-aligned 8-column group never crosses a 64 boundary.
        h = n0 / 192;
        int rem  = n0 - h * 192;
        int part = rem >> 6;
        d0 = rem & 63;
        dst = (part == 0) ? g_Q : (part == 1 ? g_K : g_V);
    }

    #pragma unroll
    for (int i = 0; i < 8; i++) {
        int m = blockIdx.y * 128 + ty * 8 + i;
        float c[8];
        #pragma unroll
        for (int j = 0; j < 4; j++) {
            float2 f = unpack2(acc[i][j]);
            c[2*j]   = f.x + bz[2*j];
            c[2*j+1] = f.y + bz[2*j+1];
        }
        if (QKV_EPI) {
            int bb = m >> 11, s = m & (NS - 1);
            size_t base = (((size_t)bb * NH + h) * NS + s) * DH + d0;
            *(float4*)&dst[base]     = make_float4(c[0], c[1], c[2], c[3]);
            *(float4*)&dst[base + 4] = make_float4(c[4], c[5], c[6], c[7]);
        } else {
            size_t base = (size_t)m * Ndim + n0;
            *(float4*)&Cout[base]     = make_float4(c[0], c[1], c[2], c[3]);
            *(float4*)&Cout[base + 4] = make_float4(c[4], c[5], c[6], c[7]);
        }
    }
}

// ---------------- attention -------------------------------------------------
// One block per (b, h, 64-query tile), 256 threads (16x16), 64-key chunks.
// Logits are <= ~1 so no online max is needed: p = exp(s) directly (masked /
// far-ALiBi terms underflow to exactly 0). Both inner GEMMs use f32x2 with
// duplicated-pair smem operands (Qt2, Pt2) -> zero pack instructions.
#define ATTN_SMEM_BYTES ((4096 + 4096) * 8 + (4096 + 4096) * 4 + 64 * 4)

__global__ void __launch_bounds__(256) attn_kernel(const void* __restrict__ maskp)
{
    extern __shared__ __align__(16) char smem_raw[];
    u64*   Qt2 = (u64*)smem_raw;            // [d][q] dup pairs, 64*64
    u64*   Pt2 = Qt2 + 4096;                // [k][q] dup pairs
    float* Kt  = (float*)(Pt2 + 4096);      // [d][k]
    float* Vs  = Kt + 4096;                 // [k][d]
    float* mk  = Vs + 4096;                 // [64] additive mask (0 / -1e30)

    const int tid = threadIdx.x;
    const int tx = tid & 15, ty = tid >> 4;
    const int qb = blockIdx.x, h = blockIdx.y, b = blockIdx.z;

    const size_t headbase = ((size_t)(b * NH + h)) * NS * DH;
    const float* Qg = g_Q + headbase + (size_t)qb * 64 * DH;
    const float* Kg = g_K + headbase;
    const float* Vg = g_V + headbase;
    const float slope = exp2f(-0.5f * (float)(h + 1));  // start^(h+1), start=2^-0.5
    const int mode = g_mask_mode;

    // load Q tile -> Qt2 transposed duplicated
    #pragma unroll
    for (int t = 0; t < 4; t++) {
        int idx = tid + 256 * t;
        int row = idx >> 4;
        int c4  = (idx & 15) * 4;
        float4 v = *(const float4*)&Qg[row * 64 + c4];
        Qt2[(c4+0)*64 + row] = pack_dup(v.x);
        Qt2[(c4+1)*64 + row] = pack_dup(v.y);
        Qt2[(c4+2)*64 + row] = pack_dup(v.z);
        Qt2[(c4+3)*64 + row] = pack_dup(v.w);
    }

    u64 o2[4][2];
    #pragma unroll
    for (int r = 0; r < 4; r++) { o2[r][0] = 0ull; o2[r][1] = 0ull; }
    float dn[4] = {0.f, 0.f, 0.f, 0.f};
    const int qg0 = qb * 64 + ty * 4;

    for (int k0 = 0; k0 < NS; k0 += 64) {
        __syncthreads();  // also orders Qt2 writes (1st iter) / prior PV reads
        #pragma unroll
        for (int t = 0; t < 4; t++) {
            int idx = tid + 256 * t;
            int row = idx >> 4;
            int c4  = (idx & 15) * 4;
            float4 kv = *(const float4*)&Kg[(k0 + row) * 64 + c4];
            Kt[(c4+0)*64 + row] = kv.x;
            Kt[(c4+1)*64 + row] = kv.y;
            Kt[(c4+2)*64 + row] = kv.z;
            Kt[(c4+3)*64 + row] = kv.w;
            *(float4*)&Vs[row * 64 + c4] = *(const float4*)&Vg[(k0 + row) * 64 + c4];
        }
        if (tid < 64) {
            int kg = k0 + tid;
            bool mv;
            if      (mode == 0) mv = ((const unsigned char*)maskp)[b * NS + kg] != 0;
            else if (mode == 1) mv = ((const int*)maskp)[b * NS + kg] != 0;
            else                mv = ((const float*)maskp)[b * NS + kg] != 0.f;
            mk[tid] = mv ? 0.f : -1e30f;
        }
        __syncthreads();

        // S = Q K^T (4x4 per-thread tile, pairs along k)
        u64 s2[4][2];
        #pragma unroll
        for (int r = 0; r < 4; r++) { s2[r][0] = 0ull; s2[r][1] = 0ull; }
        #pragma unroll 16
        for (int d = 0; d < 64; d++) {
            ulonglong2 qa0 = *(const ulonglong2*)&Qt2[d*64 + ty*4];
            ulonglong2 qa1 = *(const ulonglong2*)&Qt2[d*64 + ty*4 + 2];
            ulonglong2 kb  = *(const ulonglong2*)&Kt [d*64 + tx*4];
            fma2(s2[0][0], qa0.x, kb.x); fma2(s2[0][1], qa0.x, kb.y);
            fma2(s2[1][0], qa0.y, kb.x); fma2(s2[1][1], qa0.y, kb.y);
            fma2(s2[2][0], qa1.x, kb.x); fma2(s2[2][1], qa1.x, kb.y);
            fma2(s2[3][0], qa1.y, kb.x); fma2(s2[3][1], qa1.y, kb.y);
        }

        // p = exp(scale*s + alibi + mask); write P transposed/duplicated
        #pragma unroll
        for (int r = 0; r < 4; r++) {
            const float qd = (float)(qg0 + r);
            #pragma unroll
            for (int j = 0; j < 2; j++) {
                float2 sv = unpack2(s2[r][j]);
                int kc = tx * 4 + 2 * j;
                float kf = (float)(k0 + kc);
                float p0 = __expf(sv.x * ATTN_SCALE - slope * fabsf(qd - kf)        + mk[kc]);
                float p1 = __expf(sv.y * ATTN_SCALE - slope * fabsf(qd - (kf + 1.f)) + mk[kc + 1]);
                dn[r] += p0 + p1;
                Pt2[(kc    ) * 64 + (ty*4 + r)] = pack_dup(p0);
                Pt2[(kc + 1) * 64 + (ty*4 + r)] = pack_dup(p1);
            }
        }
        __syncthreads();

        // O += P V (pairs along d)
        #pragma unroll 16
        for (int kk = 0; kk < 64; kk++) {
            ulonglong2 pv0 = *(const ulonglong2*)&Pt2[kk*64 + ty*4];
            ulonglong2 pv1 = *(const ulonglong2*)&Pt2[kk*64 + ty*4 + 2];
            ulonglong2 vv  = *(const ulonglong2*)&Vs [kk*64 + tx*4];
            fma2(o2[0][0], pv0.x, vv.x); fma2(o2[0][1], pv0.x, vv.y);
            fma2(o2[1][0], pv0.y, vv.x); fma2(o2[1][1], pv0.y, vv.y);
            fma2(o2[2][0], pv1.x, vv.x); fma2(o2[2][1], pv1.x, vv.y);
            fma2(o2[3][0], pv1.y, vv.x); fma2(o2[3][1], pv1.y, vv.y);
        }
    }

    // reduce denominators over the 16 lanes sharing a query row (half-warp)
    #pragma unroll
    for (int m_ = 1; m_ < 16; m_ <<= 1) {
        #pragma unroll
        for (int r = 0; r < 4; r++) dn[r] += __shfl_xor_sync(0xffffffffu, dn[r], m_);
    }

    #pragma unroll
    for (int r = 0; r < 4; r++) {
        float inv = 1.f / dn[r];
        float2 f0 = unpack2(o2[r][0]);
        float2 f1 = unpack2(o2[r][1]);
        int qg = qg0 + r;
        size_t base = ((size_t)b * NS + qg) * ND + h * 64 + tx * 4;
        *(float4*)&g_ctx[base] = make_float4(f0.x*inv, f0.y*inv, f1.x*inv, f1.y*inv);
    }
}

// ---------------- launch ----------------------------------------------------
extern "C" void kernel_launch(void* const* d_in, const int* in_sizes, int n_in,
                              void* d_out, int out_size)
{
    const float* x     = (const float*)d_in[0];  // [2,2048,1024]
    const void*  mask  = d_in[1];                // [2,2048] bool (dtype detected)
    const float* Wqkv  = (const float*)d_in[2];  // [3072,1024]
    const float* bqkv  = (const float*)d_in[3];  // [3072]
    const float* Wproj = (const float*)d_in[4];  // [1024,1024]
    const float* bproj = (const float*)d_in[5];  // [1024]
    float* out = (float*)d_out;                  // [4096,1024]

    (void)in_sizes; (void)n_in; (void)out_size;

    cudaFuncSetAttribute(attn_kernel,
                         cudaFuncAttributeMaxDynamicSharedMemorySize,
                         ATTN_SMEM_BYTES);

    detect_mask_kernel<<<1, 1024>>>((const unsigned int*)mask);

    // QKV projection, scattered into g_Q/g_K/g_V [B,H,S,dh]
    gemm_nt<1><<<dim3(NQKV/128, NM/128), 256>>>(x, Wqkv, bqkv, nullptr, NQKV);

    // attention -> g_ctx [B,S,D]
    attn_kernel<<<dim3(NS/64, NH, NB), 256, ATTN_SMEM_BYTES>>>(mask);

    // output projection -> d_out
    gemm_nt<0><<<dim3(ND/128, NM/128), 256>>>(nullptr, Wproj, bproj, out, ND);
}

// round 3
// speedup vs baseline: 3.0210x; 3.0210x over previous
#include <cuda_runtime.h>
#include <cuda_bf16.h>

// Problem constants
#define NB 2
#define NS 2048
#define ND 1024
#define NH 16
#define DH 64
#define NM (NB*NS)        // 4096
#define NQKV (3*ND)       // 3072
#define ATTN_SCALE 0.03125f

typedef unsigned long long u64;
typedef unsigned int u32;

// ---------------- scratch (device globals) -----------------------------------
__device__ int g_mask_mode;
// split hi/lo bf16 buffers
__device__ __nv_bfloat16 g_xh[(size_t)NM*ND],   g_xl[(size_t)NM*ND];
__device__ __nv_bfloat16 g_wqh[(size_t)NQKV*ND],g_wql[(size_t)NQKV*ND];
__device__ __nv_bfloat16 g_wph[(size_t)ND*ND],  g_wpl[(size_t)ND*ND];
__device__ __nv_bfloat16 g_ch[(size_t)NM*ND],   g_cl[(size_t)NM*ND];
// Q/K/V hi/lo, layout [B,H,S,DH]
#define QKV_ELEMS (NB*NH*NS*DH)
__device__ __nv_bfloat16 g_Qh[QKV_ELEMS], g_Ql[QKV_ELEMS];
__device__ __nv_bfloat16 g_Kh[QKV_ELEMS], g_Kl[QKV_ELEMS];
__device__ __nv_bfloat16 g_Vh[QKV_ELEMS], g_Vl[QKV_ELEMS];

// ---------------- PTX helpers ------------------------------------------------
__device__ __forceinline__ u32 smem_u32(const void* p){
    u32 a; asm("{ .reg .u64 t; cvta.to.shared.u64 t, %1; cvt.u32.u64 %0, t; }" : "=r"(a) : "l"(p));
    return a;
}
__device__ __forceinline__ void ldsm4(u32* r, u32 addr){
    asm volatile("ldmatrix.sync.aligned.m8n8.x4.shared.b16 {%0,%1,%2,%3}, [%4];"
        : "=r"(r[0]),"=r"(r[1]),"=r"(r[2]),"=r"(r[3]) : "r"(addr));
}
__device__ __forceinline__ void ldsm2(u32* r, u32 addr){
    asm volatile("ldmatrix.sync.aligned.m8n8.x2.shared.b16 {%0,%1}, [%2];"
        : "=r"(r[0]),"=r"(r[1]) : "r"(addr));
}
__device__ __forceinline__ void ldsm2t(u32* r, u32 addr){
    asm volatile("ldmatrix.sync.aligned.m8n8.x2.trans.shared.b16 {%0,%1}, [%2];"
        : "=r"(r[0]),"=r"(r[1]) : "r"(addr));
}
__device__ __forceinline__ void mma_bf16(float* c, const u32* a, const u32* b){
    asm volatile("mma.sync.aligned.m16n8k16.row.col.f32.bf16.bf16.f32 "
        "{%0,%1,%2,%3}, {%4,%5,%6,%7}, {%8,%9}, {%0,%1,%2,%3};"
        : "+f"(c[0]),"+f"(c[1]),"+f"(c[2]),"+f"(c[3])
        : "r"(a[0]),"r"(a[1]),"r"(a[2]),"r"(a[3]), "r"(b[0]),"r"(b[1]));
}
// split two floats into packed (hi,hi) and (lo,lo) bf16x2 words
__device__ __forceinline__ void split_pack(float a, float b, u32& hi, u32& lo){
    __nv_bfloat16 ha = __float2bfloat16(a), hb = __float2bfloat16(b);
    float ra = a - __bfloat162float(ha), rb = b - __bfloat162float(hb);
    __nv_bfloat162 H; H.x = ha; H.y = hb;
    __nv_bfloat162 L; L.x = __float2bfloat16(ra); L.y = __float2bfloat16(rb);
    hi = *(u32*)&H; lo = *(u32*)&L;
}

// ---------------- mask dtype detector ----------------------------------------
__global__ void detect_mask_kernel(const unsigned int* __restrict__ w){
    __shared__ int not_f, not_i;
    int t = threadIdx.x;
    if (t == 0){ not_f = 0; not_i = 0; }
    __syncthreads();
    unsigned v = w[t];
    if (v != 0u && v != 0x3F800000u) atomicExch(&not_f, 1);
    if (v > 1u)                      atomicExch(&not_i, 1);
    __syncthreads();
    if (t == 0) g_mask_mode = (not_f == 0) ? 2 : ((not_i == 0) ? 1 : 0);
}

// ---------------- fp32 -> (hi,lo) bf16 split ---------------------------------
__global__ void __launch_bounds__(256) split_kernel(
    const float* __restrict__ src, __nv_bfloat16* __restrict__ hi,
    __nv_bfloat16* __restrict__ lo, int n4)
{
    int i = blockIdx.x * 256 + threadIdx.x;
    if (i >= n4) return;
    float4 v = ((const float4*)src)[i];
    u32 h0, l0, h1, l1;
    split_pack(v.x, v.y, h0, l0);
    split_pack(v.z, v.w, h1, l1);
    ((uint2*)hi)[i] = make_uint2(h0, h1);
    ((uint2*)lo)[i] = make_uint2(l0, l1);
}

// ---------------- HMMA NT GEMM with split-bf16 -------------------------------
// C[M,N] = (Ah+Al)(Bh+Bl)^T + bias  (dropping AlBl).
// Block 128x128, 8 warps (2m x 4n), warp tile 64x32, BK=32, 2-stage smem.
#define GSTRIDE 40                 // bf16 per smem row (80B; conflict-free ldmatrix)
#define GMAT (128*GSTRIDE*2)       // 10240 B per matrix tile
#define GSTAGE (4*GMAT)            // Ah,Al,Bh,Bl
#define GSMEM  (2*GSTAGE)          // 81920 B

template<int QKV_EPI>
__global__ void __launch_bounds__(256) gemm_mma(
    const __nv_bfloat16* __restrict__ Ah, const __nv_bfloat16* __restrict__ Al,
    const __nv_bfloat16* __restrict__ Bh, const __nv_bfloat16* __restrict__ Bl,
    const float* __restrict__ bias, float* __restrict__ Cout)
{
    extern __shared__ __align__(16) char sm[];
    const u32 smb = smem_u32(sm);
    const int tid = threadIdx.x, lane = tid & 31, wid = tid >> 5;
    const int wm = wid >> 2, wn = wid & 3;

    const __nv_bfloat16* APh = Ah + (size_t)blockIdx.y * 128 * ND;
    const __nv_bfloat16* APl = Al + (size_t)blockIdx.y * 128 * ND;
    const __nv_bfloat16* BPh = Bh + (size_t)blockIdx.x * 128 * ND;
    const __nv_bfloat16* BPl = Bl + (size_t)blockIdx.x * 128 * ND;

    float C[4][4][4];
    #pragma unroll
    for (int i = 0; i < 4; i++)
        #pragma unroll
        for (int j = 0; j < 4; j++)
            #pragma unroll
            for (int e = 0; e < 4; e++) C[i][j][e] = 0.f;

    uint4 rg[8];

#define G_LDG(k0) do { \
    _Pragma("unroll") \
    for (int t = 0; t < 2; t++) { \
        int u_ = tid + 256*t; int row = u_ >> 2; int cb = (u_ & 3) * 8; \
        size_t go = (size_t)row * ND + (k0) + cb; \
        rg[0+t] = *(const uint4*)(APh + go); rg[2+t] = *(const uint4*)(APl + go); \
        rg[4+t] = *(const uint4*)(BPh + go); rg[6+t] = *(const uint4*)(BPl + go); \
    } } while(0)

#define G_STS(st) do { \
    _Pragma("unroll") \
    for (int t = 0; t < 2; t++) { \
        int u_ = tid + 256*t; int row = u_ >> 2; int cb = (u_ & 3) * 8; \
        u32 so = (st) + (u32)((row*GSTRIDE + cb)*2); \
        *(uint4*)(sm + so + 0*GMAT) = rg[0+t]; *(uint4*)(sm + so + 1*GMAT) = rg[2+t]; \
        *(uint4*)(sm + so + 2*GMAT) = rg[4+t]; *(uint4*)(sm + so + 3*GMAT) = rg[6+t]; \
    } } while(0)

    G_LDG(0);
    G_STS(0u);
    __syncthreads();

    for (int c = 0; c < ND/32; c++) {
        const u32 st = (u32)(c & 1) * GSTAGE;
        if (c + 1 < ND/32) G_LDG((c + 1) * 32);

        #pragma unroll
        for (int kk = 0; kk < 2; kk++) {
            u32 ah[4][4], al[4][4], bh_[4][2], bl_[4][2];
            #pragma unroll
            for (int i = 0; i < 4; i++) {
                u32 row = wm*64 + i*16 + (lane & 15);
                u32 col = kk*16 + (lane >> 4) * 8;
                u32 off = (row*GSTRIDE + col) * 2;
                ldsm4(ah[i], smb + st + 0*GMAT + off);
                ldsm4(al[i], smb + st + 1*GMAT + off);
            }
            #pragma unroll
            for (int j = 0; j < 4; j++) {
                u32 row = wn*32 + j*8 + (lane & 7);
                u32 col = kk*16 + ((lane >> 3) & 1) * 8;
                u32 off = (row*GSTRIDE + col) * 2;
                ldsm2(bh_[j], smb + st + 2*GMAT + off);
                ldsm2(bl_[j], smb + st + 3*GMAT + off);
            }
            #pragma unroll
            for (int i = 0; i < 4; i++)
                #pragma unroll
                for (int j = 0; j < 4; j++) {
                    mma_bf16(C[i][j], ah[i], bh_[j]);
                    mma_bf16(C[i][j], al[i], bh_[j]);
                    mma_bf16(C[i][j], ah[i], bl_[j]);
                }
        }
        if (c + 1 < ND/32) {
            __syncthreads();
            G_STS((u32)((c + 1) & 1) * GSTAGE);
            __syncthreads();
        }
    }
#undef G_LDG
#undef G_STS

    // ---- epilogue ----
    const int mb = blockIdx.y*128 + wm*64;
    const int nb = blockIdx.x*128 + wn*32;
    #pragma unroll
    for (int i = 0; i < 4; i++) {
        #pragma unroll
        for (int j = 0; j < 4; j++) {
            int n = nb + j*8 + 2*(lane & 3);
            float2 bz = *(const float2*)(bias + n);
            int m0 = mb + i*16 + (lane >> 2);
            int m1 = m0 + 8;
            float v00 = C[i][j][0] + bz.x, v01 = C[i][j][1] + bz.y;
            float v10 = C[i][j][2] + bz.x, v11 = C[i][j][3] + bz.y;
            if (QKV_EPI) {
                int h = n / 192, rem = n - h*192, part = rem >> 6, d = rem & 63;
                __nv_bfloat16* dh_ = (part==0) ? g_Qh : (part==1 ? g_Kh : g_Vh);
                __nv_bfloat16* dl_ = (part==0) ? g_Ql : (part==1 ? g_Kl : g_Vl);
                u32 hi, lo;
                {
                    int bb = m0 >> 11, ss = m0 & (NS-1);
                    size_t base = (((size_t)bb*NH + h)*NS + ss)*DH + d;
                    split_pack(v00, v01, hi, lo);
                    *(u32*)&dh_[base] = hi; *(u32*)&dl_[base] = lo;
                }
                {
                    int bb = m1 >> 11, ss = m1 & (NS-1);
                    size_t base = (((size_t)bb*NH + h)*NS + ss)*DH + d;
                    split_pack(v10, v11, hi, lo);
                    *(u32*)&dh_[base] = hi; *(u32*)&dl_[base] = lo;
                }
            } else {
                *(float2*)&Cout[(size_t)m0*ND + n] = make_float2(v00, v01);
                *(float2*)&Cout[(size_t)m1*ND + n] = make_float2(v10, v11);
            }
        }
    }
}

// ---------------- attention (HMMA, split-bf16, flash-style) ------------------
// Block = (b, h, 64-q tile), 4 warps (128 thr), each warp owns 16 q rows.
// Per 64-key chunk: S = (Qh+Ql)(Kh+Kl)^T (3 passes) -> softmax in frags
// -> P split hi/lo packed directly into A-frags -> O += (Ph+Pl)(Vh+Vl) (3 passes).
#define ASTR 72                    // bf16 per smem row (144B)
#define AQH 0
#define AQL (64*ASTR*2)            // 9216
#define AKH (2*64*ASTR*2)
#define AKL (3*64*ASTR*2)
#define AVH (4*64*ASTR*2)
#define AVL (5*64*ASTR*2)
#define AMK (6*64*ASTR*2)          // 55296
#define ASMEM (AMK + 64*4)

__global__ void __launch_bounds__(128) attn_mma(const void* __restrict__ maskp)
{
    extern __shared__ __align__(16) char sm[];
    const u32 smb = smem_u32(sm);
    float* mk = (float*)(sm + AMK);
    const int tid = threadIdx.x, lane = tid & 31, wid = tid >> 5;
    const int qb = blockIdx.x, h = blockIdx.y, b = blockIdx.z;

    const size_t hb = ((size_t)(b*NH + h)) * NS * DH;
    const __nv_bfloat16* Qhp = g_Qh + hb + (size_t)qb*64*DH;
    const __nv_bfloat16* Qlp = g_Ql + hb + (size_t)qb*64*DH;
    const __nv_bfloat16* Khp = g_Kh + hb;
    const __nv_bfloat16* Klp = g_Kl + hb;
    const __nv_bfloat16* Vhp = g_Vh + hb;
    const __nv_bfloat16* Vlp = g_Vl + hb;

    const float slope = exp2f(-0.5f * (float)(h + 1));
    const int mode = g_mask_mode;

    // load Q tile to smem
    #pragma unroll
    for (int t = 0; t < 4; t++) {
        int u_ = tid + 128*t; int row = u_ >> 3; int cb = (u_ & 7) * 8;
        u32 so = (u32)((row*ASTR + cb) * 2);
        *(uint4*)(sm + AQH + so) = *(const uint4*)(Qhp + row*DH + cb);
        *(uint4*)(sm + AQL + so) = *(const uint4*)(Qlp + row*DH + cb);
    }
    __syncthreads();

    // Q fragments (persistent): 4 k-steps, hi & lo
    u32 qh[4][4], ql[4][4];
    #pragma unroll
    for (int kk = 0; kk < 4; kk++) {
        u32 row = wid*16 + (lane & 15);
        u32 col = kk*16 + (lane >> 4) * 8;
        u32 off = (row*ASTR + col) * 2;
        ldsm4(qh[kk], smb + AQH + off);
        ldsm4(ql[kk], smb + AQL + off);
    }

    float O[8][4];
    #pragma unroll
    for (int j = 0; j < 8; j++)
        #pragma unroll
        for (int e = 0; e < 4; e++) O[j][e] = 0.f;
    float dn0 = 0.f, dn1 = 0.f;
    const float qf0 = (float)(qb*64 + wid*16 + (lane >> 2));
    const float qf1 = qf0 + 8.f;

    for (int k0 = 0; k0 < NS; k0 += 64) {
        __syncthreads();
        #pragma unroll
        for (int t = 0; t < 4; t++) {
            int u_ = tid + 128*t; int row = u_ >> 3; int cb = (u_ & 7) * 8;
            size_t go = (size_t)(k0 + row)*DH + cb;
            u32 so = (u32)((row*ASTR + cb) * 2);
            *(uint4*)(sm + AKH + so) = *(const uint4*)(Khp + go);
            *(uint4*)(sm + AKL + so) = *(const uint4*)(Klp + go);
            *(uint4*)(sm + AVH + so) = *(const uint4*)(Vhp + go);
            *(uint4*)(sm + AVL + so) = *(const uint4*)(Vlp + go);
        }
        if (tid < 64) {
            int kg = k0 + tid;
            bool mv;
            if      (mode == 0) mv = ((const unsigned char*)maskp)[b*NS + kg] != 0;
            else if (mode == 1) mv = ((const int*)maskp)[b*NS + kg] != 0;
            else                mv = ((const float*)maskp)[b*NS + kg] != 0.f;
            mk[tid] = mv ? 0.f : -1e30f;
        }
        __syncthreads();

        // S = Q K^T   (8 n-frags of 8 keys)
        float S[8][4];
        #pragma unroll
        for (int j = 0; j < 8; j++)
            #pragma unroll
            for (int e = 0; e < 4; e++) S[j][e] = 0.f;
        #pragma unroll
        for (int kk = 0; kk < 4; kk++) {
            #pragma unroll
            for (int j = 0; j < 8; j++) {
                u32 row = j*8 + (lane & 7);
                u32 col = kk*16 + ((lane >> 3) & 1) * 8;
                u32 off = (row*ASTR + col) * 2;
                u32 kb[2], kl2[2];
                ldsm2(kb,  smb + AKH + off);
                ldsm2(kl2, smb + AKL + off);
                mma_bf16(S[j], qh[kk], kb);
                mma_bf16(S[j], ql[kk], kb);
                mma_bf16(S[j], qh[kk], kl2);
            }
        }

        // softmax + pack P into A-fragments (hi & lo)
        u32 aPh[4][4], aPl[4][4];
        #pragma unroll
        for (int j = 0; j < 8; j++) {
            int kc = j*8 + 2*(lane & 3);
            float kf = (float)(k0 + kc);
            float m0 = mk[kc], m1 = mk[kc + 1];
            float p0 = __expf(S[j][0]*ATTN_SCALE - slope*fabsf(qf0 - kf)       + m0);
            float p1 = __expf(S[j][1]*ATTN_SCALE - slope*fabsf(qf0 - kf - 1.f) + m1);
            float p2 = __expf(S[j][2]*ATTN_SCALE - slope*fabsf(qf1 - kf)       + m0);
            float p3 = __expf(S[j][3]*ATTN_SCALE - slope*fabsf(qf1 - kf - 1.f) + m1);
            dn0 += p0 + p1;
            dn1 += p2 + p3;
            u32 h01, l01, h23, l23;
            split_pack(p0, p1, h01, l01);
            split_pack(p2, p3, h23, l23);
            int t = j >> 1, o = (j & 1) * 2;
            aPh[t][o]   = h01; aPl[t][o]   = l01;   // rows r0, this 8-key block
            aPh[t][o+1] = h23; aPl[t][o+1] = l23;   // rows r1
        }

        // O += P V   (V via ldmatrix.trans from [k][d])
        #pragma unroll
        for (int j = 0; j < 8; j++) {
            #pragma unroll
            for (int t = 0; t < 4; t++) {
                u32 row = t*16 + (lane & 15);
                u32 off = (row*ASTR + j*8) * 2;
                u32 vh_[2], vl_[2];
                ldsm2t(vh_, smb + AVH + off);
                ldsm2t(vl_, smb + AVL + off);
                mma_bf16(O[j], aPh[t], vh_);
                mma_bf16(O[j], aPl[t], vh_);
                mma_bf16(O[j], aPh[t], vl_);
            }
        }
    }

    // reduce denominators across the 4 lanes of each quad (cols partition)
    #pragma unroll
    for (int m_ = 1; m_ < 4; m_ <<= 1) {
        dn0 += __shfl_xor_sync(0xffffffffu, dn0, m_);
        dn1 += __shfl_xor_sync(0xffffffffu, dn1, m_);
    }
    const float inv0 = 1.f / dn0, inv1 = 1.f / dn1;

    // write ctx as hi/lo bf16: [b, s, h*64 + d]
    const int q0 = qb*64 + wid*16 + (lane >> 2);
    const int q1 = q0 + 8;
    #pragma unroll
    for (int j = 0; j < 8; j++) {
        int d = h*64 + j*8 + 2*(lane & 3);
        u32 hi, lo;
        split_pack(O[j][0]*inv0, O[j][1]*inv0, hi, lo);
        size_t b0 = ((size_t)b*NS + q0)*ND + d;
        *(u32*)&g_ch[b0] = hi; *(u32*)&g_cl[b0] = lo;
        split_pack(O[j][2]*inv1, O[j][3]*inv1, hi, lo);
        size_t b1 = ((size_t)b*NS + q1)*ND + d;
        *(u32*)&g_ch[b1] = hi; *(u32*)&g_cl[b1] = lo;
    }
}

// ---------------- launch -----------------------------------------------------
extern "C" void kernel_launch(void* const* d_in, const int* in_sizes, int n_in,
                              void* d_out, int out_size)
{
    const float* x     = (const float*)d_in[0];  // [2,2048,1024]
    const void*  mask  = d_in[1];                // [2,2048] bool
    const float* Wqkv  = (const float*)d_in[2];  // [3072,1024]
    const float* bqkv  = (const float*)d_in[3];  // [3072]
    const float* Wproj = (const float*)d_in[4];  // [1024,1024]
    const float* bproj = (const float*)d_in[5];  // [1024]
    float* out = (float*)d_out;                  // [4096,1024]

    (void)in_sizes; (void)n_in; (void)out_size;

    static bool inited = false;
    static __nv_bfloat16 *p_xh,*p_xl,*p_wqh,*p_wql,*p_wph,*p_wpl;
    if (!inited) {
        cudaFuncSetAttribute(gemm_mma<1>, cudaFuncAttributeMaxDynamicSharedMemorySize, GSMEM);
        cudaFuncSetAttribute(gemm_mma<0>, cudaFuncAttributeMaxDynamicSharedMemorySize, GSMEM);
        cudaFuncSetAttribute(attn_mma,    cudaFuncAttributeMaxDynamicSharedMemorySize, ASMEM);
        cudaGetSymbolAddress((void**)&p_xh, g_xh);   cudaGetSymbolAddress((void**)&p_xl, g_xl);
        cudaGetSymbolAddress((void**)&p_wqh, g_wqh); cudaGetSymbolAddress((void**)&p_wql, g_wql);
        cudaGetSymbolAddress((void**)&p_wph, g_wph); cudaGetSymbolAddress((void**)&p_wpl, g_wpl);
        inited = true;
    }

    detect_mask_kernel<<<1, 1024>>>((const unsigned int*)mask);

    // split fp32 inputs/weights into hi/lo bf16
    split_kernel<<<(NM*ND/4 + 255)/256, 256>>>(x, p_xh, p_xl, NM*ND/4);
    split_kernel<<<(NQKV*ND/4 + 255)/256, 256>>>(Wqkv, p_wqh, p_wql, NQKV*ND/4);
    split_kernel<<<(ND*ND/4 + 255)/256, 256>>>(Wproj, p_wph, p_wpl, ND*ND/4);

    // QKV projection -> g_Q/K/V (hi/lo), scattered
    gemm_mma<1><<<dim3(NQKV/128, NM/128), 256, GSMEM>>>(
        p_xh, p_xl, p_wqh, p_wql, bqkv, nullptr);

    // attention -> g_ch/g_cl (hi/lo ctx)
    attn_mma<<<dim3(NS/64, NH, NB), 128, ASMEM>>>(mask);

    // output projection -> d_out (fp32)
    {
        static __nv_bfloat16 *p_ch = nullptr, *p_cl = nullptr;
        if (!p_ch) { cudaGetSymbolAddress((void**)&p_ch, g_ch); cudaGetSymbolAddress((void**)&p_cl, g_cl); }
        gemm_mma<0><<<dim3(ND/128, NM/128), 256, GSMEM>>>(
            p_ch, p_cl, p_wph, p_wpl, bproj, out);
    }
}

// round 4
// speedup vs baseline: 3.2803x; 1.0858x over previous
#include <cuda_runtime.h>
#include <cuda_bf16.h>

// Problem constants
#define NB 2
#define NS 2048
#define ND 1024
#define NH 16
#define DH 64
#define NM (NB*NS)        // 4096
#define NQKV (3*ND)       // 3072
#define ATTN_SCALE 0.03125f

typedef unsigned long long u64;
typedef unsigned int u32;

// ---------------- scratch (device globals) -----------------------------------
__device__ int g_mask_mode;
__device__ __nv_bfloat16 g_xh[(size_t)NM*ND],   g_xl[(size_t)NM*ND];
__device__ __nv_bfloat16 g_wqh[(size_t)NQKV*ND],g_wql[(size_t)NQKV*ND];
__device__ __nv_bfloat16 g_wph[(size_t)ND*ND],  g_wpl[(size_t)ND*ND];
__device__ __nv_bfloat16 g_ch[(size_t)NM*ND],   g_cl[(size_t)NM*ND];
#define QKV_ELEMS (NB*NH*NS*DH)
__device__ __nv_bfloat16 g_Qh[QKV_ELEMS], g_Ql[QKV_ELEMS];
__device__ __nv_bfloat16 g_Kh[QKV_ELEMS], g_Kl[QKV_ELEMS];
__device__ __nv_bfloat16 g_Vh[QKV_ELEMS], g_Vl[QKV_ELEMS];

// ---------------- PTX helpers ------------------------------------------------
__device__ __forceinline__ u32 smem_u32(const void* p){
    u32 a; asm("{ .reg .u64 t; cvta.to.shared.u64 t, %1; cvt.u32.u64 %0, t; }" : "=r"(a) : "l"(p));
    return a;
}
__device__ __forceinline__ void ldsm4(u32* r, u32 addr){
    asm volatile("ldmatrix.sync.aligned.m8n8.x4.shared.b16 {%0,%1,%2,%3}, [%4];"
        : "=r"(r[0]),"=r"(r[1]),"=r"(r[2]),"=r"(r[3]) : "r"(addr));
}
__device__ __forceinline__ void ldsm4t(u32* r, u32 addr){
    asm volatile("ldmatrix.sync.aligned.m8n8.x4.trans.shared.b16 {%0,%1,%2,%3}, [%4];"
        : "=r"(r[0]),"=r"(r[1]),"=r"(r[2]),"=r"(r[3]) : "r"(addr));
}
__device__ __forceinline__ void mma_bf16(float* c, const u32* a, const u32* b){
    asm volatile("mma.sync.aligned.m16n8k16.row.col.f32.bf16.bf16.f32 "
        "{%0,%1,%2,%3}, {%4,%5,%6,%7}, {%8,%9}, {%0,%1,%2,%3};"
        : "+f"(c[0]),"+f"(c[1]),"+f"(c[2]),"+f"(c[3])
        : "r"(a[0]),"r"(a[1]),"r"(a[2]),"r"(a[3]), "r"(b[0]),"r"(b[1]));
}
__device__ __forceinline__ void split_pack(float a, float b, u32& hi, u32& lo){
    __nv_bfloat16 ha = __float2bfloat16(a), hb = __float2bfloat16(b);
    float ra = a - __bfloat162float(ha), rb = b - __bfloat162float(hb);
    __nv_bfloat162 H; H.x = ha; H.y = hb;
    __nv_bfloat162 L; L.x = __float2bfloat16(ra); L.y = __float2bfloat16(rb);
    hi = *(u32*)&H; lo = *(u32*)&L;
}
__device__ __forceinline__ void cp16(u32 dst, const void* src){
    asm volatile("cp.async.cg.shared.global [%0], [%1], 16;" :: "r"(dst), "l"(src));
}
#define CP_COMMIT() asm volatile("cp.async.commit_group;" ::: "memory")
#define CP_WAIT(n)  asm volatile("cp.async.wait_group %0;" :: "n"(n) : "memory")

// ---------------- mask dtype detector ----------------------------------------
__global__ void detect_mask_kernel(const unsigned int* __restrict__ w){
    __shared__ int not_f, not_i;
    int t = threadIdx.x;
    if (t == 0){ not_f = 0; not_i = 0; }
    __syncthreads();
    unsigned v = w[t];
    if (v != 0u && v != 0x3F800000u) atomicExch(&not_f, 1);
    if (v > 1u)                      atomicExch(&not_i, 1);
    __syncthreads();
    if (t == 0) g_mask_mode = (not_f == 0) ? 2 : ((not_i == 0) ? 1 : 0);
}

// ---------------- fp32 -> (hi,lo) bf16 split ---------------------------------
__global__ void __launch_bounds__(256) split_kernel(
    const float* __restrict__ src, __nv_bfloat16* __restrict__ hi,
    __nv_bfloat16* __restrict__ lo, int n4)
{
    int i = blockIdx.x * 256 + threadIdx.x;
    if (i >= n4) return;
    float4 v = ((const float4*)src)[i];
    u32 h0, l0, h1, l1;
    split_pack(v.x, v.y, h0, l0);
    split_pack(v.z, v.w, h1, l1);
    ((uint2*)hi)[i] = make_uint2(h0, h1);
    ((uint2*)lo)[i] = make_uint2(l0, l1);
}

// ---------------- HMMA NT GEMM with split-bf16 -------------------------------
#define GSTRIDE 40
#define GMAT (128*GSTRIDE*2)
#define GSTAGE (4*GMAT)
#define GSMEM  (2*GSTAGE)

template<int QKV_EPI>
__global__ void __launch_bounds__(256) gemm_mma(
    const __nv_bfloat16* __restrict__ Ah, const __nv_bfloat16* __restrict__ Al,
    const __nv_bfloat16* __restrict__ Bh, const __nv_bfloat16* __restrict__ Bl,
    const float* __restrict__ bias, float* __restrict__ Cout)
{
    extern __shared__ __align__(16) char sm[];
    const u32 smb = smem_u32(sm);
    const int tid = threadIdx.x, lane = tid & 31, wid = tid >> 5;
    const int wm = wid >> 2, wn = wid & 3;

    const __nv_bfloat16* APh = Ah + (size_t)blockIdx.y * 128 * ND;
    const __nv_bfloat16* APl = Al + (size_t)blockIdx.y * 128 * ND;
    const __nv_bfloat16* BPh = Bh + (size_t)blockIdx.x * 128 * ND;
    const __nv_bfloat16* BPl = Bl + (size_t)blockIdx.x * 128 * ND;

    float C[4][4][4];
    #pragma unroll
    for (int i = 0; i < 4; i++)
        #pragma unroll
        for (int j = 0; j < 4; j++)
            #pragma unroll
            for (int e = 0; e < 4; e++) C[i][j][e] = 0.f;

    uint4 rg[8];

#define G_LDG(k0) do { \
    _Pragma("unroll") \
    for (int t = 0; t < 2; t++) { \
        int u_ = tid + 256*t; int row = u_ >> 2; int cb = (u_ & 3) * 8; \
        size_t go = (size_t)row * ND + (k0) + cb; \
        rg[0+t] = *(const uint4*)(APh + go); rg[2+t] = *(const uint4*)(APl + go); \
        rg[4+t] = *(const uint4*)(BPh + go); rg[6+t] = *(const uint4*)(BPl + go); \
    } } while(0)

#define G_STS(st) do { \
    _Pragma("unroll") \
    for (int t = 0; t < 2; t++) { \
        int u_ = tid + 256*t; int row = u_ >> 2; int cb = (u_ & 3) * 8; \
        u32 so = (st) + (u32)((row*GSTRIDE + cb)*2); \
        *(uint4*)(sm + so + 0*GMAT) = rg[0+t]; *(uint4*)(sm + so + 1*GMAT) = rg[2+t]; \
        *(uint4*)(sm + so + 2*GMAT) = rg[4+t]; *(uint4*)(sm + so + 3*GMAT) = rg[6+t]; \
    } } while(0)

    G_LDG(0);
    G_STS(0u);
    __syncthreads();

    for (int c = 0; c < ND/32; c++) {
        const u32 st = (u32)(c & 1) * GSTAGE;
        if (c + 1 < ND/32) G_LDG((c + 1) * 32);

        #pragma unroll
        for (int kk = 0; kk < 2; kk++) {
            u32 ah[4][4], al[4][4], bh_[4][2], bl_[4][2];
            #pragma unroll
            for (int i = 0; i < 4; i++) {
                u32 row = wm*64 + i*16 + (lane & 15);
                u32 col = kk*16 + (lane >> 4) * 8;
                u32 off = (row*GSTRIDE + col) * 2;
                ldsm4(ah[i], smb + st + 0*GMAT + off);
                ldsm4(al[i], smb + st + 1*GMAT + off);
            }
            #pragma unroll
            for (int jp = 0; jp < 2; jp++) {
                u32 row = wn*32 + jp*16 + (lane & 7) + ((lane & 16) >> 1);
                u32 col = kk*16 + (lane & 8);
                u32 off = (row*GSTRIDE + col) * 2;
                u32 t4[4];
                ldsm4(t4, smb + st + 2*GMAT + off);
                bh_[2*jp][0]=t4[0]; bh_[2*jp][1]=t4[1]; bh_[2*jp+1][0]=t4[2]; bh_[2*jp+1][1]=t4[3];
                ldsm4(t4, smb + st + 3*GMAT + off);
                bl_[2*jp][0]=t4[0]; bl_[2*jp][1]=t4[1]; bl_[2*jp+1][0]=t4[2]; bl_[2*jp+1][1]=t4[3];
            }
            #pragma unroll
            for (int i = 0; i < 4; i++)
                #pragma unroll
                for (int j = 0; j < 4; j++) {
                    mma_bf16(C[i][j], ah[i], bh_[j]);
                    mma_bf16(C[i][j], al[i], bh_[j]);
                    mma_bf16(C[i][j], ah[i], bl_[j]);
                }
        }
        if (c + 1 < ND/32) {
            __syncthreads();
            G_STS((u32)((c + 1) & 1) * GSTAGE);
            __syncthreads();
        }
    }
#undef G_LDG
#undef G_STS

    const int mb = blockIdx.y*128 + wm*64;
    const int nb = blockIdx.x*128 + wn*32;
    #pragma unroll
    for (int i = 0; i < 4; i++) {
        #pragma unroll
        for (int j = 0; j < 4; j++) {
            int n = nb + j*8 + 2*(lane & 3);
            float2 bz = *(const float2*)(bias + n);
            int m0 = mb + i*16 + (lane >> 2);
            int m1 = m0 + 8;
            float v00 = C[i][j][0] + bz.x, v01 = C[i][j][1] + bz.y;
            float v10 = C[i][j][2] + bz.x, v11 = C[i][j][3] + bz.y;
            if (QKV_EPI) {
                int h = n / 192, rem = n - h*192, part = rem >> 6, d = rem & 63;
                __nv_bfloat16* dh_ = (part==0) ? g_Qh : (part==1 ? g_Kh : g_Vh);
                __nv_bfloat16* dl_ = (part==0) ? g_Ql : (part==1 ? g_Kl : g_Vl);
                u32 hi, lo;
                {
                    int bb = m0 >> 11, ss = m0 & (NS-1);
                    size_t base = (((size_t)bb*NH + h)*NS + ss)*DH + d;
                    split_pack(v00, v01, hi, lo);
                    *(u32*)&dh_[base] = hi; *(u32*)&dl_[base] = lo;
                }
                {
                    int bb = m1 >> 11, ss = m1 & (NS-1);
                    size_t base = (((size_t)bb*NH + h)*NS + ss)*DH + d;
                    split_pack(v10, v11, hi, lo);
                    *(u32*)&dh_[base] = hi; *(u32*)&dl_[base] = lo;
                }
            } else {
                *(float2*)&Cout[(size_t)m0*ND + n] = make_float2(v00, v01);
                *(float2*)&Cout[(size_t)m1*ND + n] = make_float2(v10, v11);
            }
        }
    }
}

// ---------------- attention (HMMA, q-tile 128, cp.async 2-stage) -------------
// Block = (b, h, 128-q tile), 8 warps; each warp 16 q rows. 64-key chunks.
// smem: two 36864B stages (KH,KL,VH,VL @ 9216 each); Q staged through stage0
// once at start; full mask (2048 f32) at 73728.
#define ASTR 72
#define ASTAGE 36864
#define AMSK  (2*ASTAGE)           // 73728
#define ASMEM (AMSK + NS*4)        // 81920
#define NCH (NS/64)                // 32

__global__ void __launch_bounds__(256) attn_mma(const void* __restrict__ maskp)
{
    extern __shared__ __align__(16) char sm[];
    const u32 smb = smem_u32(sm);
    float* mk = (float*)(sm + AMSK);
    const int tid = threadIdx.x, lane = tid & 31, wid = tid >> 5;
    const int qb = blockIdx.x, h = blockIdx.y, b = blockIdx.z;

    const size_t hb = ((size_t)(b*NH + h)) * NS * DH;
    const __nv_bfloat16* Qhp = g_Qh + hb + (size_t)qb*128*DH;
    const __nv_bfloat16* Qlp = g_Ql + hb + (size_t)qb*128*DH;
    const __nv_bfloat16* Khp = g_Kh + hb;
    const __nv_bfloat16* Klp = g_Kl + hb;
    const __nv_bfloat16* Vhp = g_Vh + hb;
    const __nv_bfloat16* Vlp = g_Vl + hb;

    const float slope = exp2f(-0.5f * (float)(h + 1));
    const int mode = g_mask_mode;

    // stage Q (128 rows) through stage0; mask -> mk
    #pragma unroll
    for (int t = 0; t < 4; t++) {
        int idx = tid + 256*t; int row = idx >> 3; int cb = (idx & 7) * 8;
        u32 so = (u32)((row*ASTR + cb) * 2);
        *(uint4*)(sm + so)         = *(const uint4*)(Qhp + row*DH + cb);
        *(uint4*)(sm + 18432 + so) = *(const uint4*)(Qlp + row*DH + cb);
    }
    for (int i = tid; i < NS; i += 256) {
        bool mv;
        if      (mode == 0) mv = ((const unsigned char*)maskp)[b*NS + i] != 0;
        else if (mode == 1) mv = ((const int*)maskp)[b*NS + i] != 0;
        else                mv = ((const float*)maskp)[b*NS + i] != 0.f;
        mk[i] = mv ? 0.f : -1e30f;
    }
    __syncthreads();

    // persistent Q fragments
    u32 qh[4][4], ql[4][4];
    #pragma unroll
    for (int kk = 0; kk < 4; kk++) {
        u32 row = wid*16 + (lane & 15);
        u32 col = kk*16 + (lane >> 4) * 8;
        u32 off = (row*ASTR + col) * 2;
        ldsm4(qh[kk], smb + off);
        ldsm4(ql[kk], smb + 18432 + off);
    }
    __syncthreads();   // done reading Q staging (stage0 reused for K/V)

#define ISSUE_ARR(ptr, aoff, stg, k0) do { \
    _Pragma("unroll") \
    for (int t = 0; t < 2; t++) { \
        int idx = tid + 256*t; int row = idx >> 3; int cb = (idx & 7) * 8; \
        cp16(smb + (stg) + (aoff) + (u32)((row*ASTR + cb)*2), \
             (ptr) + (size_t)((k0) + row)*DH + cb); \
    } } while(0)
#define ISSUE_CHUNK(k0, stg) do { \
    ISSUE_ARR(Khp, 0,     stg, k0); ISSUE_ARR(Klp, 9216,  stg, k0); \
    ISSUE_ARR(Vhp, 18432, stg, k0); ISSUE_ARR(Vlp, 27648, stg, k0); \
    } while(0)

    float O[8][4];
    #pragma unroll
    for (int j = 0; j < 8; j++)
        #pragma unroll
        for (int e = 0; e < 4; e++) O[j][e] = 0.f;
    float dn0 = 0.f, dn1 = 0.f;
    const float qf0 = (float)(qb*128 + wid*16 + (lane >> 2));
    const float qf1 = qf0 + 8.f;

    ISSUE_CHUNK(0, 0u);
    CP_COMMIT();

    for (int c = 0; c < NCH; c++) {
        const int k0 = c * 64;
        const u32 stg = (u32)(c & 1) * ASTAGE;
        if (c + 1 < NCH) {
            ISSUE_CHUNK(k0 + 64, (u32)((c + 1) & 1) * ASTAGE);
            CP_COMMIT();
            CP_WAIT(1);
        } else {
            CP_WAIT(0);
        }
        __syncthreads();

        // S = Q K^T
        float S[8][4];
        #pragma unroll
        for (int j = 0; j < 8; j++)
            #pragma unroll
            for (int e = 0; e < 4; e++) S[j][e] = 0.f;
        #pragma unroll
        for (int kk = 0; kk < 4; kk++) {
            #pragma unroll
            for (int jp = 0; jp < 4; jp++) {
                u32 row = jp*16 + (lane & 7) + ((lane & 16) >> 1);
                u32 col = kk*16 + (lane & 8);
                u32 off = stg + (row*ASTR + col) * 2;
                u32 kh4[4], kl4[4];
                ldsm4(kh4, smb + off);
                ldsm4(kl4, smb + off + 9216);
                mma_bf16(S[2*jp],   qh[kk], kh4);
                mma_bf16(S[2*jp],   ql[kk], kh4);
                mma_bf16(S[2*jp],   qh[kk], kl4);
                mma_bf16(S[2*jp+1], qh[kk], kh4+2);
                mma_bf16(S[2*jp+1], ql[kk], kh4+2);
                mma_bf16(S[2*jp+1], qh[kk], kl4+2);
            }
        }

        // softmax + pack P into A-frags
        u32 aPh[4][4], aPl[4][4];
        #pragma unroll
        for (int j = 0; j < 8; j++) {
            int kc = k0 + j*8 + 2*(lane & 3);
            float kf = (float)kc;
            float m0 = mk[kc], m1 = mk[kc + 1];
            float p0 = __expf(S[j][0]*ATTN_SCALE - slope*fabsf(qf0 - kf)       + m0);
            float p1 = __expf(S[j][1]*ATTN_SCALE - slope*fabsf(qf0 - kf - 1.f) + m1);
            float p2 = __expf(S[j][2]*ATTN_SCALE - slope*fabsf(qf1 - kf)       + m0);
            float p3 = __expf(S[j][3]*ATTN_SCALE - slope*fabsf(qf1 - kf - 1.f) + m1);
            dn0 += p0 + p1;
            dn1 += p2 + p3;
            u32 h01, l01, h23, l23;
            split_pack(p0, p1, h01, l01);
            split_pack(p2, p3, h23, l23);
            int t = j >> 1, o = (j & 1) * 2;
            aPh[t][o]   = h01; aPl[t][o]   = l01;
            aPh[t][o+1] = h23; aPl[t][o+1] = l23;
        }

        // O += P V
        #pragma unroll
        for (int t = 0; t < 4; t++) {
            #pragma unroll
            for (int jp = 0; jp < 4; jp++) {
                u32 row = t*16 + (lane & 15);
                u32 col = (jp*2 + (lane >> 4)) * 8;
                u32 off = stg + 18432 + (row*ASTR + col) * 2;
                u32 vh4[4], vl4[4];
                ldsm4t(vh4, smb + off);
                ldsm4t(vl4, smb + off + 9216);
                mma_bf16(O[2*jp],   aPh[t], vh4);
                mma_bf16(O[2*jp],   aPl[t], vh4);
                mma_bf16(O[2*jp],   aPh[t], vl4);
                mma_bf16(O[2*jp+1], aPh[t], vh4+2);
                mma_bf16(O[2*jp+1], aPl[t], vh4+2);
                mma_bf16(O[2*jp+1], aPh[t], vl4+2);
            }
        }
        __syncthreads();   // all warps done reading stage c before c+2 issue
    }
#undef ISSUE_ARR
#undef ISSUE_CHUNK

    #pragma unroll
    for (int m_ = 1; m_ < 4; m_ <<= 1) {
        dn0 += __shfl_xor_sync(0xffffffffu, dn0, m_);
        dn1 += __shfl_xor_sync(0xffffffffu, dn1, m_);
    }
    const float inv0 = 1.f / dn0, inv1 = 1.f / dn1;

    const int q0 = qb*128 + wid*16 + (lane >> 2);
    const int q1 = q0 + 8;
    #pragma unroll
    for (int j = 0; j < 8; j++) {
        int d = h*64 + j*8 + 2*(lane & 3);
        u32 hi, lo;
        split_pack(O[j][0]*inv0, O[j][1]*inv0, hi, lo);
        size_t b0 = ((size_t)b*NS + q0)*ND + d;
        *(u32*)&g_ch[b0] = hi; *(u32*)&g_cl[b0] = lo;
        split_pack(O[j][2]*inv1, O[j][3]*inv1, hi, lo);
        size_t b1 = ((size_t)b*NS + q1)*ND + d;
        *(u32*)&g_ch[b1] = hi; *(u32*)&g_cl[b1] = lo;
    }
}

// ---------------- launch -----------------------------------------------------
extern "C" void kernel_launch(void* const* d_in, const int* in_sizes, int n_in,
                              void* d_out, int out_size)
{
    const float* x     = (const float*)d_in[0];
    const void*  mask  = d_in[1];
    const float* Wqkv  = (const float*)d_in[2];
    const float* bqkv  = (const float*)d_in[3];
    const float* Wproj = (const float*)d_in[4];
    const float* bproj = (const float*)d_in[5];
    float* out = (float*)d_out;

    (void)in_sizes; (void)n_in; (void)out_size;

    static bool inited = false;
    static __nv_bfloat16 *p_xh,*p_xl,*p_wqh,*p_wql,*p_wph,*p_wpl,*p_ch,*p_cl;
    if (!inited) {
        cudaFuncSetAttribute(gemm_mma<1>, cudaFuncAttributeMaxDynamicSharedMemorySize, GSMEM);
        cudaFuncSetAttribute(gemm_mma<0>, cudaFuncAttributeMaxDynamicSharedMemorySize, GSMEM);
        cudaFuncSetAttribute(attn_mma,    cudaFuncAttributeMaxDynamicSharedMemorySize, ASMEM);
        cudaGetSymbolAddress((void**)&p_xh, g_xh);   cudaGetSymbolAddress((void**)&p_xl, g_xl);
        cudaGetSymbolAddress((void**)&p_wqh, g_wqh); cudaGetSymbolAddress((void**)&p_wql, g_wql);
        cudaGetSymbolAddress((void**)&p_wph, g_wph); cudaGetSymbolAddress((void**)&p_wpl, g_wpl);
        cudaGetSymbolAddress((void**)&p_ch, g_ch);   cudaGetSymbolAddress((void**)&p_cl, g_cl);
        inited = true;
    }

    detect_mask_kernel<<<1, 1024>>>((const unsigned int*)mask);

    split_kernel<<<(NM*ND/4 + 255)/256, 256>>>(x, p_xh, p_xl, NM*ND/4);
    split_kernel<<<(NQKV*ND/4 + 255)/256, 256>>>(Wqkv, p_wqh, p_wql, NQKV*ND/4);
    split_kernel<<<(ND*ND/4 + 255)/256, 256>>>(Wproj, p_wph, p_wpl, ND*ND/4);

    gemm_mma<1><<<dim3(NQKV/128, NM/128), 256, GSMEM>>>(
        p_xh, p_xl, p_wqh, p_wql, bqkv, nullptr);

    attn_mma<<<dim3(NS/128, NH, NB), 256, ASMEM>>>(mask);

    gemm_mma<0><<<dim3(ND/128, NM/128), 256, GSMEM>>>(
        p_ch, p_cl, p_wph, p_wpl, bproj, out);
}

// round 6
// speedup vs baseline: 3.3459x; 1.0200x over previous
#include <cuda_runtime.h>
#include <cuda_bf16.h>

// Problem constants
#define NB 2
#define NS 2048
#define ND 1024
#define NH 16
#define DH 64
#define NM (NB*NS)        // 4096
#define NQKV (3*ND)       // 3072
#define ATTN_SCALE 0.03125f

typedef unsigned long long u64;
typedef unsigned int u32;

// ---------------- scratch (device globals) -----------------------------------
__device__ int g_mask_mode;
__device__ __nv_bfloat16 g_xh[(size_t)NM*ND],   g_xl[(size_t)NM*ND];
__device__ __nv_bfloat16 g_wqh[(size_t)NQKV*ND],g_wql[(size_t)NQKV*ND];
__device__ __nv_bfloat16 g_wph[(size_t)ND*ND],  g_wpl[(size_t)ND*ND];
__device__ __nv_bfloat16 g_ch[(size_t)NM*ND],   g_cl[(size_t)NM*ND];
#define QKV_ELEMS (NB*NH*NS*DH)
__device__ __nv_bfloat16 g_Qh[QKV_ELEMS], g_Ql[QKV_ELEMS];
__device__ __nv_bfloat16 g_Kh[QKV_ELEMS], g_Kl[QKV_ELEMS];
__device__ __nv_bfloat16 g_Vh[QKV_ELEMS], g_Vl[QKV_ELEMS];

// ---------------- PTX helpers ------------------------------------------------
__device__ __forceinline__ u32 smem_u32(const void* p){
    u32 a; asm("{ .reg .u64 t; cvta.to.shared.u64 t, %1; cvt.u32.u64 %0, t; }" : "=r"(a) : "l"(p));
    return a;
}
__device__ __forceinline__ void ldsm4(u32* r, u32 addr){
    asm volatile("ldmatrix.sync.aligned.m8n8.x4.shared.b16 {%0,%1,%2,%3}, [%4];"
        : "=r"(r[0]),"=r"(r[1]),"=r"(r[2]),"=r"(r[3]) : "r"(addr));
}
__device__ __forceinline__ void ldsm4t(u32* r, u32 addr){
    asm volatile("ldmatrix.sync.aligned.m8n8.x4.trans.shared.b16 {%0,%1,%2,%3}, [%4];"
        : "=r"(r[0]),"=r"(r[1]),"=r"(r[2]),"=r"(r[3]) : "r"(addr));
}
__device__ __forceinline__ void mma_bf16(float* c, const u32* a, const u32* b){
    asm volatile("mma.sync.aligned.m16n8k16.row.col.f32.bf16.bf16.f32 "
        "{%0,%1,%2,%3}, {%4,%5,%6,%7}, {%8,%9}, {%0,%1,%2,%3};"
        : "+f"(c[0]),"+f"(c[1]),"+f"(c[2]),"+f"(c[3])
        : "r"(a[0]),"r"(a[1]),"r"(a[2]),"r"(a[3]), "r"(b[0]),"r"(b[1]));
}
__device__ __forceinline__ void split_pack(float a, float b, u32& hi, u32& lo){
    __nv_bfloat16 ha = __float2bfloat16(a), hb = __float2bfloat16(b);
    float ra = a - __bfloat162float(ha), rb = b - __bfloat162float(hb);
    __nv_bfloat162 H; H.x = ha; H.y = hb;
    __nv_bfloat162 L; L.x = __float2bfloat16(ra); L.y = __float2bfloat16(rb);
    hi = *(u32*)&H; lo = *(u32*)&L;
}
__device__ __forceinline__ void cp16(u32 dst, const void* src){
    asm volatile("cp.async.cg.shared.global [%0], [%1], 16;" :: "r"(dst), "l"(src));
}
#define CP_COMMIT() asm volatile("cp.async.commit_group;" ::: "memory")
#define CP_WAIT(n)  asm volatile("cp.async.wait_group %0;" :: "n"(n) : "memory")

// ---------------- mask dtype detector ----------------------------------------
__global__ void detect_mask_kernel(const unsigned int* __restrict__ w){
    __shared__ int not_f, not_i;
    int t = threadIdx.x;
    if (t == 0){ not_f = 0; not_i = 0; }
    __syncthreads();
    unsigned v = w[t];
    if (v != 0u && v != 0x3F800000u) atomicExch(&not_f, 1);
    if (v > 1u)                      atomicExch(&not_i, 1);
    __syncthreads();
    if (t == 0) g_mask_mode = (not_f == 0) ? 2 : ((not_i == 0) ? 1 : 0);
}

// ---------------- fp32 -> (hi,lo) bf16 split ---------------------------------
__global__ void __launch_bounds__(256) split_kernel(
    const float* __restrict__ src, __nv_bfloat16* __restrict__ hi,
    __nv_bfloat16* __restrict__ lo, int n4)
{
    int i = blockIdx.x * 256 + threadIdx.x;
    if (i >= n4) return;
    float4 v = ((const float4*)src)[i];
    u32 h0, l0, h1, l1;
    split_pack(v.x, v.y, h0, l0);
    split_pack(v.z, v.w, h1, l1);
    ((uint2*)hi)[i] = make_uint2(h0, h1);
    ((uint2*)lo)[i] = make_uint2(l0, l1);
}

// ---------------- HMMA NT GEMM, pass-major, 3-stage cp.async -----------------
#define GSTRIDE 40
#define GMAT (128*GSTRIDE*2)   // 10240
#define GSTAGE (4*GMAT)        // 40960
#define GSMEM  (3*GSTAGE)      // 122880
#define GNCH (ND/32)           // 32

template<int QKV_EPI>
__global__ void __launch_bounds__(256) gemm_mma(
    const __nv_bfloat16* __restrict__ Ah, const __nv_bfloat16* __restrict__ Al,
    const __nv_bfloat16* __restrict__ Bh, const __nv_bfloat16* __restrict__ Bl,
    const float* __restrict__ bias, float* __restrict__ Cout)
{
    extern __shared__ __align__(16) char sm[];
    const u32 smb = smem_u32(sm);
    const int tid = threadIdx.x, lane = tid & 31, wid = tid >> 5;
    const int wm = wid >> 2, wn = wid & 3;

    const __nv_bfloat16* APh = Ah + (size_t)blockIdx.y * 128 * ND;
    const __nv_bfloat16* APl = Al + (size_t)blockIdx.y * 128 * ND;
    const __nv_bfloat16* BPh = Bh + (size_t)blockIdx.x * 128 * ND;
    const __nv_bfloat16* BPl = Bl + (size_t)blockIdx.x * 128 * ND;

    float C[4][4][4];
    #pragma unroll
    for (int i = 0; i < 4; i++)
        #pragma unroll
        for (int j = 0; j < 4; j++)
            #pragma unroll
            for (int e = 0; e < 4; e++) C[i][j][e] = 0.f;

#define G_ISSUE(k0, st) do { \
    _Pragma("unroll") \
    for (int t = 0; t < 2; t++) { \
        int u_ = tid + 256*t; int row = u_ >> 2; int cb = (u_ & 3) * 8; \
        size_t go = (size_t)row * ND + (k0) + cb; \
        u32 so = (st) + (u32)((row*GSTRIDE + cb)*2); \
        cp16(smb + so + 0*GMAT, APh + go); cp16(smb + so + 1*GMAT, APl + go); \
        cp16(smb + so + 2*GMAT, BPh + go); cp16(smb + so + 3*GMAT, BPl + go); \
    } } while(0)

    G_ISSUE(0, 0u);        CP_COMMIT();
    G_ISSUE(32, GSTAGE);   CP_COMMIT();

    for (int c = 0; c < GNCH; c++) {
        if (c + 2 < GNCH) CP_WAIT(1); else CP_WAIT(0);
        __syncthreads();
        const u32 st = (u32)(c % 3) * GSTAGE;
        if (c + 2 < GNCH) { G_ISSUE((c + 2)*32, (u32)((c + 2) % 3) * GSTAGE); CP_COMMIT(); }

        #pragma unroll
        for (int kk = 0; kk < 2; kk++) {
            const u32 aoff = ((wm*64 + (lane & 15))*GSTRIDE + kk*16 + (lane >> 4)*8) * 2;
            const u32 boff = ((wn*32 + (lane & 7) + ((lane & 16) >> 1))*GSTRIDE + kk*16 + (lane & 8)) * 2;

            u32 ah[4][4], bh_[4][2];
            #pragma unroll
            for (int i = 0; i < 4; i++) ldsm4(ah[i], smb + st + 0*GMAT + aoff + i*16*GSTRIDE*2);
            #pragma unroll
            for (int jp = 0; jp < 2; jp++) {
                u32 t4[4];
                ldsm4(t4, smb + st + 2*GMAT + boff + jp*16*GSTRIDE*2);
                bh_[2*jp][0]=t4[0]; bh_[2*jp][1]=t4[1]; bh_[2*jp+1][0]=t4[2]; bh_[2*jp+1][1]=t4[3];
            }
            // pass 1: Ah*Bh (16 independent MMAs)
            #pragma unroll
            for (int i = 0; i < 4; i++)
                #pragma unroll
                for (int j = 0; j < 4; j++) mma_bf16(C[i][j], ah[i], bh_[j]);
            // pass 2: Al*Bh
            u32 al[4][4];
            #pragma unroll
            for (int i = 0; i < 4; i++) ldsm4(al[i], smb + st + 1*GMAT + aoff + i*16*GSTRIDE*2);
            #pragma unroll
            for (int i = 0; i < 4; i++)
                #pragma unroll
                for (int j = 0; j < 4; j++) mma_bf16(C[i][j], al[i], bh_[j]);
            // pass 3: Ah*Bl
            u32 bl_[4][2];
            #pragma unroll
            for (int jp = 0; jp < 2; jp++) {
                u32 t4[4];
                ldsm4(t4, smb + st + 3*GMAT + boff + jp*16*GSTRIDE*2);
                bl_[2*jp][0]=t4[0]; bl_[2*jp][1]=t4[1]; bl_[2*jp+1][0]=t4[2]; bl_[2*jp+1][1]=t4[3];
            }
            #pragma unroll
            for (int i = 0; i < 4; i++)
                #pragma unroll
                for (int j = 0; j < 4; j++) mma_bf16(C[i][j], ah[i], bl_[j]);
        }
    }
#undef G_ISSUE

    const int mb = blockIdx.y*128 + wm*64;
    const int nb = blockIdx.x*128 + wn*32;
    #pragma unroll
    for (int i = 0; i < 4; i++) {
        #pragma unroll
        for (int j = 0; j < 4; j++) {
            int n = nb + j*8 + 2*(lane & 3);
            float2 bz = *(const float2*)(bias + n);
            int m0 = mb + i*16 + (lane >> 2);
            int m1 = m0 + 8;
            float v00 = C[i][j][0] + bz.x, v01 = C[i][j][1] + bz.y;
            float v10 = C[i][j][2] + bz.x, v11 = C[i][j][3] + bz.y;
            if (QKV_EPI) {
                int h = n / 192, rem = n - h*192, part = rem >> 6, d = rem & 63;
                __nv_bfloat16* dh_ = (part==0) ? g_Qh : (part==1 ? g_Kh : g_Vh);
                __nv_bfloat16* dl_ = (part==0) ? g_Ql : (part==1 ? g_Kl : g_Vl);
                u32 hi, lo;
                {
                    int bb = m0 >> 11, ss = m0 & (NS-1);
                    size_t base = (((size_t)bb*NH + h)*NS + ss)*DH + d;
                    split_pack(v00, v01, hi, lo);
                    *(u32*)&dh_[base] = hi; *(u32*)&dl_[base] = lo;
                }
                {
                    int bb = m1 >> 11, ss = m1 & (NS-1);
                    size_t base = (((size_t)bb*NH + h)*NS + ss)*DH + d;
                    split_pack(v10, v11, hi, lo);
                    *(u32*)&dh_[base] = hi; *(u32*)&dl_[base] = lo;
                }
            } else {
                *(float2*)&Cout[(size_t)m0*ND + n] = make_float2(v00, v01);
                *(float2*)&Cout[(size_t)m1*ND + n] = make_float2(v10, v11);
            }
        }
    }
}

// ---------------- attention: pass-major MMA, 3-stage cp.async ----------------
#define ASTR 72
#define ASTAGE 36864
#define AMSK  (3*ASTAGE)           // 110592
#define ASMEM (AMSK + NS*4)        // 118784
#define NCH (NS/64)                // 32

__global__ void __launch_bounds__(256) attn_mma(const void* __restrict__ maskp)
{
    extern __shared__ __align__(16) char sm[];
    const u32 smb = smem_u32(sm);
    float* mk = (float*)(sm + AMSK);
    const int tid = threadIdx.x, lane = tid & 31, wid = tid >> 5;
    const int qb = blockIdx.x, h = blockIdx.y, b = blockIdx.z;

    const size_t hb = ((size_t)(b*NH + h)) * NS * DH;
    const __nv_bfloat16* Qhp = g_Qh + hb + (size_t)qb*128*DH;
    const __nv_bfloat16* Qlp = g_Ql + hb + (size_t)qb*128*DH;
    const __nv_bfloat16* Khp = g_Kh + hb;
    const __nv_bfloat16* Klp = g_Kl + hb;
    const __nv_bfloat16* Vhp = g_Vh + hb;
    const __nv_bfloat16* Vlp = g_Vl + hb;

    const float slope = exp2f(-0.5f * (float)(h + 1));
    const int mode = g_mask_mode;

    // stage Q through stage-0 area; mask -> mk
    #pragma unroll
    for (int t = 0; t < 4; t++) {
        int idx = tid + 256*t; int row = idx >> 3; int cb = (idx & 7) * 8;
        u32 so = (u32)((row*ASTR + cb) * 2);
        *(uint4*)(sm + so)         = *(const uint4*)(Qhp + row*DH + cb);
        *(uint4*)(sm + 18432 + so) = *(const uint4*)(Qlp + row*DH + cb);
    }
    for (int i = tid; i < NS; i += 256) {
        bool mv;
        if      (mode == 0) mv = ((const unsigned char*)maskp)[b*NS + i] != 0;
        else if (mode == 1) mv = ((const int*)maskp)[b*NS + i] != 0;
        else                mv = ((const float*)maskp)[b*NS + i] != 0.f;
        mk[i] = mv ? 0.f : -1e30f;
    }
    __syncthreads();

    u32 qh[4][4], ql[4][4];
    #pragma unroll
    for (int kk = 0; kk < 4; kk++) {
        u32 off = ((wid*16 + (lane & 15))*ASTR + kk*16 + (lane >> 4)*8) * 2;
        ldsm4(qh[kk], smb + off);
        ldsm4(ql[kk], smb + 18432 + off);
    }
    __syncthreads();   // Q staging consumed; stage 0 reusable

#define ISSUE_ARR(ptr, aoff, stg, k0) do { \
    _Pragma("unroll") \
    for (int t = 0; t < 2; t++) { \
        int idx = tid + 256*t; int row = idx >> 3; int cb = (idx & 7) * 8; \
        cp16(smb + (stg) + (aoff) + (u32)((row*ASTR + cb)*2), \
             (ptr) + (size_t)((k0) + row)*DH + cb); \
    } } while(0)
#define ISSUE_CHUNK(k0, stg) do { \
    ISSUE_ARR(Khp, 0,     stg, k0); ISSUE_ARR(Klp, 9216,  stg, k0); \
    ISSUE_ARR(Vhp, 18432, stg, k0); ISSUE_ARR(Vlp, 27648, stg, k0); \
    } while(0)

    float O[8][4];
    #pragma unroll
    for (int j = 0; j < 8; j++)
        #pragma unroll
        for (int e = 0; e < 4; e++) O[j][e] = 0.f;
    float dn0 = 0.f, dn1 = 0.f;
    const float qf0 = (float)(qb*128 + wid*16 + (lane >> 2));
    const float qf1 = qf0 + 8.f;

    ISSUE_CHUNK(0, 0u);       CP_COMMIT();
    ISSUE_CHUNK(64, ASTAGE);  CP_COMMIT();

    for (int c = 0; c < NCH; c++) {
        const int k0 = c * 64;
        if (c + 2 < NCH) CP_WAIT(1); else CP_WAIT(0);
        __syncthreads();
        const u32 stg = (u32)(c % 3) * ASTAGE;
        if (c + 2 < NCH) { ISSUE_CHUNK(k0 + 128, (u32)((c + 2) % 3) * ASTAGE); CP_COMMIT(); }

        // ---- S = Q K^T, pass-major ----
        float S[8][4];
        #pragma unroll
        for (int j = 0; j < 8; j++)
            #pragma unroll
            for (int e = 0; e < 4; e++) S[j][e] = 0.f;
        #pragma unroll
        for (int kk = 0; kk < 4; kk++) {
            const u32 koff = stg + (((lane & 7) + ((lane & 16) >> 1))*ASTR + kk*16 + (lane & 8)) * 2;
            u32 kh4[4][4];
            #pragma unroll
            for (int jp = 0; jp < 4; jp++) ldsm4(kh4[jp], smb + koff + jp*16*ASTR*2);
            #pragma unroll
            for (int jp = 0; jp < 4; jp++) {
                mma_bf16(S[2*jp],   qh[kk], kh4[jp]);
                mma_bf16(S[2*jp+1], qh[kk], kh4[jp]+2);
            }
            #pragma unroll
            for (int jp = 0; jp < 4; jp++) {
                mma_bf16(S[2*jp],   ql[kk], kh4[jp]);
                mma_bf16(S[2*jp+1], ql[kk], kh4[jp]+2);
            }
            u32 kl4[4][4];
            #pragma unroll
            for (int jp = 0; jp < 4; jp++) ldsm4(kl4[jp], smb + koff + 9216 + jp*16*ASTR*2);
            #pragma unroll
            for (int jp = 0; jp < 4; jp++) {
                mma_bf16(S[2*jp],   qh[kk], kl4[jp]);
                mma_bf16(S[2*jp+1], qh[kk], kl4[jp]+2);
            }
        }

        // ---- softmax + pack P ----
        u32 aPh[4][4], aPl[4][4];
        #pragma unroll
        for (int j = 0; j < 8; j++) {
            int kc = k0 + j*8 + 2*(lane & 3);
            float kf = (float)kc;
            float m0 = mk[kc], m1 = mk[kc + 1];
            float p0 = __expf(S[j][0]*ATTN_SCALE - slope*fabsf(qf0 - kf)       + m0);
            float p1 = __expf(S[j][1]*ATTN_SCALE - slope*fabsf(qf0 - kf - 1.f) + m1);
            float p2 = __expf(S[j][2]*ATTN_SCALE - slope*fabsf(qf1 - kf)       + m0);
            float p3 = __expf(S[j][3]*ATTN_SCALE - slope*fabsf(qf1 - kf - 1.f) + m1);
            dn0 += p0 + p1;
            dn1 += p2 + p3;
            u32 h01, l01, h23, l23;
            split_pack(p0, p1, h01, l01);
            split_pack(p2, p3, h23, l23);
            int t = j >> 1, o = (j & 1) * 2;
            aPh[t][o]   = h01; aPl[t][o]   = l01;
            aPh[t][o+1] = h23; aPl[t][o+1] = l23;
        }

        // ---- O += P V, pass-major ----
        #pragma unroll
        for (int t = 0; t < 4; t++) {
            const u32 voff = stg + 18432 + ((t*16 + (lane & 15))*ASTR + (lane >> 4)*8) * 2;
            u32 vh4[4][4];
            #pragma unroll
            for (int jp = 0; jp < 4; jp++) ldsm4t(vh4[jp], smb + voff + jp*16*2);
            #pragma unroll
            for (int jp = 0; jp < 4; jp++) {
                mma_bf16(O[2*jp],   aPh[t], vh4[jp]);
                mma_bf16(O[2*jp+1], aPh[t], vh4[jp]+2);
            }
            #pragma unroll
            for (int jp = 0; jp < 4; jp++) {
                mma_bf16(O[2*jp],   aPl[t], vh4[jp]);
                mma_bf16(O[2*jp+1], aPl[t], vh4[jp]+2);
            }
            u32 vl4[4][4];
            #pragma unroll
            for (int jp = 0; jp < 4; jp++) ldsm4t(vl4[jp], smb + voff + 9216 + jp*16*2);
            #pragma unroll
            for (int jp = 0; jp < 4; jp++) {
                mma_bf16(O[2*jp],   aPh[t], vl4[jp]);
                mma_bf16(O[2*jp+1], aPh[t], vl4[jp]+2);
            }
        }
    }
#undef ISSUE_ARR
#undef ISSUE_CHUNK

    #pragma unroll
    for (int m_ = 1; m_ < 4; m_ <<= 1) {
        dn0 += __shfl_xor_sync(0xffffffffu, dn0, m_);
        dn1 += __shfl_xor_sync(0xffffffffu, dn1, m_);
    }
    const float inv0 = 1.f / dn0, inv1 = 1.f / dn1;

    const int q0 = qb*128 + wid*16 + (lane >> 2);
    const int q1 = q0 + 8;
    #pragma unroll
    for (int j = 0; j < 8; j++) {
        int d = h*64 + j*8 + 2*(lane & 3);
        u32 hi, lo;
        split_pack(O[j][0]*inv0, O[j][1]*inv0, hi, lo);
        size_t b0 = ((size_t)b*NS + q0)*ND + d;
        *(u32*)&g_ch[b0] = hi; *(u32*)&g_cl[b0] = lo;
        split_pack(O[j][2]*inv1, O[j][3]*inv1, hi, lo);
        size_t b1 = ((size_t)b*NS + q1)*ND + d;
        *(u32*)&g_ch[b1] = hi; *(u32*)&g_cl[b1] = lo;
    }
}

// ---------------- launch -----------------------------------------------------
extern "C" void kernel_launch(void* const* d_in, const int* in_sizes, int n_in,
                              void* d_out, int out_size)
{
    const float* x     = (const float*)d_in[0];
    const void*  mask  = d_in[1];
    const float* Wqkv  = (const float*)d_in[2];
    const float* bqkv  = (const float*)d_in[3];
    const float* Wproj = (const float*)d_in[4];
    const float* bproj = (const float*)d_in[5];
    float* out = (float*)d_out;

    (void)in_sizes; (void)n_in; (void)out_size;

    static bool inited = false;
    static __nv_bfloat16 *p_xh,*p_xl,*p_wqh,*p_wql,*p_wph,*p_wpl,*p_ch,*p_cl;
    if (!inited) {
        cudaFuncSetAttribute(gemm_mma<1>, cudaFuncAttributeMaxDynamicSharedMemorySize, GSMEM);
        cudaFuncSetAttribute(gemm_mma<0>, cudaFuncAttributeMaxDynamicSharedMemorySize, GSMEM);
        cudaFuncSetAttribute(attn_mma,    cudaFuncAttributeMaxDynamicSharedMemorySize, ASMEM);
        cudaGetSymbolAddress((void**)&p_xh, g_xh);   cudaGetSymbolAddress((void**)&p_xl, g_xl);
        cudaGetSymbolAddress((void**)&p_wqh, g_wqh); cudaGetSymbolAddress((void**)&p_wql, g_wql);
        cudaGetSymbolAddress((void**)&p_wph, g_wph); cudaGetSymbolAddress((void**)&p_wpl, g_wpl);
        cudaGetSymbolAddress((void**)&p_ch, g_ch);   cudaGetSymbolAddress((void**)&p_cl, g_cl);
        inited = true;
    }

    detect_mask_kernel<<<1, 1024>>>((const unsigned int*)mask);

    split_kernel<<<(NM*ND/4 + 255)/256, 256>>>(x, p_xh, p_xl, NM*ND/4);
    split_kernel<<<(NQKV*ND/4 + 255)/256, 256>>>(Wqkv, p_wqh, p_wql, NQKV*ND/4);
    split_kernel<<<(ND*ND/4 + 255)/256, 256>>>(Wproj, p_wph, p_wpl, ND*ND/4);

    gemm_mma<1><<<dim3(NQKV/128, NM/128), 256, GSMEM>>>(
        p_xh, p_xl, p_wqh, p_wql, bqkv, nullptr);

    attn_mma<<<dim3(NS/128, NH, NB), 256, ASMEM>>>(mask);

    gemm_mma<0><<<dim3(ND/128, NM/128), 256, GSMEM>>>(
        p_ch, p_cl, p_wph, p_wpl, bproj, out);
}

// round 8
// speedup vs baseline: 4.3058x; 1.2869x over previous
#include <cuda_runtime.h>
#include <cuda_bf16.h>
#include <cuda_fp16.h>

// Problem constants
#define NB 2
#define NS 2048
#define ND 1024
#define NH 16
#define DH 64
#define NM (NB*NS)        // 4096
#define NQKV (3*ND)       // 3072
#define ATTN_SCALE 0.03125f

typedef unsigned long long u64;
typedef unsigned int u32;

// ---------------- scratch (device globals) -----------------------------------
__device__ int g_mask_mode;
__device__ __nv_bfloat16 g_xh[(size_t)NM*ND],   g_xl[(size_t)NM*ND];
__device__ __nv_bfloat16 g_wqh[(size_t)NQKV*ND],g_wql[(size_t)NQKV*ND];
__device__ __nv_bfloat16 g_wph[(size_t)ND*ND],  g_wpl[(size_t)ND*ND];
__device__ __nv_bfloat16 g_ch[(size_t)NM*ND],   g_cl[(size_t)NM*ND];
#define QKV_ELEMS (NB*NH*NS*DH)
__device__ __half g_Qf[QKV_ELEMS], g_Kf[QKV_ELEMS], g_Vf[QKV_ELEMS];

// ---------------- PTX helpers ------------------------------------------------
__device__ __forceinline__ u32 smem_u32(const void* p){
    u32 a; asm("{ .reg .u64 t; cvta.to.shared.u64 t, %1; cvt.u32.u64 %0, t; }" : "=r"(a) : "l"(p));
    return a;
}
__device__ __forceinline__ void ldsm4(u32* r, u32 addr){
    asm volatile("ldmatrix.sync.aligned.m8n8.x4.shared.b16 {%0,%1,%2,%3}, [%4];"
        : "=r"(r[0]),"=r"(r[1]),"=r"(r[2]),"=r"(r[3]) : "r"(addr));
}
__device__ __forceinline__ void ldsm4t(u32* r, u32 addr){
    asm volatile("ldmatrix.sync.aligned.m8n8.x4.trans.shared.b16 {%0,%1,%2,%3}, [%4];"
        : "=r"(r[0]),"=r"(r[1]),"=r"(r[2]),"=r"(r[3]) : "r"(addr));
}
__device__ __forceinline__ void mma_bf16(float* c, const u32* a, const u32* b){
    asm volatile("mma.sync.aligned.m16n8k16.row.col.f32.bf16.bf16.f32 "
        "{%0,%1,%2,%3}, {%4,%5,%6,%7}, {%8,%9}, {%0,%1,%2,%3};"
        : "+f"(c[0]),"+f"(c[1]),"+f"(c[2]),"+f"(c[3])
        : "r"(a[0]),"r"(a[1]),"r"(a[2]),"r"(a[3]), "r"(b[0]),"r"(b[1]));
}
__device__ __forceinline__ void mma_fp16(float* c, const u32* a, const u32* b){
    asm volatile("mma.sync.aligned.m16n8k16.row.col.f32.f16.f16.f32 "
        "{%0,%1,%2,%3}, {%4,%5,%6,%7}, {%8,%9}, {%0,%1,%2,%3};"
        : "+f"(c[0]),"+f"(c[1]),"+f"(c[2]),"+f"(c[3])
        : "r"(a[0]),"r"(a[1]),"r"(a[2]),"r"(a[3]), "r"(b[0]),"r"(b[1]));
}
__device__ __forceinline__ void split_pack(float a, float b, u32& hi, u32& lo){
    __nv_bfloat16 ha = __float2bfloat16(a), hb = __float2bfloat16(b);
    float ra = a - __bfloat162float(ha), rb = b - __bfloat162float(hb);
    __nv_bfloat162 H; H.x = ha; H.y = hb;
    __nv_bfloat162 L; L.x = __float2bfloat16(ra); L.y = __float2bfloat16(rb);
    hi = *(u32*)&H; lo = *(u32*)&L;
}
__device__ __forceinline__ void split_pack_h(float a, float b, u32& hi, u32& lo){
    __half ha = __float2half_rn(a), hb = __float2half_rn(b);
    float ra = a - __half2float(ha), rb = b - __half2float(hb);
    __half2 H; H.x = ha; H.y = hb;
    __half2 L; L.x = __float2half_rn(ra); L.y = __float2half_rn(rb);
    hi = *(u32*)&H; lo = *(u32*)&L;
}
__device__ __forceinline__ u32 pack_h2(float a, float b){
    __half2 H; H.x = __float2half_rn(a); H.y = __float2half_rn(b);
    return *(u32*)&H;
}
__device__ __forceinline__ void cp16(u32 dst, const void* src){
    asm volatile("cp.async.cg.shared.global [%0], [%1], 16;" :: "r"(dst), "l"(src));
}
#define CP_COMMIT() asm volatile("cp.async.commit_group;" ::: "memory")
#define CP_WAIT(n)  asm volatile("cp.async.wait_group %0;" :: "n"(n) : "memory")

// ---------------- mask dtype detector ----------------------------------------
__global__ void detect_mask_kernel(const unsigned int* __restrict__ w){
    __shared__ int not_f, not_i;
    int t = threadIdx.x;
    if (t == 0){ not_f = 0; not_i = 0; }
    __syncthreads();
    unsigned v = w[t];
    if (v != 0u && v != 0x3F800000u) atomicExch(&not_f, 1);
    if (v > 1u)                      atomicExch(&not_i, 1);
    __syncthreads();
    if (t == 0) g_mask_mode = (not_f == 0) ? 2 : ((not_i == 0) ? 1 : 0);
}

// ---------------- fp32 -> (hi,lo) bf16 split ---------------------------------
__global__ void __launch_bounds__(256) split_kernel(
    const float* __restrict__ src, __nv_bfloat16* __restrict__ hi,
    __nv_bfloat16* __restrict__ lo, int n4)
{
    int i = blockIdx.x * 256 + threadIdx.x;
    if (i >= n4) return;
    float4 v = ((const float4*)src)[i];
    u32 h0, l0, h1, l1;
    split_pack(v.x, v.y, h0, l0);
    split_pack(v.z, v.w, h1, l1);
    ((uint2*)hi)[i] = make_uint2(h0, h1);
    ((uint2*)lo)[i] = make_uint2(l0, l1);
}

// ---------------- HMMA NT GEMM, bf16 3-pass, 3-stage cp.async ----------------
#define GSTRIDE 40
#define GMAT (128*GSTRIDE*2)   // 10240
#define GSTAGE (4*GMAT)        // 40960
#define GSMEM  (3*GSTAGE)      // 122880
#define GNCH (ND/32)           // 32

template<int QKV_EPI>
__global__ void __launch_bounds__(256) gemm_mma(
    const __nv_bfloat16* __restrict__ Ah, const __nv_bfloat16* __restrict__ Al,
    const __nv_bfloat16* __restrict__ Bh, const __nv_bfloat16* __restrict__ Bl,
    const float* __restrict__ bias, float* __restrict__ Cout)
{
    extern __shared__ __align__(16) char sm[];
    const u32 smb = smem_u32(sm);
    const int tid = threadIdx.x, lane = tid & 31, wid = tid >> 5;
    const int wm = wid >> 2, wn = wid & 3;

    const __nv_bfloat16* APh = Ah + (size_t)blockIdx.y * 128 * ND;
    const __nv_bfloat16* APl = Al + (size_t)blockIdx.y * 128 * ND;
    const __nv_bfloat16* BPh = Bh + (size_t)blockIdx.x * 128 * ND;
    const __nv_bfloat16* BPl = Bl + (size_t)blockIdx.x * 128 * ND;

    float C[4][4][4];
    #pragma unroll
    for (int i = 0; i < 4; i++)
        #pragma unroll
        for (int j = 0; j < 4; j++)
            #pragma unroll
            for (int e = 0; e < 4; e++) C[i][j][e] = 0.f;

#define G_ISSUE(k0, st) do { \
    _Pragma("unroll") \
    for (int t = 0; t < 2; t++) { \
        int u_ = tid + 256*t; int row = u_ >> 2; int cb = (u_ & 3) * 8; \
        size_t go = (size_t)row * ND + (k0) + cb; \
        u32 so = (st) + (u32)((row*GSTRIDE + cb)*2); \
        cp16(smb + so + 0*GMAT, APh + go); cp16(smb + so + 1*GMAT, APl + go); \
        cp16(smb + so + 2*GMAT, BPh + go); cp16(smb + so + 3*GMAT, BPl + go); \
    } } while(0)

    G_ISSUE(0, 0u);        CP_COMMIT();
    G_ISSUE(32, GSTAGE);   CP_COMMIT();

    for (int c = 0; c < GNCH; c++) {
        if (c + 2 < GNCH) CP_WAIT(1); else CP_WAIT(0);
        __syncthreads();
        const u32 st = (u32)(c % 3) * GSTAGE;
        if (c + 2 < GNCH) { G_ISSUE((c + 2)*32, (u32)((c + 2) % 3) * GSTAGE); CP_COMMIT(); }

        #pragma unroll
        for (int kk = 0; kk < 2; kk++) {
            const u32 aoff = ((wm*64 + (lane & 15))*GSTRIDE + kk*16 + (lane >> 4)*8) * 2;
            const u32 boff = ((wn*32 + (lane & 7) + ((lane & 16) >> 1))*GSTRIDE + kk*16 + (lane & 8)) * 2;

            u32 ah[4][4], bh_[4][2];
            #pragma unroll
            for (int i = 0; i < 4; i++) ldsm4(ah[i], smb + st + 0*GMAT + aoff + i*16*GSTRIDE*2);
            #pragma unroll
            for (int jp = 0; jp < 2; jp++) {
                u32 t4[4];
                ldsm4(t4, smb + st + 2*GMAT + boff + jp*16*GSTRIDE*2);
                bh_[2*jp][0]=t4[0]; bh_[2*jp][1]=t4[1]; bh_[2*jp+1][0]=t4[2]; bh_[2*jp+1][1]=t4[3];
            }
            #pragma unroll
            for (int i = 0; i < 4; i++)
                #pragma unroll
                for (int j = 0; j < 4; j++) mma_bf16(C[i][j], ah[i], bh_[j]);
            u32 al[4][4];
            #pragma unroll
            for (int i = 0; i < 4; i++) ldsm4(al[i], smb + st + 1*GMAT + aoff + i*16*GSTRIDE*2);
            #pragma unroll
            for (int i = 0; i < 4; i++)
                #pragma unroll
                for (int j = 0; j < 4; j++) mma_bf16(C[i][j], al[i], bh_[j]);
            u32 bl_[4][2];
            #pragma unroll
            for (int jp = 0; jp < 2; jp++) {
                u32 t4[4];
                ldsm4(t4, smb + st + 3*GMAT + boff + jp*16*GSTRIDE*2);
                bl_[2*jp][0]=t4[0]; bl_[2*jp][1]=t4[1]; bl_[2*jp+1][0]=t4[2]; bl_[2*jp+1][1]=t4[3];
            }
            #pragma unroll
            for (int i = 0; i < 4; i++)
                #pragma unroll
                for (int j = 0; j < 4; j++) mma_bf16(C[i][j], ah[i], bl_[j]);
        }
    }
#undef G_ISSUE

    const int mb = blockIdx.y*128 + wm*64;
    const int nb = blockIdx.x*128 + wn*32;
    #pragma unroll
    for (int i = 0; i < 4; i++) {
        #pragma unroll
        for (int j = 0; j < 4; j++) {
            int n = nb + j*8 + 2*(lane & 3);
            float2 bz = *(const float2*)(bias + n);
            int m0 = mb + i*16 + (lane >> 2);
            int m1 = m0 + 8;
            float v00 = C[i][j][0] + bz.x, v01 = C[i][j][1] + bz.y;
            float v10 = C[i][j][2] + bz.x, v11 = C[i][j][3] + bz.y;
            if (QKV_EPI) {
                // qkv col n -> head n/192, part (n%192)/64, d = n%64; fp16 hi-only
                int h = n / 192, rem = n - h*192, part = rem >> 6, d = rem & 63;
                __half* dst = (part==0) ? g_Qf : (part==1 ? g_Kf : g_Vf);
                {
                    int bb = m0 >> 11, ss = m0 & (NS-1);
                    size_t base = (((size_t)bb*NH + h)*NS + ss)*DH + d;
                    *(u32*)&dst[base] = pack_h2(v00, v01);
                }
                {
                    int bb = m1 >> 11, ss = m1 & (NS-1);
                    size_t base = (((size_t)bb*NH + h)*NS + ss)*DH + d;
                    *(u32*)&dst[base] = pack_h2(v10, v11);
                }
            } else {
                *(float2*)&Cout[(size_t)m0*ND + n] = make_float2(v00, v01);
                *(float2*)&Cout[(size_t)m1*ND + n] = make_float2(v10, v11);
            }
        }
    }
}

// ---------------- attention: fp16, QK 1-pass, PV 2-pass ----------------------
// Block = (b, h, 128-q tile), 8 warps. 64-key chunks, 3-stage cp.async.
// smem stage = KH(9216) + VH(9216) = 18432; Q staged once through stage 0.
#define ASTR 72
#define ASTAGE 18432
#define AMSK  (3*ASTAGE)           // 55296
#define ASMEM (AMSK + NS*4)        // 63488
#define NCH (NS/64)                // 32

__global__ void __launch_bounds__(256) attn_mma(const void* __restrict__ maskp)
{
    extern __shared__ __align__(16) char sm[];
    const u32 smb = smem_u32(sm);
    float* mk = (float*)(sm + AMSK);
    const int tid = threadIdx.x, lane = tid & 31, wid = tid >> 5;
    const int qb = blockIdx.x, h = blockIdx.y, b = blockIdx.z;

    const size_t hb = ((size_t)(b*NH + h)) * NS * DH;
    const __half* Qp = g_Qf + hb + (size_t)qb*128*DH;
    const __half* Kp = g_Kf + hb;
    const __half* Vp = g_Vf + hb;

    const float slope = exp2f(-0.5f * (float)(h + 1));
    const int mode = g_mask_mode;

    // stage Q (128 rows x 64 halves) through stage 0; mask -> mk
    #pragma unroll
    for (int t = 0; t < 4; t++) {
        int idx = tid + 256*t; int row = idx >> 3; int cb = (idx & 7) * 8;
        *(uint4*)(sm + (u32)((row*ASTR + cb)*2)) = *(const uint4*)(Qp + row*DH + cb);
    }
    for (int i = tid; i < NS; i += 256) {
        bool mv;
        if      (mode == 0) mv = ((const unsigned char*)maskp)[b*NS + i] != 0;
        else if (mode == 1) mv = ((const int*)maskp)[b*NS + i] != 0;
        else                mv = ((const float*)maskp)[b*NS + i] != 0.f;
        mk[i] = mv ? 0.f : -1e30f;
    }
    __syncthreads();

    u32 qh[4][4];
    #pragma unroll
    for (int kk = 0; kk < 4; kk++) {
        u32 off = ((wid*16 + (lane & 15))*ASTR + kk*16 + (lane >> 4)*8) * 2;
        ldsm4(qh[kk], smb + off);
    }
    __syncthreads();   // Q staging consumed; stage 0 reusable

#define ISSUE_ARR(ptr, aoff, stg, k0) do { \
    _Pragma("unroll") \
    for (int t = 0; t < 2; t++) { \
        int idx = tid + 256*t; int row = idx >> 3; int cb = (idx & 7) * 8; \
        cp16(smb + (stg) + (aoff) + (u32)((row*ASTR + cb)*2), \
             (ptr) + (size_t)((k0) + row)*DH + cb); \
    } } while(0)
#define ISSUE_CHUNK(k0, stg) do { \
    ISSUE_ARR(Kp, 0,    stg, k0); \
    ISSUE_ARR(Vp, 9216, stg, k0); \
    } while(0)

    float O[8][4];
    #pragma unroll
    for (int j = 0; j < 8; j++)
        #pragma unroll
        for (int e = 0; e < 4; e++) O[j][e] = 0.f;
    float dn0 = 0.f, dn1 = 0.f;
    const float qf0 = (float)(qb*128 + wid*16 + (lane >> 2));
    const float qf1 = qf0 + 8.f;

    ISSUE_CHUNK(0, 0u);       CP_COMMIT();
    ISSUE_CHUNK(64, ASTAGE);  CP_COMMIT();

    for (int c = 0; c < NCH; c++) {
        const int k0 = c * 64;
        if (c + 2 < NCH) CP_WAIT(1); else CP_WAIT(0);
        __syncthreads();
        const u32 stg = (u32)(c % 3) * ASTAGE;
        if (c + 2 < NCH) { ISSUE_CHUNK(k0 + 128, (u32)((c + 2) % 3) * ASTAGE); CP_COMMIT(); }

        // ---- S = Q K^T (single fp16 pass) ----
        float S[8][4];
        #pragma unroll
        for (int j = 0; j < 8; j++)
            #pragma unroll
            for (int e = 0; e < 4; e++) S[j][e] = 0.f;
        #pragma unroll
        for (int kk = 0; kk < 4; kk++) {
            const u32 koff = stg + (((lane & 7) + ((lane & 16) >> 1))*ASTR + kk*16 + (lane & 8)) * 2;
            u32 kh4[4][4];
            #pragma unroll
            for (int jp = 0; jp < 4; jp++) ldsm4(kh4[jp], smb + koff + jp*16*ASTR*2);
            #pragma unroll
            for (int jp = 0; jp < 4; jp++) {
                mma_fp16(S[2*jp],   qh[kk], kh4[jp]);
                mma_fp16(S[2*jp+1], qh[kk], kh4[jp]+2);
            }
        }

        // ---- softmax + split P to fp16 hi/lo ----
        u32 aPh[4][4], aPl[4][4];
        #pragma unroll
        for (int j = 0; j < 8; j++) {
            int kc = k0 + j*8 + 2*(lane & 3);
            float kf = (float)kc;
            float m0 = mk[kc], m1 = mk[kc + 1];
            float p0 = __expf(S[j][0]*ATTN_SCALE - slope*fabsf(qf0 - kf)       + m0);
            float p1 = __expf(S[j][1]*ATTN_SCALE - slope*fabsf(qf0 - kf - 1.f) + m1);
            float p2 = __expf(S[j][2]*ATTN_SCALE - slope*fabsf(qf1 - kf)       + m0);
            float p3 = __expf(S[j][3]*ATTN_SCALE - slope*fabsf(qf1 - kf - 1.f) + m1);
            dn0 += p0 + p1;
            dn1 += p2 + p3;
            u32 h01, l01, h23, l23;
            split_pack_h(p0, p1, h01, l01);
            split_pack_h(p2, p3, h23, l23);
            int t = j >> 1, o = (j & 1) * 2;
            aPh[t][o]   = h01; aPl[t][o]   = l01;
            aPh[t][o+1] = h23; aPl[t][o+1] = l23;
        }

        // ---- O += P V (Ph*Vh + Pl*Vh), pass-major ----
        #pragma unroll
        for (int t = 0; t < 4; t++) {
            const u32 voff = stg + 9216 + ((t*16 + (lane & 15))*ASTR + (lane >> 4)*8) * 2;
            u32 vh4[4][4];
            #pragma unroll
            for (int jp = 0; jp < 4; jp++) ldsm4t(vh4[jp], smb + voff + jp*16*2);
            #pragma unroll
            for (int jp = 0; jp < 4; jp++) {
                mma_fp16(O[2*jp],   aPh[t], vh4[jp]);
                mma_fp16(O[2*jp+1], aPh[t], vh4[jp]+2);
            }
            #pragma unroll
            for (int jp = 0; jp < 4; jp++) {
                mma_fp16(O[2*jp],   aPl[t], vh4[jp]);
                mma_fp16(O[2*jp+1], aPl[t], vh4[jp]+2);
            }
        }
    }
#undef ISSUE_ARR
#undef ISSUE_CHUNK

    #pragma unroll
    for (int m_ = 1; m_ < 4; m_ <<= 1) {
        dn0 += __shfl_xor_sync(0xffffffffu, dn0, m_);
        dn1 += __shfl_xor_sync(0xffffffffu, dn1, m_);
    }
    const float inv0 = 1.f / dn0, inv1 = 1.f / dn1;

    // ctx written as bf16 hi/lo for the 3-pass output projection
    const int q0 = qb*128 + wid*16 + (lane >> 2);
    const int q1 = q0 + 8;
    #pragma unroll
    for (int j = 0; j < 8; j++) {
        int d = h*64 + j*8 + 2*(lane & 3);
        u32 hi, lo;
        split_pack(O[j][0]*inv0, O[j][1]*inv0, hi, lo);
        size_t b0 = ((size_t)b*NS + q0)*ND + d;
        *(u32*)&g_ch[b0] = hi; *(u32*)&g_cl[b0] = lo;
        split_pack(O[j][2]*inv1, O[j][3]*inv1, hi, lo);
        size_t b1 = ((size_t)b*NS + q1)*ND + d;
        *(u32*)&g_ch[b1] = hi; *(u32*)&g_cl[b1] = lo;
    }
}

// ---------------- launch -----------------------------------------------------
extern "C" void kernel_launch(void* const* d_in, const int* in_sizes, int n_in,
                              void* d_out, int out_size)
{
    const float* x     = (const float*)d_in[0];
    const void*  mask  = d_in[1];
    const float* Wqkv  = (const float*)d_in[2];
    const float* bqkv  = (const float*)d_in[3];
    const float* Wproj = (const float*)d_in[4];
    const float* bproj = (const float*)d_in[5];
    float* out = (float*)d_out;

    (void)in_sizes; (void)n_in; (void)out_size;

    static bool inited = false;
    static __nv_bfloat16 *p_xh,*p_xl,*p_wqh,*p_wql,*p_wph,*p_wpl,*p_ch,*p_cl;
    if (!inited) {
        cudaFuncSetAttribute(gemm_mma<1>, cudaFuncAttributeMaxDynamicSharedMemorySize, GSMEM);
        cudaFuncSetAttribute(gemm_mma<0>, cudaFuncAttributeMaxDynamicSharedMemorySize, GSMEM);
        cudaFuncSetAttribute(attn_mma,    cudaFuncAttributeMaxDynamicSharedMemorySize, ASMEM);
        cudaGetSymbolAddress((void**)&p_xh, g_xh);   cudaGetSymbolAddress((void**)&p_xl, g_xl);
        cudaGetSymbolAddress((void**)&p_wqh, g_wqh); cudaGetSymbolAddress((void**)&p_wql, g_wql);
        cudaGetSymbolAddress((void**)&p_wph, g_wph); cudaGetSymbolAddress((void**)&p_wpl, g_wpl);
        cudaGetSymbolAddress((void**)&p_ch, g_ch);   cudaGetSymbolAddress((void**)&p_cl, g_cl);
        inited = true;
    }

    detect_mask_kernel<<<1, 1024>>>((const unsigned int*)mask);

    split_kernel<<<(NM*ND/4 + 255)/256, 256>>>(x, p_xh, p_xl, NM*ND/4);
    split_kernel<<<(NQKV*ND/4 + 255)/256, 256>>>(Wqkv, p_wqh, p_wql, NQKV*ND/4);
    split_kernel<<<(ND*ND/4 + 255)/256, 256>>>(Wproj, p_wph, p_wpl, ND*ND/4);

    gemm_mma<1><<<dim3(NQKV/128, NM/128), 256, GSMEM>>>(
        p_xh, p_xl, p_wqh, p_wql, bqkv, nullptr);

    attn_mma<<<dim3(NS/128, NH, NB), 256, ASMEM>>>(mask);

    gemm_mma<0><<<dim3(ND/128, NM/128), 256, GSMEM>>>(
        p_ch, p_cl, p_wph, p_wpl, bproj, out);
}

// round 10
// speedup vs baseline: 5.3026x; 1.2315x over previous
#include <cuda_runtime.h>
#include <cuda_bf16.h>
#include <cuda_fp16.h>

// Problem constants
#define NB 2
#define NS 2048
#define ND 1024
#define NH 16
#define DH 64
#define NM (NB*NS)        // 4096
#define NQKV (3*ND)       // 3072
#define ATTN_SCALE 0.03125f

typedef unsigned long long u64;
typedef unsigned int u32;

// ---------------- scratch (device globals) -----------------------------------
__device__ int g_mask_mode;
__device__ __nv_bfloat16 g_xh[(size_t)NM*ND],   g_xl[(size_t)NM*ND];
__device__ __nv_bfloat16 g_wqh[(size_t)NQKV*ND],g_wql[(size_t)NQKV*ND];
__device__ __half g_wpf[(size_t)ND*ND];      // Wproj fp16
__device__ __half g_cf[(size_t)NM*ND];       // ctx fp16
#define QKV_ELEMS (NB*NH*NS*DH)
__device__ __half g_Qf[QKV_ELEMS], g_Kf[QKV_ELEMS], g_Vf[QKV_ELEMS];

// ---------------- PTX helpers ------------------------------------------------
__device__ __forceinline__ u32 smem_u32(const void* p){
    u32 a; asm("{ .reg .u64 t; cvta.to.shared.u64 t, %1; cvt.u32.u64 %0, t; }" : "=r"(a) : "l"(p));
    return a;
}
__device__ __forceinline__ void ldsm4(u32* r, u32 addr){
    asm volatile("ldmatrix.sync.aligned.m8n8.x4.shared.b16 {%0,%1,%2,%3}, [%4];"
        : "=r"(r[0]),"=r"(r[1]),"=r"(r[2]),"=r"(r[3]) : "r"(addr));
}
__device__ __forceinline__ void ldsm4t(u32* r, u32 addr){
    asm volatile("ldmatrix.sync.aligned.m8n8.x4.trans.shared.b16 {%0,%1,%2,%3}, [%4];"
        : "=r"(r[0]),"=r"(r[1]),"=r"(r[2]),"=r"(r[3]) : "r"(addr));
}
__device__ __forceinline__ void mma_bf16(float* c, const u32* a, const u32* b){
    asm volatile("mma.sync.aligned.m16n8k16.row.col.f32.bf16.bf16.f32 "
        "{%0,%1,%2,%3}, {%4,%5,%6,%7}, {%8,%9}, {%0,%1,%2,%3};"
        : "+f"(c[0]),"+f"(c[1]),"+f"(c[2]),"+f"(c[3])
        : "r"(a[0]),"r"(a[1]),"r"(a[2]),"r"(a[3]), "r"(b[0]),"r"(b[1]));
}
__device__ __forceinline__ void mma_fp16(float* c, const u32* a, const u32* b){
    asm volatile("mma.sync.aligned.m16n8k16.row.col.f32.f16.f16.f32 "
        "{%0,%1,%2,%3}, {%4,%5,%6,%7}, {%8,%9}, {%0,%1,%2,%3};"
        : "+f"(c[0]),"+f"(c[1]),"+f"(c[2]),"+f"(c[3])
        : "r"(a[0]),"r"(a[1]),"r"(a[2]),"r"(a[3]), "r"(b[0]),"r"(b[1]));
}
__device__ __forceinline__ void split_pack(float a, float b, u32& hi, u32& lo){
    __nv_bfloat16 ha = __float2bfloat16(a), hb = __float2bfloat16(b);
    float ra = a - __bfloat162float(ha), rb = b - __bfloat162float(hb);
    __nv_bfloat162 H; H.x = ha; H.y = hb;
    __nv_bfloat162 L; L.x = __float2bfloat16(ra); L.y = __float2bfloat16(rb);
    hi = *(u32*)&H; lo = *(u32*)&L;
}
__device__ __forceinline__ u32 pack_h2(float a, float b){
    __half2 H; H.x = __float2half_rn(a); H.y = __float2half_rn(b);
    return *(u32*)&H;
}
__device__ __forceinline__ void cp16(u32 dst, const void* src){
    asm volatile("cp.async.cg.shared.global [%0], [%1], 16;" :: "r"(dst), "l"(src));
}
#define CP_COMMIT() asm volatile("cp.async.commit_group;" ::: "memory")
#define CP_WAIT(n)  asm volatile("cp.async.wait_group %0;" :: "n"(n) : "memory")

// ---------------- mask dtype detector ----------------------------------------
__global__ void detect_mask_kernel(const unsigned int* __restrict__ w){
    __shared__ int not_f, not_i;
    int t = threadIdx.x;
    if (t == 0){ not_f = 0; not_i = 0; }
    __syncthreads();
    unsigned v = w[t];
    if (v != 0u && v != 0x3F800000u) atomicExch(&not_f, 1);
    if (v > 1u)                      atomicExch(&not_i, 1);
    __syncthreads();
    if (t == 0) g_mask_mode = (not_f == 0) ? 2 : ((not_i == 0) ? 1 : 0);
}

// ---------------- fp32 -> (hi,lo) bf16 split ---------------------------------
__global__ void __launch_bounds__(256) split_kernel(
    const float* __restrict__ src, __nv_bfloat16* __restrict__ hi,
    __nv_bfloat16* __restrict__ lo, int n4)
{
    int i = blockIdx.x * 256 + threadIdx.x;
    if (i >= n4) return;
    float4 v = ((const float4*)src)[i];
    u32 h0, l0, h1, l1;
    split_pack(v.x, v.y, h0, l0);
    split_pack(v.z, v.w, h1, l1);
    ((uint2*)hi)[i] = make_uint2(h0, h1);
    ((uint2*)lo)[i] = make_uint2(l0, l1);
}

// ---------------- fp32 -> fp16 convert ---------------------------------------
__global__ void __launch_bounds__(256) cvt_f16_kernel(
    const float* __restrict__ src, __half* __restrict__ dst, int n4)
{
    int i = blockIdx.x * 256 + threadIdx.x;
    if (i >= n4) return;
    float4 v = ((const float4*)src)[i];
    ((uint2*)dst)[i] = make_uint2(pack_h2(v.x, v.y), pack_h2(v.z, v.w));
}

// ---------------- QKV GEMM: bf16 3-pass, 3-stage cp.async --------------------
#define GSTRIDE 40
#define GMAT (128*GSTRIDE*2)   // 10240
#define GSTAGE (4*GMAT)        // 40960
#define GSMEM  (3*GSTAGE)      // 122880
#define GNCH (ND/32)           // 32

__global__ void __launch_bounds__(256) gemm_qkv(
    const __nv_bfloat16* __restrict__ Ah, const __nv_bfloat16* __restrict__ Al,
    const __nv_bfloat16* __restrict__ Bh, const __nv_bfloat16* __restrict__ Bl,
    const float* __restrict__ bias)
{
    extern __shared__ __align__(16) char sm[];
    const u32 smb = smem_u32(sm);
    const int tid = threadIdx.x, lane = tid & 31, wid = tid >> 5;
    const int wm = wid >> 2, wn = wid & 3;

    const __nv_bfloat16* APh = Ah + (size_t)blockIdx.y * 128 * ND;
    const __nv_bfloat16* APl = Al + (size_t)blockIdx.y * 128 * ND;
    const __nv_bfloat16* BPh = Bh + (size_t)blockIdx.x * 128 * ND;
    const __nv_bfloat16* BPl = Bl + (size_t)blockIdx.x * 128 * ND;

    float C[4][4][4];
    #pragma unroll
    for (int i = 0; i < 4; i++)
        #pragma unroll
        for (int j = 0; j < 4; j++)
            #pragma unroll
            for (int e = 0; e < 4; e++) C[i][j][e] = 0.f;

#define G_ISSUE(k0, st) do { \
    _Pragma("unroll") \
    for (int t = 0; t < 2; t++) { \
        int u_ = tid + 256*t; int row = u_ >> 2; int cb = (u_ & 3) * 8; \
        size_t go = (size_t)row * ND + (k0) + cb; \
        u32 so = (st) + (u32)((row*GSTRIDE + cb)*2); \
        cp16(smb + so + 0*GMAT, APh + go); cp16(smb + so + 1*GMAT, APl + go); \
        cp16(smb + so + 2*GMAT, BPh + go); cp16(smb + so + 3*GMAT, BPl + go); \
    } } while(0)

    G_ISSUE(0, 0u);        CP_COMMIT();
    G_ISSUE(32, GSTAGE);   CP_COMMIT();

    for (int c = 0; c < GNCH; c++) {
        if (c + 2 < GNCH) CP_WAIT(1); else CP_WAIT(0);
        __syncthreads();
        const u32 st = (u32)(c % 3) * GSTAGE;
        if (c + 2 < GNCH) { G_ISSUE((c + 2)*32, (u32)((c + 2) % 3) * GSTAGE); CP_COMMIT(); }

        #pragma unroll
        for (int kk = 0; kk < 2; kk++) {
            const u32 aoff = ((wm*64 + (lane & 15))*GSTRIDE + kk*16 + (lane >> 4)*8) * 2;
            const u32 boff = ((wn*32 + (lane & 7) + ((lane & 16) >> 1))*GSTRIDE + kk*16 + (lane & 8)) * 2;

            u32 ah[4][4], bh_[4][2];
            #pragma unroll
            for (int i = 0; i < 4; i++) ldsm4(ah[i], smb + st + 0*GMAT + aoff + i*16*GSTRIDE*2);
            #pragma unroll
            for (int jp = 0; jp < 2; jp++) {
                u32 t4[4];
                ldsm4(t4, smb + st + 2*GMAT + boff + jp*16*GSTRIDE*2);
                bh_[2*jp][0]=t4[0]; bh_[2*jp][1]=t4[1]; bh_[2*jp+1][0]=t4[2]; bh_[2*jp+1][1]=t4[3];
            }
            #pragma unroll
            for (int i = 0; i < 4; i++)
                #pragma unroll
                for (int j = 0; j < 4; j++) mma_bf16(C[i][j], ah[i], bh_[j]);
            u32 al[4][4];
            #pragma unroll
            for (int i = 0; i < 4; i++) ldsm4(al[i], smb + st + 1*GMAT + aoff + i*16*GSTRIDE*2);
            #pragma unroll
            for (int i = 0; i < 4; i++)
                #pragma unroll
                for (int j = 0; j < 4; j++) mma_bf16(C[i][j], al[i], bh_[j]);
            u32 bl_[4][2];
            #pragma unroll
            for (int jp = 0; jp < 2; jp++) {
                u32 t4[4];
                ldsm4(t4, smb + st + 3*GMAT + boff + jp*16*GSTRIDE*2);
                bl_[2*jp][0]=t4[0]; bl_[2*jp][1]=t4[1]; bl_[2*jp+1][0]=t4[2]; bl_[2*jp+1][1]=t4[3];
            }
            #pragma unroll
            for (int i = 0; i < 4; i++)
                #pragma unroll
                for (int j = 0; j < 4; j++) mma_bf16(C[i][j], ah[i], bl_[j]);
        }
    }
#undef G_ISSUE

    const int mb = blockIdx.y*128 + wm*64;
    const int nb = blockIdx.x*128 + wn*32;
    #pragma unroll
    for (int i = 0; i < 4; i++) {
        #pragma unroll
        for (int j = 0; j < 4; j++) {
            int n = nb + j*8 + 2*(lane & 3);
            float2 bz = *(const float2*)(bias + n);
            int m0 = mb + i*16 + (lane >> 2);
            int m1 = m0 + 8;
            // qkv col n -> head n/192, part (n%192)/64, d = n%64; fp16 hi-only
            int h = n / 192, rem = n - h*192, part = rem >> 6, d = rem & 63;
            __half* dst = (part==0) ? g_Qf : (part==1 ? g_Kf : g_Vf);
            {
                int bb = m0 >> 11, ss = m0 & (NS-1);
                size_t base = (((size_t)bb*NH + h)*NS + ss)*DH + d;
                *(u32*)&dst[base] = pack_h2(C[i][j][0] + bz.x, C[i][j][1] + bz.y);
            }
            {
                int bb = m1 >> 11, ss = m1 & (NS-1);
                size_t base = (((size_t)bb*NH + h)*NS + ss)*DH + d;
                *(u32*)&dst[base] = pack_h2(C[i][j][2] + bz.x, C[i][j][3] + bz.y);
            }
        }
    }
}

// ---------------- output projection: fp16 1-pass -----------------------------
#define FSTAGE (2*GMAT)        // 20480
#define FSMEM  (3*FSTAGE)      // 61440

__global__ void __launch_bounds__(256) gemm_out(
    const __half* __restrict__ A, const __half* __restrict__ B,
    const float* __restrict__ bias, float* __restrict__ Cout)
{
    extern __shared__ __align__(16) char sm[];
    const u32 smb = smem_u32(sm);
    const int tid = threadIdx.x, lane = tid & 31, wid = tid >> 5;
    const int wm = wid >> 2, wn = wid & 3;

    const __half* AP = A + (size_t)blockIdx.y * 128 * ND;
    const __half* BP = B + (size_t)blockIdx.x * 128 * ND;

    float C[4][4][4];
    #pragma unroll
    for (int i = 0; i < 4; i++)
        #pragma unroll
        for (int j = 0; j < 4; j++)
            #pragma unroll
            for (int e = 0; e < 4; e++) C[i][j][e] = 0.f;

#define F_ISSUE(k0, st) do { \
    _Pragma("unroll") \
    for (int t = 0; t < 2; t++) { \
        int u_ = tid + 256*t; int row = u_ >> 2; int cb = (u_ & 3) * 8; \
        size_t go = (size_t)row * ND + (k0) + cb; \
        u32 so = (st) + (u32)((row*GSTRIDE + cb)*2); \
        cp16(smb + so + 0*GMAT, AP + go); cp16(smb + so + 1*GMAT, BP + go); \
    } } while(0)

    F_ISSUE(0, 0u);        CP_COMMIT();
    F_ISSUE(32, FSTAGE);   CP_COMMIT();

    for (int c = 0; c < GNCH; c++) {
        if (c + 2 < GNCH) CP_WAIT(1); else CP_WAIT(0);
        __syncthreads();
        const u32 st = (u32)(c % 3) * FSTAGE;
        if (c + 2 < GNCH) { F_ISSUE((c + 2)*32, (u32)((c + 2) % 3) * FSTAGE); CP_COMMIT(); }

        #pragma unroll
        for (int kk = 0; kk < 2; kk++) {
            const u32 aoff = ((wm*64 + (lane & 15))*GSTRIDE + kk*16 + (lane >> 4)*8) * 2;
            const u32 boff = ((wn*32 + (lane & 7) + ((lane & 16) >> 1))*GSTRIDE + kk*16 + (lane & 8)) * 2;

            u32 ah[4][4], bh_[4][2];
            #pragma unroll
            for (int i = 0; i < 4; i++) ldsm4(ah[i], smb + st + 0*GMAT + aoff + i*16*GSTRIDE*2);
            #pragma unroll
            for (int jp = 0; jp < 2; jp++) {
                u32 t4[4];
                ldsm4(t4, smb + st + 1*GMAT + boff + jp*16*GSTRIDE*2);
                bh_[2*jp][0]=t4[0]; bh_[2*jp][1]=t4[1]; bh_[2*jp+1][0]=t4[2]; bh_[2*jp+1][1]=t4[3];
            }
            #pragma unroll
            for (int i = 0; i < 4; i++)
                #pragma unroll
                for (int j = 0; j < 4; j++) mma_fp16(C[i][j], ah[i], bh_[j]);
        }
    }
#undef F_ISSUE

    const int mb = blockIdx.y*128 + wm*64;
    const int nb = blockIdx.x*128 + wn*32;
    #pragma unroll
    for (int i = 0; i < 4; i++) {
        #pragma unroll
        for (int j = 0; j < 4; j++) {
            int n = nb + j*8 + 2*(lane & 3);
            float2 bz = *(const float2*)(bias + n);
            int m0 = mb + i*16 + (lane >> 2);
            int m1 = m0 + 8;
            *(float2*)&Cout[(size_t)m0*ND + n] = make_float2(C[i][j][0] + bz.x, C[i][j][1] + bz.y);
            *(float2*)&Cout[(size_t)m1*ND + n] = make_float2(C[i][j][2] + bz.x, C[i][j][3] + bz.y);
        }
    }
}

// ---------------- attention: fp16, QK 1-pass, PV 1-pass ----------------------
// Block = (b, h, 128-q tile), 8 warps. 64-key chunks, 3-stage cp.async.
#define ASTR 72
#define ASTAGE 18432
#define AMSK  (3*ASTAGE)           // 55296
#define ASMEM (AMSK + NS*4)        // 63488
#define NCH (NS/64)                // 32

__global__ void __launch_bounds__(256) attn_mma(const void* __restrict__ maskp)
{
    extern __shared__ __align__(16) char sm[];
    const u32 smb = smem_u32(sm);
    float* mk = (float*)(sm + AMSK);
    const int tid = threadIdx.x, lane = tid & 31, wid = tid >> 5;
    const int qb = blockIdx.x, h = blockIdx.y, b = blockIdx.z;

    const size_t hb = ((size_t)(b*NH + h)) * NS * DH;
    const __half* Qp = g_Qf + hb + (size_t)qb*128*DH;
    const __half* Kp = g_Kf + hb;
    const __half* Vp = g_Vf + hb;

    const float slope = exp2f(-0.5f * (float)(h + 1));
    const int mode = g_mask_mode;

    // stage Q (128 rows x 64 halves) through stage 0; mask -> mk
    #pragma unroll
    for (int t = 0; t < 4; t++) {
        int idx = tid + 256*t; int row = idx >> 3; int cb = (idx & 7) * 8;
        *(uint4*)(sm + (u32)((row*ASTR + cb)*2)) = *(const uint4*)(Qp + row*DH + cb);
    }
    for (int i = tid; i < NS; i += 256) {
        bool mv;
        if      (mode == 0) mv = ((const unsigned char*)maskp)[b*NS + i] != 0;
        else if (mode == 1) mv = ((const int*)maskp)[b*NS + i] != 0;
        else                mv = ((const float*)maskp)[b*NS + i] != 0.f;
        mk[i] = mv ? 0.f : -1e30f;
    }
    __syncthreads();

    u32 qh[4][4];
    #pragma unroll
    for (int kk = 0; kk < 4; kk++) {
        u32 off = ((wid*16 + (lane & 15))*ASTR + kk*16 + (lane >> 4)*8) * 2;
        ldsm4(qh[kk], smb + off);
    }
    __syncthreads();   // Q staging consumed; stage 0 reusable

#define ISSUE_ARR(ptr, aoff, stg, k0) do { \
    _Pragma("unroll") \
    for (int t = 0; t < 2; t++) { \
        int idx = tid + 256*t; int row = idx >> 3; int cb = (idx & 7) * 8; \
        cp16(smb + (stg) + (aoff) + (u32)((row*ASTR + cb)*2), \
             (ptr) + (size_t)((k0) + row)*DH + cb); \
    } } while(0)
#define ISSUE_CHUNK(k0, stg) do { \
    ISSUE_ARR(Kp, 0,    stg, k0); \
    ISSUE_ARR(Vp, 9216, stg, k0); \
    } while(0)

    float O[8][4];
    #pragma unroll
    for (int j = 0; j < 8; j++)
        #pragma unroll
        for (int e = 0; e < 4; e++) O[j][e] = 0.f;
    float dn0 = 0.f, dn1 = 0.f;
    const float qf0 = (float)(qb*128 + wid*16 + (lane >> 2));
    const float qf1 = qf0 + 8.f;

    ISSUE_CHUNK(0, 0u);       CP_COMMIT();
    ISSUE_CHUNK(64, ASTAGE);  CP_COMMIT();

    for (int c = 0; c < NCH; c++) {
        const int k0 = c * 64;
        if (c + 2 < NCH) CP_WAIT(1); else CP_WAIT(0);
        __syncthreads();
        const u32 stg = (u32)(c % 3) * ASTAGE;
        if (c + 2 < NCH) { ISSUE_CHUNK(k0 + 128, (u32)((c + 2) % 3) * ASTAGE); CP_COMMIT(); }

        // ---- S = Q K^T (single fp16 pass) ----
        float S[8][4];
        #pragma unroll
        for (int j = 0; j < 8; j++)
            #pragma unroll
            for (int e = 0; e < 4; e++) S[j][e] = 0.f;
        #pragma unroll
        for (int kk = 0; kk < 4; kk++) {
            const u32 koff = stg + (((lane & 7) + ((lane & 16) >> 1))*ASTR + kk*16 + (lane & 8)) * 2;
            u32 kh4[4][4];
            #pragma unroll
            for (int jp = 0; jp < 4; jp++) ldsm4(kh4[jp], smb + koff + jp*16*ASTR*2);
            #pragma unroll
            for (int jp = 0; jp < 4; jp++) {
                mma_fp16(S[2*jp],   qh[kk], kh4[jp]);
                mma_fp16(S[2*jp+1], qh[kk], kh4[jp]+2);
            }
        }

        // ---- softmax + pack P fp16 ----
        u32 aPh[4][4];
        #pragma unroll
        for (int j = 0; j < 8; j++) {
            int kc = k0 + j*8 + 2*(lane & 3);
            float kf = (float)kc;
            float m0 = mk[kc], m1 = mk[kc + 1];
            float p0 = __expf(S[j][0]*ATTN_SCALE - slope*fabsf(qf0 - kf)       + m0);
            float p1 = __expf(S[j][1]*ATTN_SCALE - slope*fabsf(qf0 - kf - 1.f) + m1);
            float p2 = __expf(S[j][2]*ATTN_SCALE - slope*fabsf(qf1 - kf)       + m0);
            float p3 = __expf(S[j][3]*ATTN_SCALE - slope*fabsf(qf1 - kf - 1.f) + m1);
            dn0 += p0 + p1;
            dn1 += p2 + p3;
            int t = j >> 1, o = (j & 1) * 2;
            aPh[t][o]   = pack_h2(p0, p1);
            aPh[t][o+1] = pack_h2(p2, p3);
        }

        // ---- O += P V (single fp16 pass) ----
        #pragma unroll
        for (int t = 0; t < 4; t++) {
            const u32 voff = stg + 9216 + ((t*16 + (lane & 15))*ASTR + (lane >> 4)*8) * 2;
            u32 vh4[4][4];
            #pragma unroll
            for (int jp = 0; jp < 4; jp++) ldsm4t(vh4[jp], smb + voff + jp*16*2);
            #pragma unroll
            for (int jp = 0; jp < 4; jp++) {
                mma_fp16(O[2*jp],   aPh[t], vh4[jp]);
                mma_fp16(O[2*jp+1], aPh[t], vh4[jp]+2);
            }
        }
    }
#undef ISSUE_ARR
#undef ISSUE_CHUNK

    #pragma unroll
    for (int m_ = 1; m_ < 4; m_ <<= 1) {
        dn0 += __shfl_xor_sync(0xffffffffu, dn0, m_);
        dn1 += __shfl_xor_sync(0xffffffffu, dn1, m_);
    }
    const float inv0 = 1.f / dn0, inv1 = 1.f / dn1;

    // ctx written as fp16 for the 1-pass output projection
    const int q0 = qb*128 + wid*16 + (lane >> 2);
    const int q1 = q0 + 8;
    #pragma unroll
    for (int j = 0; j < 8; j++) {
        int d = h*64 + j*8 + 2*(lane & 3);
        size_t b0 = ((size_t)b*NS + q0)*ND + d;
        *(u32*)&g_cf[b0] = pack_h2(O[j][0]*inv0, O[j][1]*inv0);
        size_t b1 = ((size_t)b*NS + q1)*ND + d;
        *(u32*)&g_cf[b1] = pack_h2(O[j][2]*inv1, O[j][3]*inv1);
    }
}

// ---------------- launch -----------------------------------------------------
extern "C" void kernel_launch(void* const* d_in, const int* in_sizes, int n_in,
                              void* d_out, int out_size)
{
    const float* x     = (const float*)d_in[0];
    const void*  mask  = d_in[1];
    const float* Wqkv  = (const float*)d_in[2];
    const float* bqkv  = (const float*)d_in[3];
    const float* Wproj = (const float*)d_in[4];
    const float* bproj = (const float*)d_in[5];
    float* out = (float*)d_out;

    (void)in_sizes; (void)n_in; (void)out_size;

    static bool inited = false;
    static __nv_bfloat16 *p_xh,*p_xl,*p_wqh,*p_wql;
    static __half *p_wpf, *p_cf;
    if (!inited) {
        cudaFuncSetAttribute(gemm_qkv, cudaFuncAttributeMaxDynamicSharedMemorySize, GSMEM);
        cudaFuncSetAttribute(gemm_out, cudaFuncAttributeMaxDynamicSharedMemorySize, FSMEM);
        cudaFuncSetAttribute(attn_mma, cudaFuncAttributeMaxDynamicSharedMemorySize, ASMEM);
        cudaGetSymbolAddress((void**)&p_xh, g_xh);   cudaGetSymbolAddress((void**)&p_xl, g_xl);
        cudaGetSymbolAddress((void**)&p_wqh, g_wqh); cudaGetSymbolAddress((void**)&p_wql, g_wql);
        cudaGetSymbolAddress((void**)&p_wpf, g_wpf); cudaGetSymbolAddress((void**)&p_cf, g_cf);
        inited = true;
    }

    detect_mask_kernel<<<1, 1024>>>((const unsigned int*)mask);

    split_kernel<<<(NM*ND/4 + 255)/256, 256>>>(x, p_xh, p_xl, NM*ND/4);
    split_kernel<<<(NQKV*ND/4 + 255)/256, 256>>>(Wqkv, p_wqh, p_wql, NQKV*ND/4);
    cvt_f16_kernel<<<(ND*ND/4 + 255)/256, 256>>>(Wproj, p_wpf, ND*ND/4);

    gemm_qkv<<<dim3(NQKV/128, NM/128), 256, GSMEM>>>(
        p_xh, p_xl, p_wqh, p_wql, bqkv);

    attn_mma<<<dim3(NS/128, NH, NB), 256, ASMEM>>>(mask);

    gemm_out<<<dim3(ND/128, NM/128), 256, FSMEM>>>(
        p_cf, p_wpf, bproj, out);
}

// round 11
// speedup vs baseline: 6.8023x; 1.2828x over previous
#include <cuda_runtime.h>
#include <cuda_fp16.h>

// Problem constants
#define NB 2
#define NS 2048
#define ND 1024
#define NH 16
#define DH 64
#define NM (NB*NS)        // 4096
#define NQKV (3*ND)       // 3072
#define ATTN_SCALE 0.03125f

typedef unsigned long long u64;
typedef unsigned int u32;

// ---------------- scratch (device globals) -----------------------------------
__device__ int g_mask_mode;
__device__ __half g_xhh[(size_t)NM*ND], g_xhl[(size_t)NM*ND];  // x fp16 hi/lo
__device__ __half g_wqf[(size_t)NQKV*ND];    // Wqkv fp16
__device__ __half g_wpf[(size_t)ND*ND];      // Wproj fp16
__device__ __half g_cf[(size_t)NM*ND];       // ctx fp16
#define QKV_ELEMS (NB*NH*NS*DH)
__device__ __half g_Qf[QKV_ELEMS], g_Kf[QKV_ELEMS], g_Vf[QKV_ELEMS];

// ---------------- PTX helpers ------------------------------------------------
__device__ __forceinline__ u32 smem_u32(const void* p){
    u32 a; asm("{ .reg .u64 t; cvta.to.shared.u64 t, %1; cvt.u32.u64 %0, t; }" : "=r"(a) : "l"(p));
    return a;
}
__device__ __forceinline__ void ldsm4(u32* r, u32 addr){
    asm volatile("ldmatrix.sync.aligned.m8n8.x4.shared.b16 {%0,%1,%2,%3}, [%4];"
        : "=r"(r[0]),"=r"(r[1]),"=r"(r[2]),"=r"(r[3]) : "r"(addr));
}
__device__ __forceinline__ void ldsm4t(u32* r, u32 addr){
    asm volatile("ldmatrix.sync.aligned.m8n8.x4.trans.shared.b16 {%0,%1,%2,%3}, [%4];"
        : "=r"(r[0]),"=r"(r[1]),"=r"(r[2]),"=r"(r[3]) : "r"(addr));
}
__device__ __forceinline__ void mma_fp16(float* c, const u32* a, const u32* b){
    asm volatile("mma.sync.aligned.m16n8k16.row.col.f32.f16.f16.f32 "
        "{%0,%1,%2,%3}, {%4,%5,%6,%7}, {%8,%9}, {%0,%1,%2,%3};"
        : "+f"(c[0]),"+f"(c[1]),"+f"(c[2]),"+f"(c[3])
        : "r"(a[0]),"r"(a[1]),"r"(a[2]),"r"(a[3]), "r"(b[0]),"r"(b[1]));
}
__device__ __forceinline__ void split_pack_h(float a, float b, u32& hi, u32& lo){
    __half ha = __float2half_rn(a), hb = __float2half_rn(b);
    float ra = a - __half2float(ha), rb = b - __half2float(hb);
    __half2 H; H.x = ha; H.y = hb;
    __half2 L; L.x = __float2half_rn(ra); L.y = __float2half_rn(rb);
    hi = *(u32*)&H; lo = *(u32*)&L;
}
__device__ __forceinline__ u32 pack_h2(float a, float b){
    __half2 H; H.x = __float2half_rn(a); H.y = __float2half_rn(b);
    return *(u32*)&H;
}
__device__ __forceinline__ void cp16(u32 dst, const void* src){
    asm volatile("cp.async.cg.shared.global [%0], [%1], 16;" :: "r"(dst), "l"(src));
}
#define CP_COMMIT() asm volatile("cp.async.commit_group;" ::: "memory")
#define CP_WAIT(n)  asm volatile("cp.async.wait_group %0;" :: "n"(n) : "memory")

// ---------------- mask dtype detector ----------------------------------------
__global__ void detect_mask_kernel(const unsigned int* __restrict__ w){
    __shared__ int not_f, not_i;
    int t = threadIdx.x;
    if (t == 0){ not_f = 0; not_i = 0; }
    __syncthreads();
    unsigned v = w[t];
    if (v != 0u && v != 0x3F800000u) atomicExch(&not_f, 1);
    if (v > 1u)                      atomicExch(&not_i, 1);
    __syncthreads();
    if (t == 0) g_mask_mode = (not_f == 0) ? 2 : ((not_i == 0) ? 1 : 0);
}

// ---------------- fp32 -> (hi,lo) fp16 split ---------------------------------
__global__ void __launch_bounds__(256) split_h_kernel(
    const float* __restrict__ src, __half* __restrict__ hi,
    __half* __restrict__ lo, int n4)
{
    int i = blockIdx.x * 256 + threadIdx.x;
    if (i >= n4) return;
    float4 v = ((const float4*)src)[i];
    u32 h0, l0, h1, l1;
    split_pack_h(v.x, v.y, h0, l0);
    split_pack_h(v.z, v.w, h1, l1);
    ((uint2*)hi)[i] = make_uint2(h0, h1);
    ((uint2*)lo)[i] = make_uint2(l0, l1);
}

// ---------------- fp32 -> fp16 convert ---------------------------------------
__global__ void __launch_bounds__(256) cvt_f16_kernel(
    const float* __restrict__ src, __half* __restrict__ dst, int n4)
{
    int i = blockIdx.x * 256 + threadIdx.x;
    if (i >= n4) return;
    float4 v = ((const float4*)src)[i];
    ((uint2*)dst)[i] = make_uint2(pack_h2(v.x, v.y), pack_h2(v.z, v.w));
}

// ---------------- common GEMM geometry ---------------------------------------
#define GSTRIDE 40
#define GMAT (128*GSTRIDE*2)   // 10240
#define GNCH (ND/32)           // 32

// ---------------- QKV GEMM: fp16 2-pass (xh*W + xl*W), 3-stage cp.async ------
#define QSTAGE (3*GMAT)        // 30720
#define QSMEM  (3*QSTAGE)      // 92160

__global__ void __launch_bounds__(256) gemm_qkv(
    const __half* __restrict__ Ah, const __half* __restrict__ Al,
    const __half* __restrict__ B, const float* __restrict__ bias)
{
    extern __shared__ __align__(16) char sm[];
    const u32 smb = smem_u32(sm);
    const int tid = threadIdx.x, lane = tid & 31, wid = tid >> 5;
    const int wm = wid >> 2, wn = wid & 3;

    const __half* APh = Ah + (size_t)blockIdx.y * 128 * ND;
    const __half* APl = Al + (size_t)blockIdx.y * 128 * ND;
    const __half* BP  = B  + (size_t)blockIdx.x * 128 * ND;

    float C[4][4][4];
    #pragma unroll
    for (int i = 0; i < 4; i++)
        #pragma unroll
        for (int j = 0; j < 4; j++)
            #pragma unroll
            for (int e = 0; e < 4; e++) C[i][j][e] = 0.f;

#define Q_ISSUE(k0, st) do { \
    _Pragma("unroll") \
    for (int t = 0; t < 2; t++) { \
        int u_ = tid + 256*t; int row = u_ >> 2; int cb = (u_ & 3) * 8; \
        size_t go = (size_t)row * ND + (k0) + cb; \
        u32 so = (st) + (u32)((row*GSTRIDE + cb)*2); \
        cp16(smb + so + 0*GMAT, APh + go); cp16(smb + so + 1*GMAT, APl + go); \
        cp16(smb + so + 2*GMAT, BP + go); \
    } } while(0)

    Q_ISSUE(0, 0u);        CP_COMMIT();
    Q_ISSUE(32, QSTAGE);   CP_COMMIT();

    for (int c = 0; c < GNCH; c++) {
        if (c + 2 < GNCH) CP_WAIT(1); else CP_WAIT(0);
        __syncthreads();
        const u32 st = (u32)(c % 3) * QSTAGE;
        if (c + 2 < GNCH) { Q_ISSUE((c + 2)*32, (u32)((c + 2) % 3) * QSTAGE); CP_COMMIT(); }

        #pragma unroll
        for (int kk = 0; kk < 2; kk++) {
            const u32 aoff = ((wm*64 + (lane & 15))*GSTRIDE + kk*16 + (lane >> 4)*8) * 2;
            const u32 boff = ((wn*32 + (lane & 7) + ((lane & 16) >> 1))*GSTRIDE + kk*16 + (lane & 8)) * 2;

            u32 ah[4][4], bh_[4][2];
            #pragma unroll
            for (int i = 0; i < 4; i++) ldsm4(ah[i], smb + st + 0*GMAT + aoff + i*16*GSTRIDE*2);
            #pragma unroll
            for (int jp = 0; jp < 2; jp++) {
                u32 t4[4];
                ldsm4(t4, smb + st + 2*GMAT + boff + jp*16*GSTRIDE*2);
                bh_[2*jp][0]=t4[0]; bh_[2*jp][1]=t4[1]; bh_[2*jp+1][0]=t4[2]; bh_[2*jp+1][1]=t4[3];
            }
            // pass 1: xh * W
            #pragma unroll
            for (int i = 0; i < 4; i++)
                #pragma unroll
                for (int j = 0; j < 4; j++) mma_fp16(C[i][j], ah[i], bh_[j]);
            // pass 2: xl * W
            u32 al[4][4];
            #pragma unroll
            for (int i = 0; i < 4; i++) ldsm4(al[i], smb + st + 1*GMAT + aoff + i*16*GSTRIDE*2);
            #pragma unroll
            for (int i = 0; i < 4; i++)
                #pragma unroll
                for (int j = 0; j < 4; j++) mma_fp16(C[i][j], al[i], bh_[j]);
        }
    }
#undef Q_ISSUE

    const int mb = blockIdx.y*128 + wm*64;
    const int nb = blockIdx.x*128 + wn*32;
    #pragma unroll
    for (int i = 0; i < 4; i++) {
        #pragma unroll
        for (int j = 0; j < 4; j++) {
            int n = nb + j*8 + 2*(lane & 3);
            float2 bz = *(const float2*)(bias + n);
            int m0 = mb + i*16 + (lane >> 2);
            int m1 = m0 + 8;
            // qkv col n -> head n/192, part (n%192)/64, d = n%64; fp16 hi-only
            int h = n / 192, rem = n - h*192, part = rem >> 6, d = rem & 63;
            __half* dst = (part==0) ? g_Qf : (part==1 ? g_Kf : g_Vf);
            {
                int bb = m0 >> 11, ss = m0 & (NS-1);
                size_t base = (((size_t)bb*NH + h)*NS + ss)*DH + d;
                *(u32*)&dst[base] = pack_h2(C[i][j][0] + bz.x, C[i][j][1] + bz.y);
            }
            {
                int bb = m1 >> 11, ss = m1 & (NS-1);
                size_t base = (((size_t)bb*NH + h)*NS + ss)*DH + d;
                *(u32*)&dst[base] = pack_h2(C[i][j][2] + bz.x, C[i][j][3] + bz.y);
            }
        }
    }
}

// ---------------- output projection: fp16 1-pass -----------------------------
#define FSTAGE (2*GMAT)        // 20480
#define FSMEM  (3*FSTAGE)      // 61440

__global__ void __launch_bounds__(256) gemm_out(
    const __half* __restrict__ A, const __half* __restrict__ B,
    const float* __restrict__ bias, float* __restrict__ Cout)
{
    extern __shared__ __align__(16) char sm[];
    const u32 smb = smem_u32(sm);
    const int tid = threadIdx.x, lane = tid & 31, wid = tid >> 5;
    const int wm = wid >> 2, wn = wid & 3;

    const __half* AP = A + (size_t)blockIdx.y * 128 * ND;
    const __half* BP = B + (size_t)blockIdx.x * 128 * ND;

    float C[4][4][4];
    #pragma unroll
    for (int i = 0; i < 4; i++)
        #pragma unroll
        for (int j = 0; j < 4; j++)
            #pragma unroll
            for (int e = 0; e < 4; e++) C[i][j][e] = 0.f;

#define F_ISSUE(k0, st) do { \
    _Pragma("unroll") \
    for (int t = 0; t < 2; t++) { \
        int u_ = tid + 256*t; int row = u_ >> 2; int cb = (u_ & 3) * 8; \
        size_t go = (size_t)row * ND + (k0) + cb; \
        u32 so = (st) + (u32)((row*GSTRIDE + cb)*2); \
        cp16(smb + so + 0*GMAT, AP + go); cp16(smb + so + 1*GMAT, BP + go); \
    } } while(0)

    F_ISSUE(0, 0u);        CP_COMMIT();
    F_ISSUE(32, FSTAGE);   CP_COMMIT();

    for (int c = 0; c < GNCH; c++) {
        if (c + 2 < GNCH) CP_WAIT(1); else CP_WAIT(0);
        __syncthreads();
        const u32 st = (u32)(c % 3) * FSTAGE;
        if (c + 2 < GNCH) { F_ISSUE((c + 2)*32, (u32)((c + 2) % 3) * FSTAGE); CP_COMMIT(); }

        #pragma unroll
        for (int kk = 0; kk < 2; kk++) {
            const u32 aoff = ((wm*64 + (lane & 15))*GSTRIDE + kk*16 + (lane >> 4)*8) * 2;
            const u32 boff = ((wn*32 + (lane & 7) + ((lane & 16) >> 1))*GSTRIDE + kk*16 + (lane & 8)) * 2;

            u32 ah[4][4], bh_[4][2];
            #pragma unroll
            for (int i = 0; i < 4; i++) ldsm4(ah[i], smb + st + 0*GMAT + aoff + i*16*GSTRIDE*2);
            #pragma unroll
            for (int jp = 0; jp < 2; jp++) {
                u32 t4[4];
                ldsm4(t4, smb + st + 1*GMAT + boff + jp*16*GSTRIDE*2);
                bh_[2*jp][0]=t4[0]; bh_[2*jp][1]=t4[1]; bh_[2*jp+1][0]=t4[2]; bh_[2*jp+1][1]=t4[3];
            }
            #pragma unroll
            for (int i = 0; i < 4; i++)
                #pragma unroll
                for (int j = 0; j < 4; j++) mma_fp16(C[i][j], ah[i], bh_[j]);
        }
    }
#undef F_ISSUE

    const int mb = blockIdx.y*128 + wm*64;
    const int nb = blockIdx.x*128 + wn*32;
    #pragma unroll
    for (int i = 0; i < 4; i++) {
        #pragma unroll
        for (int j = 0; j < 4; j++) {
            int n = nb + j*8 + 2*(lane & 3);
            float2 bz = *(const float2*)(bias + n);
            int m0 = mb + i*16 + (lane >> 2);
            int m1 = m0 + 8;
            *(float2*)&Cout[(size_t)m0*ND + n] = make_float2(C[i][j][0] + bz.x, C[i][j][1] + bz.y);
            *(float2*)&Cout[(size_t)m1*ND + n] = make_float2(C[i][j][2] + bz.x, C[i][j][3] + bz.y);
        }
    }
}

// ---------------- attention: fp16, QK 1-pass, PV 1-pass ----------------------
// Block = (b, h, 128-q tile), 8 warps. 64-key chunks, 3-stage cp.async.
#define ASTR 72
#define ASTAGE 18432
#define AMSK  (3*ASTAGE)           // 55296
#define ASMEM (AMSK + NS*4)        // 63488
#define NCH (NS/64)                // 32

__global__ void __launch_bounds__(256) attn_mma(const void* __restrict__ maskp)
{
    extern __shared__ __align__(16) char sm[];
    const u32 smb = smem_u32(sm);
    float* mk = (float*)(sm + AMSK);
    const int tid = threadIdx.x, lane = tid & 31, wid = tid >> 5;
    const int qb = blockIdx.x, h = blockIdx.y, b = blockIdx.z;

    const size_t hb = ((size_t)(b*NH + h)) * NS * DH;
    const __half* Qp = g_Qf + hb + (size_t)qb*128*DH;
    const __half* Kp = g_Kf + hb;
    const __half* Vp = g_Vf + hb;

    const float slope = exp2f(-0.5f * (float)(h + 1));
    const int mode = g_mask_mode;

    // stage Q (128 rows x 64 halves) through stage 0; mask -> mk
    #pragma unroll
    for (int t = 0; t < 4; t++) {
        int idx = tid + 256*t; int row = idx >> 3; int cb = (idx & 7) * 8;
        *(uint4*)(sm + (u32)((row*ASTR + cb)*2)) = *(const uint4*)(Qp + row*DH + cb);
    }
    for (int i = tid; i < NS; i += 256) {
        bool mv;
        if      (mode == 0) mv = ((const unsigned char*)maskp)[b*NS + i] != 0;
        else if (mode == 1) mv = ((const int*)maskp)[b*NS + i] != 0;
        else                mv = ((const float*)maskp)[b*NS + i] != 0.f;
        mk[i] = mv ? 0.f : -1e30f;
    }
    __syncthreads();

    u32 qh[4][4];
    #pragma unroll
    for (int kk = 0; kk < 4; kk++) {
        u32 off = ((wid*16 + (lane & 15))*ASTR + kk*16 + (lane >> 4)*8) * 2;
        ldsm4(qh[kk], smb + off);
    }
    __syncthreads();   // Q staging consumed; stage 0 reusable

#define ISSUE_ARR(ptr, aoff, stg, k0) do { \
    _Pragma("unroll") \
    for (int t = 0; t < 2; t++) { \
        int idx = tid + 256*t; int row = idx >> 3; int cb = (idx & 7) * 8; \
        cp16(smb + (stg) + (aoff) + (u32)((row*ASTR + cb)*2), \
             (ptr) + (size_t)((k0) + row)*DH + cb); \
    } } while(0)
#define ISSUE_CHUNK(k0, stg) do { \
    ISSUE_ARR(Kp, 0,    stg, k0); \
    ISSUE_ARR(Vp, 9216, stg, k0); \
    } while(0)

    float O[8][4];
    #pragma unroll
    for (int j = 0; j < 8; j++)
        #pragma unroll
        for (int e = 0; e < 4; e++) O[j][e] = 0.f;
    float dn0 = 0.f, dn1 = 0.f;
    const float qf0 = (float)(qb*128 + wid*16 + (lane >> 2));
    const float qf1 = qf0 + 8.f;

    ISSUE_CHUNK(0, 0u);       CP_COMMIT();
    ISSUE_CHUNK(64, ASTAGE);  CP_COMMIT();

    for (int c = 0; c < NCH; c++) {
        const int k0 = c * 64;
        if (c + 2 < NCH) CP_WAIT(1); else CP_WAIT(0);
        __syncthreads();
        const u32 stg = (u32)(c % 3) * ASTAGE;
        if (c + 2 < NCH) { ISSUE_CHUNK(k0 + 128, (u32)((c + 2) % 3) * ASTAGE); CP_COMMIT(); }

        // ---- S = Q K^T (single fp16 pass) ----
        float S[8][4];
        #pragma unroll
        for (int j = 0; j < 8; j++)
            #pragma unroll
            for (int e = 0; e < 4; e++) S[j][e] = 0.f;
        #pragma unroll
        for (int kk = 0; kk < 4; kk++) {
            const u32 koff = stg + (((lane & 7) + ((lane & 16) >> 1))*ASTR + kk*16 + (lane & 8)) * 2;
            u32 kh4[4][4];
            #pragma unroll
            for (int jp = 0; jp < 4; jp++) ldsm4(kh4[jp], smb + koff + jp*16*ASTR*2);
            #pragma unroll
            for (int jp = 0; jp < 4; jp++) {
                mma_fp16(S[2*jp],   qh[kk], kh4[jp]);
                mma_fp16(S[2*jp+1], qh[kk], kh4[jp]+2);
            }
        }

        // ---- softmax + pack P fp16 ----
        u32 aPh[4][4];
        #pragma unroll
        for (int j = 0; j < 8; j++) {
            int kc = k0 + j*8 + 2*(lane & 3);
            float kf = (float)kc;
            float m0 = mk[kc], m1 = mk[kc + 1];
            float p0 = __expf(S[j][0]*ATTN_SCALE - slope*fabsf(qf0 - kf)       + m0);
            float p1 = __expf(S[j][1]*ATTN_SCALE - slope*fabsf(qf0 - kf - 1.f) + m1);
            float p2 = __expf(S[j][2]*ATTN_SCALE - slope*fabsf(qf1 - kf)       + m0);
            float p3 = __expf(S[j][3]*ATTN_SCALE - slope*fabsf(qf1 - kf - 1.f) + m1);
            dn0 += p0 + p1;
            dn1 += p2 + p3;
            int t = j >> 1, o = (j & 1) * 2;
            aPh[t][o]   = pack_h2(p0, p1);
            aPh[t][o+1] = pack_h2(p2, p3);
        }

        // ---- O += P V (single fp16 pass) ----
        #pragma unroll
        for (int t = 0; t < 4; t++) {
            const u32 voff = stg + 9216 + ((t*16 + (lane & 15))*ASTR + (lane >> 4)*8) * 2;
            u32 vh4[4][4];
            #pragma unroll
            for (int jp = 0; jp < 4; jp++) ldsm4t(vh4[jp], smb + voff + jp*16*2);
            #pragma unroll
            for (int jp = 0; jp < 4; jp++) {
                mma_fp16(O[2*jp],   aPh[t], vh4[jp]);
                mma_fp16(O[2*jp+1], aPh[t], vh4[jp]+2);
            }
        }
    }
#undef ISSUE_ARR
#undef ISSUE_CHUNK

    #pragma unroll
    for (int m_ = 1; m_ < 4; m_ <<= 1) {
        dn0 += __shfl_xor_sync(0xffffffffu, dn0, m_);
        dn1 += __shfl_xor_sync(0xffffffffu, dn1, m_);
    }
    const float inv0 = 1.f / dn0, inv1 = 1.f / dn1;

    // ctx written as fp16 for the 1-pass output projection
    const int q0 = qb*128 + wid*16 + (lane >> 2);
    const int q1 = q0 + 8;
    #pragma unroll
    for (int j = 0; j < 8; j++) {
        int d = h*64 + j*8 + 2*(lane & 3);
        size_t b0 = ((size_t)b*NS + q0)*ND + d;
        *(u32*)&g_cf[b0] = pack_h2(O[j][0]*inv0, O[j][1]*inv0);
        size_t b1 = ((size_t)b*NS + q1)*ND + d;
        *(u32*)&g_cf[b1] = pack_h2(O[j][2]*inv1, O[j][3]*inv1);
    }
}

// ---------------- launch -----------------------------------------------------
extern "C" void kernel_launch(void* const* d_in, const int* in_sizes, int n_in,
                              void* d_out, int out_size)
{
    const float* x     = (const float*)d_in[0];
    const void*  mask  = d_in[1];
    const float* Wqkv  = (const float*)d_in[2];
    const float* bqkv  = (const float*)d_in[3];
    const float* Wproj = (const float*)d_in[4];
    const float* bproj = (const float*)d_in[5];
    float* out = (float*)d_out;

    (void)in_sizes; (void)n_in; (void)out_size;

    static bool inited = false;
    static __half *p_xhh, *p_xhl, *p_wqf, *p_wpf, *p_cf;
    if (!inited) {
        cudaFuncSetAttribute(gemm_qkv, cudaFuncAttributeMaxDynamicSharedMemorySize, QSMEM);
        cudaFuncSetAttribute(gemm_out, cudaFuncAttributeMaxDynamicSharedMemorySize, FSMEM);
        cudaFuncSetAttribute(attn_mma, cudaFuncAttributeMaxDynamicSharedMemorySize, ASMEM);
        cudaGetSymbolAddress((void**)&p_xhh, g_xhh); cudaGetSymbolAddress((void**)&p_xhl, g_xhl);
        cudaGetSymbolAddress((void**)&p_wqf, g_wqf);
        cudaGetSymbolAddress((void**)&p_wpf, g_wpf); cudaGetSymbolAddress((void**)&p_cf, g_cf);
        inited = true;
    }

    detect_mask_kernel<<<1, 1024>>>((const unsigned int*)mask);

    split_h_kernel<<<(NM*ND/4 + 255)/256, 256>>>(x, p_xhh, p_xhl, NM*ND/4);
    cvt_f16_kernel<<<(NQKV*ND/4 + 255)/256, 256>>>(Wqkv, p_wqf, NQKV*ND/4);
    cvt_f16_kernel<<<(ND*ND/4 + 255)/256, 256>>>(Wproj, p_wpf, ND*ND/4);

    gemm_qkv<<<dim3(NQKV/128, NM/128), 256, QSMEM>>>(
        p_xhh, p_xhl, p_wqf, bqkv);

    attn_mma<<<dim3(NS/128, NH, NB), 256, ASMEM>>>(mask);

    gemm_out<<<dim3(ND/128, NM/128), 256, FSMEM>>>(
        p_cf, p_wpf, bproj, out);
}

// round 12
// speedup vs baseline: 8.5487x; 1.2567x over previous
#include <cuda_runtime.h>
#include <cuda_fp16.h>

// Problem constants
#define NB 2
#define NS 2048
#define ND 1024
#define NH 16
#define DH 64
#define NM (NB*NS)        // 4096
#define NQKV (3*ND)       // 3072
#define ATTN_SCALE 0.03125f

typedef unsigned long long u64;
typedef unsigned int u32;

// ---------------- scratch (device globals) -----------------------------------
__device__ int g_mask_mode;
__device__ __half g_xf[(size_t)NM*ND];       // x fp16
__device__ __half g_wqf[(size_t)NQKV*ND];    // Wqkv fp16
__device__ __half g_wpf[(size_t)ND*ND];      // Wproj fp16
__device__ __half g_cf[(size_t)NM*ND];       // ctx fp16
#define QKV_ELEMS (NB*NH*NS*DH)
__device__ __half g_Qf[QKV_ELEMS], g_Kf[QKV_ELEMS], g_Vf[QKV_ELEMS];

// ---------------- PTX helpers ------------------------------------------------
__device__ __forceinline__ u32 smem_u32(const void* p){
    u32 a; asm("{ .reg .u64 t; cvta.to.shared.u64 t, %1; cvt.u32.u64 %0, t; }" : "=r"(a) : "l"(p));
    return a;
}
__device__ __forceinline__ void ldsm4(u32* r, u32 addr){
    asm volatile("ldmatrix.sync.aligned.m8n8.x4.shared.b16 {%0,%1,%2,%3}, [%4];"
        : "=r"(r[0]),"=r"(r[1]),"=r"(r[2]),"=r"(r[3]) : "r"(addr));
}
__device__ __forceinline__ void ldsm4t(u32* r, u32 addr){
    asm volatile("ldmatrix.sync.aligned.m8n8.x4.trans.shared.b16 {%0,%1,%2,%3}, [%4];"
        : "=r"(r[0]),"=r"(r[1]),"=r"(r[2]),"=r"(r[3]) : "r"(addr));
}
__device__ __forceinline__ void mma_fp16(float* c, const u32* a, const u32* b){
    asm volatile("mma.sync.aligned.m16n8k16.row.col.f32.f16.f16.f32 "
        "{%0,%1,%2,%3}, {%4,%5,%6,%7}, {%8,%9}, {%0,%1,%2,%3};"
        : "+f"(c[0]),"+f"(c[1]),"+f"(c[2]),"+f"(c[3])
        : "r"(a[0]),"r"(a[1]),"r"(a[2]),"r"(a[3]), "r"(b[0]),"r"(b[1]));
}
__device__ __forceinline__ u32 pack_h2(float a, float b){
    __half2 H; H.x = __float2half_rn(a); H.y = __float2half_rn(b);
    return *(u32*)&H;
}
__device__ __forceinline__ void cp16(u32 dst, const void* src){
    asm volatile("cp.async.cg.shared.global [%0], [%1], 16;" :: "r"(dst), "l"(src));
}
#define CP_COMMIT() asm volatile("cp.async.commit_group;" ::: "memory")
#define CP_WAIT(n)  asm volatile("cp.async.wait_group %0;" :: "n"(n) : "memory")

// ---------------- mask dtype detector ----------------------------------------
__global__ void detect_mask_kernel(const unsigned int* __restrict__ w){
    __shared__ int not_f, not_i;
    int t = threadIdx.x;
    if (t == 0){ not_f = 0; not_i = 0; }
    __syncthreads();
    unsigned v = w[t];
    if (v != 0u && v != 0x3F800000u) atomicExch(&not_f, 1);
    if (v > 1u)                      atomicExch(&not_i, 1);
    __syncthreads();
    if (t == 0) g_mask_mode = (not_f == 0) ? 2 : ((not_i == 0) ? 1 : 0);
}

// ---------------- fp32 -> fp16 convert ---------------------------------------
__global__ void __launch_bounds__(256) cvt_f16_kernel(
    const float* __restrict__ src, __half* __restrict__ dst, int n4)
{
    int i = blockIdx.x * 256 + threadIdx.x;
    if (i >= n4) return;
    float4 v = ((const float4*)src)[i];
    ((uint2*)dst)[i] = make_uint2(pack_h2(v.x, v.y), pack_h2(v.z, v.w));
}

// ---------------- fp16 1-pass NT GEMM, 3-stage cp.async ----------------------
// C[M,N] = A[M,K] * B[N,K]^T + bias. Block 128x128, 8 warps (2m x 4n), BK=32.
// QKV_EPI=1: scatter into g_Qf/g_Kf/g_Vf fp16. QKV_EPI=0: fp32 out.
#define GSTRIDE 40
#define GMAT (128*GSTRIDE*2)   // 10240
#define GNCH (ND/32)           // 32
#define FSTAGE (2*GMAT)        // 20480
#define FSMEM  (3*FSTAGE)      // 61440

template<int QKV_EPI>
__global__ void __launch_bounds__(256) gemm_f16(
    const __half* __restrict__ A, const __half* __restrict__ B,
    const float* __restrict__ bias, float* __restrict__ Cout)
{
    extern __shared__ __align__(16) char sm[];
    const u32 smb = smem_u32(sm);
    const int tid = threadIdx.x, lane = tid & 31, wid = tid >> 5;
    const int wm = wid >> 2, wn = wid & 3;

    const __half* AP = A + (size_t)blockIdx.y * 128 * ND;
    const __half* BP = B + (size_t)blockIdx.x * 128 * ND;

    float C[4][4][4];
    #pragma unroll
    for (int i = 0; i < 4; i++)
        #pragma unroll
        for (int j = 0; j < 4; j++)
            #pragma unroll
            for (int e = 0; e < 4; e++) C[i][j][e] = 0.f;

#define F_ISSUE(k0, st) do { \
    _Pragma("unroll") \
    for (int t = 0; t < 2; t++) { \
        int u_ = tid + 256*t; int row = u_ >> 2; int cb = (u_ & 3) * 8; \
        size_t go = (size_t)row * ND + (k0) + cb; \
        u32 so = (st) + (u32)((row*GSTRIDE + cb)*2); \
        cp16(smb + so + 0*GMAT, AP + go); cp16(smb + so + 1*GMAT, BP + go); \
    } } while(0)

    F_ISSUE(0, 0u);        CP_COMMIT();
    F_ISSUE(32, FSTAGE);   CP_COMMIT();

    for (int c = 0; c < GNCH; c++) {
        if (c + 2 < GNCH) CP_WAIT(1); else CP_WAIT(0);
        __syncthreads();
        const u32 st = (u32)(c % 3) * FSTAGE;
        if (c + 2 < GNCH) { F_ISSUE((c + 2)*32, (u32)((c + 2) % 3) * FSTAGE); CP_COMMIT(); }

        #pragma unroll
        for (int kk = 0; kk < 2; kk++) {
            const u32 aoff = ((wm*64 + (lane & 15))*GSTRIDE + kk*16 + (lane >> 4)*8) * 2;
            const u32 boff = ((wn*32 + (lane & 7) + ((lane & 16) >> 1))*GSTRIDE + kk*16 + (lane & 8)) * 2;

            u32 ah[4][4], bh_[4][2];
            #pragma unroll
            for (int i = 0; i < 4; i++) ldsm4(ah[i], smb + st + 0*GMAT + aoff + i*16*GSTRIDE*2);
            #pragma unroll
            for (int jp = 0; jp < 2; jp++) {
                u32 t4[4];
                ldsm4(t4, smb + st + 1*GMAT + boff + jp*16*GSTRIDE*2);
                bh_[2*jp][0]=t4[0]; bh_[2*jp][1]=t4[1]; bh_[2*jp+1][0]=t4[2]; bh_[2*jp+1][1]=t4[3];
            }
            #pragma unroll
            for (int i = 0; i < 4; i++)
                #pragma unroll
                for (int j = 0; j < 4; j++) mma_fp16(C[i][j], ah[i], bh_[j]);
        }
    }
#undef F_ISSUE

    const int mb = blockIdx.y*128 + wm*64;
    const int nb = blockIdx.x*128 + wn*32;
    #pragma unroll
    for (int i = 0; i < 4; i++) {
        #pragma unroll
        for (int j = 0; j < 4; j++) {
            int n = nb + j*8 + 2*(lane & 3);
            float2 bz = *(const float2*)(bias + n);
            int m0 = mb + i*16 + (lane >> 2);
            int m1 = m0 + 8;
            if (QKV_EPI) {
                // qkv col n -> head n/192, part (n%192)/64, d = n%64; fp16
                int h = n / 192, rem = n - h*192, part = rem >> 6, d = rem & 63;
                __half* dst = (part==0) ? g_Qf : (part==1 ? g_Kf : g_Vf);
                {
                    int bb = m0 >> 11, ss = m0 & (NS-1);
                    size_t base = (((size_t)bb*NH + h)*NS + ss)*DH + d;
                    *(u32*)&dst[base] = pack_h2(C[i][j][0] + bz.x, C[i][j][1] + bz.y);
                }
                {
                    int bb = m1 >> 11, ss = m1 & (NS-1);
                    size_t base = (((size_t)bb*NH + h)*NS + ss)*DH + d;
                    *(u32*)&dst[base] = pack_h2(C[i][j][2] + bz.x, C[i][j][3] + bz.y);
                }
            } else {
                *(float2*)&Cout[(size_t)m0*ND + n] = make_float2(C[i][j][0] + bz.x, C[i][j][1] + bz.y);
                *(float2*)&Cout[(size_t)m1*ND + n] = make_float2(C[i][j][2] + bz.x, C[i][j][3] + bz.y);
            }
        }
    }
}

// ---------------- attention: fp16, QK 1-pass, PV 1-pass ----------------------
// Block = (b, h, 128-q tile), 8 warps. 64-key chunks, 3-stage cp.async.
#define ASTR 72
#define ASTAGE 18432
#define AMSK  (3*ASTAGE)           // 55296
#define ASMEM (AMSK + NS*4)        // 63488
#define NCH (NS/64)                // 32

__global__ void __launch_bounds__(256) attn_mma(const void* __restrict__ maskp)
{
    extern __shared__ __align__(16) char sm[];
    const u32 smb = smem_u32(sm);
    float* mk = (float*)(sm + AMSK);
    const int tid = threadIdx.x, lane = tid & 31, wid = tid >> 5;
    const int qb = blockIdx.x, h = blockIdx.y, b = blockIdx.z;

    const size_t hb = ((size_t)(b*NH + h)) * NS * DH;
    const __half* Qp = g_Qf + hb + (size_t)qb*128*DH;
    const __half* Kp = g_Kf + hb;
    const __half* Vp = g_Vf + hb;

    const float slope = exp2f(-0.5f * (float)(h + 1));
    const int mode = g_mask_mode;

    // stage Q (128 rows x 64 halves) through stage 0; mask -> mk
    #pragma unroll
    for (int t = 0; t < 4; t++) {
        int idx = tid + 256*t; int row = idx >> 3; int cb = (idx & 7) * 8;
        *(uint4*)(sm + (u32)((row*ASTR + cb)*2)) = *(const uint4*)(Qp + row*DH + cb);
    }
    for (int i = tid; i < NS; i += 256) {
        bool mv;
        if      (mode == 0) mv = ((const unsigned char*)maskp)[b*NS + i] != 0;
        else if (mode == 1) mv = ((const int*)maskp)[b*NS + i] != 0;
        else                mv = ((const float*)maskp)[b*NS + i] != 0.f;
        mk[i] = mv ? 0.f : -1e30f;
    }
    __syncthreads();

    u32 qh[4][4];
    #pragma unroll
    for (int kk = 0; kk < 4; kk++) {
        u32 off = ((wid*16 + (lane & 15))*ASTR + kk*16 + (lane >> 4)*8) * 2;
        ldsm4(qh[kk], smb + off);
    }
    __syncthreads();   // Q staging consumed; stage 0 reusable

#define ISSUE_ARR(ptr, aoff, stg, k0) do { \
    _Pragma("unroll") \
    for (int t = 0; t < 2; t++) { \
        int idx = tid + 256*t; int row = idx >> 3; int cb = (idx & 7) * 8; \
        cp16(smb + (stg) + (aoff) + (u32)((row*ASTR + cb)*2), \
             (ptr) + (size_t)((k0) + row)*DH + cb); \
    } } while(0)
#define ISSUE_CHUNK(k0, stg) do { \
    ISSUE_ARR(Kp, 0,    stg, k0); \
    ISSUE_ARR(Vp, 9216, stg, k0); \
    } while(0)

    float O[8][4];
    #pragma unroll
    for (int j = 0; j < 8; j++)
        #pragma unroll
        for (int e = 0; e < 4; e++) O[j][e] = 0.f;
    float dn0 = 0.f, dn1 = 0.f;
    const float qf0 = (float)(qb*128 + wid*16 + (lane >> 2));
    const float qf1 = qf0 + 8.f;

    ISSUE_CHUNK(0, 0u);       CP_COMMIT();
    ISSUE_CHUNK(64, ASTAGE);  CP_COMMIT();

    for (int c = 0; c < NCH; c++) {
        const int k0 = c * 64;
        if (c + 2 < NCH) CP_WAIT(1); else CP_WAIT(0);
        __syncthreads();
        const u32 stg = (u32)(c % 3) * ASTAGE;
        if (c + 2 < NCH) { ISSUE_CHUNK(k0 + 128, (u32)((c + 2) % 3) * ASTAGE); CP_COMMIT(); }

        // ---- S = Q K^T (single fp16 pass) ----
        float S[8][4];
        #pragma unroll
        for (int j = 0; j < 8; j++)
            #pragma unroll
            for (int e = 0; e < 4; e++) S[j][e] = 0.f;
        #pragma unroll
        for (int kk = 0; kk < 4; kk++) {
            const u32 koff = stg + (((lane & 7) + ((lane & 16) >> 1))*ASTR + kk*16 + (lane & 8)) * 2;
            u32 kh4[4][4];
            #pragma unroll
            for (int jp = 0; jp < 4; jp++) ldsm4(kh4[jp], smb + koff + jp*16*ASTR*2);
            #pragma unroll
            for (int jp = 0; jp < 4; jp++) {
                mma_fp16(S[2*jp],   qh[kk], kh4[jp]);
                mma_fp16(S[2*jp+1], qh[kk], kh4[jp]+2);
            }
        }

        // ---- softmax + pack P fp16 ----
        u32 aPh[4][4];
        #pragma unroll
        for (int j = 0; j < 8; j++) {
            int kc = k0 + j*8 + 2*(lane & 3);
            float kf = (float)kc;
            float m0 = mk[kc], m1 = mk[kc + 1];
            float p0 = __expf(S[j][0]*ATTN_SCALE - slope*fabsf(qf0 - kf)       + m0);
            float p1 = __expf(S[j][1]*ATTN_SCALE - slope*fabsf(qf0 - kf - 1.f) + m1);
            float p2 = __expf(S[j][2]*ATTN_SCALE - slope*fabsf(qf1 - kf)       + m0);
            float p3 = __expf(S[j][3]*ATTN_SCALE - slope*fabsf(qf1 - kf - 1.f) + m1);
            dn0 += p0 + p1;
            dn1 += p2 + p3;
            int t = j >> 1, o = (j & 1) * 2;
            aPh[t][o]   = pack_h2(p0, p1);
            aPh[t][o+1] = pack_h2(p2, p3);
        }

        // ---- O += P V (single fp16 pass) ----
        #pragma unroll
        for (int t = 0; t < 4; t++) {
            const u32 voff = stg + 9216 + ((t*16 + (lane & 15))*ASTR + (lane >> 4)*8) * 2;
            u32 vh4[4][4];
            #pragma unroll
            for (int jp = 0; jp < 4; jp++) ldsm4t(vh4[jp], smb + voff + jp*16*2);
            #pragma unroll
            for (int jp = 0; jp < 4; jp++) {
                mma_fp16(O[2*jp],   aPh[t], vh4[jp]);
                mma_fp16(O[2*jp+1], aPh[t], vh4[jp]+2);
            }
        }
    }
#undef ISSUE_ARR
#undef ISSUE_CHUNK

    #pragma unroll
    for (int m_ = 1; m_ < 4; m_ <<= 1) {
        dn0 += __shfl_xor_sync(0xffffffffu, dn0, m_);
        dn1 += __shfl_xor_sync(0xffffffffu, dn1, m_);
    }
    const float inv0 = 1.f / dn0, inv1 = 1.f / dn1;

    // ctx written as fp16 for the 1-pass output projection
    const int q0 = qb*128 + wid*16 + (lane >> 2);
    const int q1 = q0 + 8;
    #pragma unroll
    for (int j = 0; j < 8; j++) {
        int d = h*64 + j*8 + 2*(lane & 3);
        size_t b0 = ((size_t)b*NS + q0)*ND + d;
        *(u32*)&g_cf[b0] = pack_h2(O[j][0]*inv0, O[j][1]*inv0);
        size_t b1 = ((size_t)b*NS + q1)*ND + d;
        *(u32*)&g_cf[b1] = pack_h2(O[j][2]*inv1, O[j][3]*inv1);
    }
}

// ---------------- launch -----------------------------------------------------
extern "C" void kernel_launch(void* const* d_in, const int* in_sizes, int n_in,
                              void* d_out, int out_size)
{
    const float* x     = (const float*)d_in[0];
    const void*  mask  = d_in[1];
    const float* Wqkv  = (const float*)d_in[2];
    const float* bqkv  = (const float*)d_in[3];
    const float* Wproj = (const float*)d_in[4];
    const float* bproj = (const float*)d_in[5];
    float* out = (float*)d_out;

    (void)in_sizes; (void)n_in; (void)out_size;

    static bool inited = false;
    static __half *p_xf, *p_wqf, *p_wpf, *p_cf;
    if (!inited) {
        cudaFuncSetAttribute(gemm_f16<1>, cudaFuncAttributeMaxDynamicSharedMemorySize, FSMEM);
        cudaFuncSetAttribute(gemm_f16<0>, cudaFuncAttributeMaxDynamicSharedMemorySize, FSMEM);
        cudaFuncSetAttribute(attn_mma,    cudaFuncAttributeMaxDynamicSharedMemorySize, ASMEM);
        cudaGetSymbolAddress((void**)&p_xf, g_xf);
        cudaGetSymbolAddress((void**)&p_wqf, g_wqf);
        cudaGetSymbolAddress((void**)&p_wpf, g_wpf);
        cudaGetSymbolAddress((void**)&p_cf, g_cf);
        inited = true;
    }

    detect_mask_kernel<<<1, 1024>>>((const unsigned int*)mask);

    cvt_f16_kernel<<<(NM*ND/4 + 255)/256, 256>>>(x, p_xf, NM*ND/4);
    cvt_f16_kernel<<<(NQKV*ND/4 + 255)/256, 256>>>(Wqkv, p_wqf, NQKV*ND/4);
    cvt_f16_kernel<<<(ND*ND/4 + 255)/256, 256>>>(Wproj, p_wpf, ND*ND/4);

    gemm_f16<1><<<dim3(NQKV/128, NM/128), 256, FSMEM>>>(
        p_xf, p_wqf, bqkv, nullptr);

    attn_mma<<<dim3(NS/128, NH, NB), 256, ASMEM>>>(mask);

    gemm_f16<0><<<dim3(ND/128, NM/128), 256, FSMEM>>>(
        p_cf, p_wpf, bproj, out);
}

// round 13
// speedup vs baseline: 9.9946x; 1.1691x over previous
#include <cuda_runtime.h>
#include <cuda_fp16.h>

// Problem constants
#define NB 2
#define NS 2048
#define ND 1024
#define NH 16
#define DH 64
#define NM (NB*NS)        // 4096
#define NQKV (3*ND)       // 3072
#define ATTN_SCALE 0.03125f

typedef unsigned long long u64;
typedef unsigned int u32;

// ---------------- scratch (device globals) -----------------------------------
__device__ int g_mask_mode;
__device__ __half g_xf[(size_t)NM*ND];       // x fp16
__device__ __half g_wqf[(size_t)NQKV*ND];    // Wqkv fp16
__device__ __half g_wpf[(size_t)ND*ND];      // Wproj fp16
__device__ __half g_cf[(size_t)NM*ND];       // ctx fp16
#define QKV_ELEMS (NB*NH*NS*DH)
__device__ __half g_Qf[QKV_ELEMS], g_Kf[QKV_ELEMS], g_Vf[QKV_ELEMS];

// ---------------- PTX helpers ------------------------------------------------
__device__ __forceinline__ u32 smem_u32(const void* p){
    u32 a; asm("{ .reg .u64 t; cvta.to.shared.u64 t, %1; cvt.u32.u64 %0, t; }" : "=r"(a) : "l"(p));
    return a;
}
__device__ __forceinline__ void ldsm4(u32* r, u32 addr){
    asm volatile("ldmatrix.sync.aligned.m8n8.x4.shared.b16 {%0,%1,%2,%3}, [%4];"
        : "=r"(r[0]),"=r"(r[1]),"=r"(r[2]),"=r"(r[3]) : "r"(addr));
}
__device__ __forceinline__ void ldsm4t(u32* r, u32 addr){
    asm volatile("ldmatrix.sync.aligned.m8n8.x4.trans.shared.b16 {%0,%1,%2,%3}, [%4];"
        : "=r"(r[0]),"=r"(r[1]),"=r"(r[2]),"=r"(r[3]) : "r"(addr));
}
__device__ __forceinline__ void mma_fp16(float* c, const u32* a, const u32* b){
    asm volatile("mma.sync.aligned.m16n8k16.row.col.f32.f16.f16.f32 "
        "{%0,%1,%2,%3}, {%4,%5,%6,%7}, {%8,%9}, {%0,%1,%2,%3};"
        : "+f"(c[0]),"+f"(c[1]),"+f"(c[2]),"+f"(c[3])
        : "r"(a[0]),"r"(a[1]),"r"(a[2]),"r"(a[3]), "r"(b[0]),"r"(b[1]));
}
__device__ __forceinline__ u32 pack_h2(float a, float b){
    __half2 H; H.x = __float2half_rn(a); H.y = __float2half_rn(b);
    return *(u32*)&H;
}
__device__ __forceinline__ void cp16(u32 dst, const void* src){
    asm volatile("cp.async.cg.shared.global [%0], [%1], 16;" :: "r"(dst), "l"(src));
}
#define CP_COMMIT() asm volatile("cp.async.commit_group;" ::: "memory")
#define CP_WAIT(n)  asm volatile("cp.async.wait_group %0;" :: "n"(n) : "memory")

// ---------------- mask dtype detector ----------------------------------------
__global__ void detect_mask_kernel(const unsigned int* __restrict__ w){
    __shared__ int not_f, not_i;
    int t = threadIdx.x;
    if (t == 0){ not_f = 0; not_i = 0; }
    __syncthreads();
    unsigned v = w[t];
    if (v != 0u && v != 0x3F800000u) atomicExch(&not_f, 1);
    if (v > 1u)                      atomicExch(&not_i, 1);
    __syncthreads();
    if (t == 0) g_mask_mode = (not_f == 0) ? 2 : ((not_i == 0) ? 1 : 0);
}

// ---------------- fp32 -> fp16 convert ---------------------------------------
__global__ void __launch_bounds__(256) cvt_f16_kernel(
    const float* __restrict__ src, __half* __restrict__ dst, int n4)
{
    int i = blockIdx.x * 256 + threadIdx.x;
    if (i >= n4) return;
    float4 v = ((const float4*)src)[i];
    ((uint2*)dst)[i] = make_uint2(pack_h2(v.x, v.y), pack_h2(v.z, v.w));
}

// ---------------- fp16 1-pass NT GEMM, 3-stage cp.async ----------------------
#define GSTRIDE 40
#define GMAT (128*GSTRIDE*2)   // 10240
#define GNCH (ND/32)           // 32
#define FSTAGE (2*GMAT)        // 20480
#define FSMEM  (3*FSTAGE)      // 61440

template<int QKV_EPI>
__global__ void __launch_bounds__(256) gemm_f16(
    const __half* __restrict__ A, const __half* __restrict__ B,
    const float* __restrict__ bias, float* __restrict__ Cout)
{
    extern __shared__ __align__(16) char sm[];
    const u32 smb = smem_u32(sm);
    const int tid = threadIdx.x, lane = tid & 31, wid = tid >> 5;
    const int wm = wid >> 2, wn = wid & 3;

    const __half* AP = A + (size_t)blockIdx.y * 128 * ND;
    const __half* BP = B + (size_t)blockIdx.x * 128 * ND;

    float C[4][4][4];
    #pragma unroll
    for (int i = 0; i < 4; i++)
        #pragma unroll
        for (int j = 0; j < 4; j++)
            #pragma unroll
            for (int e = 0; e < 4; e++) C[i][j][e] = 0.f;

#define F_ISSUE(k0, st) do { \
    _Pragma("unroll") \
    for (int t = 0; t < 2; t++) { \
        int u_ = tid + 256*t; int row = u_ >> 2; int cb = (u_ & 3) * 8; \
        size_t go = (size_t)row * ND + (k0) + cb; \
        u32 so = (st) + (u32)((row*GSTRIDE + cb)*2); \
        cp16(smb + so + 0*GMAT, AP + go); cp16(smb + so + 1*GMAT, BP + go); \
    } } while(0)

    F_ISSUE(0, 0u);        CP_COMMIT();
    F_ISSUE(32, FSTAGE);   CP_COMMIT();

    for (int c = 0; c < GNCH; c++) {
        if (c + 2 < GNCH) CP_WAIT(1); else CP_WAIT(0);
        __syncthreads();
        const u32 st = (u32)(c % 3) * FSTAGE;
        if (c + 2 < GNCH) { F_ISSUE((c + 2)*32, (u32)((c + 2) % 3) * FSTAGE); CP_COMMIT(); }

        #pragma unroll
        for (int kk = 0; kk < 2; kk++) {
            const u32 aoff = ((wm*64 + (lane & 15))*GSTRIDE + kk*16 + (lane >> 4)*8) * 2;
            const u32 boff = ((wn*32 + (lane & 7) + ((lane & 16) >> 1))*GSTRIDE + kk*16 + (lane & 8)) * 2;

            u32 ah[4][4], bh_[4][2];
            #pragma unroll
            for (int i = 0; i < 4; i++) ldsm4(ah[i], smb + st + 0*GMAT + aoff + i*16*GSTRIDE*2);
            #pragma unroll
            for (int jp = 0; jp < 2; jp++) {
                u32 t4[4];
                ldsm4(t4, smb + st + 1*GMAT + boff + jp*16*GSTRIDE*2);
                bh_[2*jp][0]=t4[0]; bh_[2*jp][1]=t4[1]; bh_[2*jp+1][0]=t4[2]; bh_[2*jp+1][1]=t4[3];
            }
            #pragma unroll
            for (int i = 0; i < 4; i++)
                #pragma unroll
                for (int j = 0; j < 4; j++) mma_fp16(C[i][j], ah[i], bh_[j]);
        }
    }
#undef F_ISSUE

    const int mb = blockIdx.y*128 + wm*64;
    const int nb = blockIdx.x*128 + wn*32;
    #pragma unroll
    for (int i = 0; i < 4; i++) {
        #pragma unroll
        for (int j = 0; j < 4; j++) {
            int n = nb + j*8 + 2*(lane & 3);
            float2 bz = *(const float2*)(bias + n);
            int m0 = mb + i*16 + (lane >> 2);
            int m1 = m0 + 8;
            if (QKV_EPI) {
                int h = n / 192, rem = n - h*192, part = rem >> 6, d = rem & 63;
                __half* dst = (part==0) ? g_Qf : (part==1 ? g_Kf : g_Vf);
                {
                    int bb = m0 >> 11, ss = m0 & (NS-1);
                    size_t base = (((size_t)bb*NH + h)*NS + ss)*DH + d;
                    *(u32*)&dst[base] = pack_h2(C[i][j][0] + bz.x, C[i][j][1] + bz.y);
                }
                {
                    int bb = m1 >> 11, ss = m1 & (NS-1);
                    size_t base = (((size_t)bb*NH + h)*NS + ss)*DH + d;
                    *(u32*)&dst[base] = pack_h2(C[i][j][2] + bz.x, C[i][j][3] + bz.y);
                }
            } else {
                *(float2*)&Cout[(size_t)m0*ND + n] = make_float2(C[i][j][0] + bz.x, C[i][j][1] + bz.y);
                *(float2*)&Cout[(size_t)m1*ND + n] = make_float2(C[i][j][2] + bz.x, C[i][j][3] + bz.y);
            }
        }
    }
}

// ---------------- attention: fp16, ALiBi-banded chunk window -----------------
// Block = (b, h, 128-q tile), 8 warps. 64-key chunks, 3-stage cp.async.
// Chunks with slope*(distance) > 20 are skipped: softmax weight < 3e-9 there,
// total perturbation < 6e-6 relative (denominator always holds near-diagonal
// terms of weight ~1). Window W_h = 20/slope_h = 20*2^((h+1)/2).
#define ASTR 72
#define ASTAGE 18432
#define AMSK  (3*ASTAGE)           // 55296
#define ASMEM (AMSK + NS*4)        // 63488
#define NCH (NS/64)                // 32

__global__ void __launch_bounds__(256) attn_mma(const void* __restrict__ maskp)
{
    extern __shared__ __align__(16) char sm[];
    const u32 smb = smem_u32(sm);
    float* mk = (float*)(sm + AMSK);
    const int tid = threadIdx.x, lane = tid & 31, wid = tid >> 5;
    const int qb = blockIdx.x, h = blockIdx.y, b = blockIdx.z;

    const size_t hb = ((size_t)(b*NH + h)) * NS * DH;
    const __half* Qp = g_Qf + hb + (size_t)qb*128*DH;
    const __half* Kp = g_Kf + hb;
    const __half* Vp = g_Vf + hb;

    const float slope = exp2f(-0.5f * (float)(h + 1));
    const int mode = g_mask_mode;

    // ALiBi band: chunk range [clo, chi] for this (h, q-tile)
    const int W = (int)(20.f * exp2f(0.5f * (float)(h + 1)));
    const int lo = qb*128 - W, hi = qb*128 + 127 + W;
    int clo = lo < 0 ? 0 : (lo >> 6);
    int chi = hi >> 6; if (chi > NCH - 1) chi = NCH - 1;

    // stage Q (128 rows x 64 halves) through stage 0; mask -> mk
    #pragma unroll
    for (int t = 0; t < 4; t++) {
        int idx = tid + 256*t; int row = idx >> 3; int cb = (idx & 7) * 8;
        *(uint4*)(sm + (u32)((row*ASTR + cb)*2)) = *(const uint4*)(Qp + row*DH + cb);
    }
    for (int i = tid; i < NS; i += 256) {
        bool mv;
        if      (mode == 0) mv = ((const unsigned char*)maskp)[b*NS + i] != 0;
        else if (mode == 1) mv = ((const int*)maskp)[b*NS + i] != 0;
        else                mv = ((const float*)maskp)[b*NS + i] != 0.f;
        mk[i] = mv ? 0.f : -1e30f;
    }
    __syncthreads();

    u32 qh[4][4];
    #pragma unroll
    for (int kk = 0; kk < 4; kk++) {
        u32 off = ((wid*16 + (lane & 15))*ASTR + kk*16 + (lane >> 4)*8) * 2;
        ldsm4(qh[kk], smb + off);
    }
    __syncthreads();   // Q staging consumed; all stages reusable

#define ISSUE_ARR(ptr, aoff, stg, k0) do { \
    _Pragma("unroll") \
    for (int t = 0; t < 2; t++) { \
        int idx = tid + 256*t; int row = idx >> 3; int cb = (idx & 7) * 8; \
        cp16(smb + (stg) + (aoff) + (u32)((row*ASTR + cb)*2), \
             (ptr) + (size_t)((k0) + row)*DH + cb); \
    } } while(0)
#define ISSUE_CHUNK(k0, stg) do { \
    ISSUE_ARR(Kp, 0,    stg, k0); \
    ISSUE_ARR(Vp, 9216, stg, k0); \
    } while(0)

    float O[8][4];
    #pragma unroll
    for (int j = 0; j < 8; j++)
        #pragma unroll
        for (int e = 0; e < 4; e++) O[j][e] = 0.f;
    float dn0 = 0.f, dn1 = 0.f;
    const float qf0 = (float)(qb*128 + wid*16 + (lane >> 2));
    const float qf1 = qf0 + 8.f;

    ISSUE_CHUNK(clo*64, (u32)(clo % 3) * ASTAGE);
    CP_COMMIT();
    if (clo + 1 <= chi) {
        ISSUE_CHUNK((clo + 1)*64, (u32)((clo + 1) % 3) * ASTAGE);
        CP_COMMIT();
    }

    for (int c = clo; c <= chi; c++) {
        const int k0 = c * 64;
        if (c + 2 <= chi) CP_WAIT(1); else CP_WAIT(0);
        __syncthreads();
        const u32 stg = (u32)(c % 3) * ASTAGE;
        if (c + 2 <= chi) { ISSUE_CHUNK(k0 + 128, (u32)((c + 2) % 3) * ASTAGE); CP_COMMIT(); }

        // ---- S = Q K^T (single fp16 pass) ----
        float S[8][4];
        #pragma unroll
        for (int j = 0; j < 8; j++)
            #pragma unroll
            for (int e = 0; e < 4; e++) S[j][e] = 0.f;
        #pragma unroll
        for (int kk = 0; kk < 4; kk++) {
            const u32 koff = stg + (((lane & 7) + ((lane & 16) >> 1))*ASTR + kk*16 + (lane & 8)) * 2;
            u32 kh4[4][4];
            #pragma unroll
            for (int jp = 0; jp < 4; jp++) ldsm4(kh4[jp], smb + koff + jp*16*ASTR*2);
            #pragma unroll
            for (int jp = 0; jp < 4; jp++) {
                mma_fp16(S[2*jp],   qh[kk], kh4[jp]);
                mma_fp16(S[2*jp+1], qh[kk], kh4[jp]+2);
            }
        }

        // ---- softmax + pack P fp16 ----
        u32 aPh[4][4];
        #pragma unroll
        for (int j = 0; j < 8; j++) {
            int kc = k0 + j*8 + 2*(lane & 3);
            float kf = (float)kc;
            float m0 = mk[kc], m1 = mk[kc + 1];
            float p0 = __expf(S[j][0]*ATTN_SCALE - slope*fabsf(qf0 - kf)       + m0);
            float p1 = __expf(S[j][1]*ATTN_SCALE - slope*fabsf(qf0 - kf - 1.f) + m1);
            float p2 = __expf(S[j][2]*ATTN_SCALE - slope*fabsf(qf1 - kf)       + m0);
            float p3 = __expf(S[j][3]*ATTN_SCALE - slope*fabsf(qf1 - kf - 1.f) + m1);
            dn0 += p0 + p1;
            dn1 += p2 + p3;
            int t = j >> 1, o = (j & 1) * 2;
            aPh[t][o]   = pack_h2(p0, p1);
            aPh[t][o+1] = pack_h2(p2, p3);
        }

        // ---- O += P V (single fp16 pass) ----
        #pragma unroll
        for (int t = 0; t < 4; t++) {
            const u32 voff = stg + 9216 + ((t*16 + (lane & 15))*ASTR + (lane >> 4)*8) * 2;
            u32 vh4[4][4];
            #pragma unroll
            for (int jp = 0; jp < 4; jp++) ldsm4t(vh4[jp], smb + voff + jp*16*2);
            #pragma unroll
            for (int jp = 0; jp < 4; jp++) {
                mma_fp16(O[2*jp],   aPh[t], vh4[jp]);
                mma_fp16(O[2*jp+1], aPh[t], vh4[jp]+2);
            }
        }
    }
#undef ISSUE_ARR
#undef ISSUE_CHUNK

    #pragma unroll
    for (int m_ = 1; m_ < 4; m_ <<= 1) {
        dn0 += __shfl_xor_sync(0xffffffffu, dn0, m_);
        dn1 += __shfl_xor_sync(0xffffffffu, dn1, m_);
    }
    const float inv0 = 1.f / dn0, inv1 = 1.f / dn1;

    // ctx written as fp16 for the 1-pass output projection
    const int q0 = qb*128 + wid*16 + (lane >> 2);
    const int q1 = q0 + 8;
    #pragma unroll
    for (int j = 0; j < 8; j++) {
        int d = h*64 + j*8 + 2*(lane & 3);
        size_t b0 = ((size_t)b*NS + q0)*ND + d;
        *(u32*)&g_cf[b0] = pack_h2(O[j][0]*inv0, O[j][1]*inv0);
        size_t b1 = ((size_t)b*NS + q1)*ND + d;
        *(u32*)&g_cf[b1] = pack_h2(O[j][2]*inv1, O[j][3]*inv1);
    }
}

// ---------------- launch -----------------------------------------------------
extern "C" void kernel_launch(void* const* d_in, const int* in_sizes, int n_in,
                              void* d_out, int out_size)
{
    const float* x     = (const float*)d_in[0];
    const void*  mask  = d_in[1];
    const float* Wqkv  = (const float*)d_in[2];
    const float* bqkv  = (const float*)d_in[3];
    const float* Wproj = (const float*)d_in[4];
    const float* bproj = (const float*)d_in[5];
    float* out = (float*)d_out;

    (void)in_sizes; (void)n_in; (void)out_size;

    static bool inited = false;
    static __half *p_xf, *p_wqf, *p_wpf, *p_cf;
    if (!inited) {
        cudaFuncSetAttribute(gemm_f16<1>, cudaFuncAttributeMaxDynamicSharedMemorySize, FSMEM);
        cudaFuncSetAttribute(gemm_f16<0>, cudaFuncAttributeMaxDynamicSharedMemorySize, FSMEM);
        cudaFuncSetAttribute(attn_mma,    cudaFuncAttributeMaxDynamicSharedMemorySize, ASMEM);
        cudaGetSymbolAddress((void**)&p_xf, g_xf);
        cudaGetSymbolAddress((void**)&p_wqf, g_wqf);
        cudaGetSymbolAddress((void**)&p_wpf, g_wpf);
        cudaGetSymbolAddress((void**)&p_cf, g_cf);
        inited = true;
    }

    detect_mask_kernel<<<1, 1024>>>((const unsigned int*)mask);

    cvt_f16_kernel<<<(NM*ND/4 + 255)/256, 256>>>(x, p_xf, NM*ND/4);
    cvt_f16_kernel<<<(NQKV*ND/4 + 255)/256, 256>>>(Wqkv, p_wqf, NQKV*ND/4);
    cvt_f16_kernel<<<(ND*ND/4 + 255)/256, 256>>>(Wproj, p_wpf, ND*ND/4);

    gemm_f16<1><<<dim3(NQKV/128, NM/128), 256, FSMEM>>>(
        p_xf, p_wqf, bqkv, nullptr);

    attn_mma<<<dim3(NS/128, NH, NB), 256, ASMEM>>>(mask);

    gemm_f16<0><<<dim3(ND/128, NM/128), 256, FSMEM>>>(
        p_cf, p_wpf, bproj, out);
}

// round 15
// speedup vs baseline: 10.7325x; 1.0738x over previous
#include <cuda_runtime.h>
#include <cuda_fp16.h>

// Problem constants
#define NB 2
#define NS 2048
#define ND 1024
#define NH 16
#define DH 64
#define NM (NB*NS)        // 4096
#define NQKV (3*ND)       // 3072
#define ATTN_SCALE 0.03125f

typedef unsigned long long u64;
typedef unsigned int u32;

// ---------------- scratch (device globals) -----------------------------------
__device__ int g_mask_mode;
__device__ __half g_xf[(size_t)NM*ND];       // x fp16
__device__ __half g_wqf[(size_t)NQKV*ND];    // Wqkv fp16
__device__ __half g_wpf[(size_t)ND*ND];      // Wproj fp16
__device__ __half g_cf[(size_t)NM*ND];       // ctx fp16
#define QKV_ELEMS (NB*NH*NS*DH)
__device__ __half g_Qf[QKV_ELEMS], g_Kf[QKV_ELEMS], g_Vf[QKV_ELEMS];

// ---------------- PTX helpers ------------------------------------------------
__device__ __forceinline__ u32 smem_u32(const void* p){
    u32 a; asm("{ .reg .u64 t; cvta.to.shared.u64 t, %1; cvt.u32.u64 %0, t; }" : "=r"(a) : "l"(p));
    return a;
}
__device__ __forceinline__ void ldsm4(u32* r, u32 addr){
    asm volatile("ldmatrix.sync.aligned.m8n8.x4.shared.b16 {%0,%1,%2,%3}, [%4];"
        : "=r"(r[0]),"=r"(r[1]),"=r"(r[2]),"=r"(r[3]) : "r"(addr));
}
__device__ __forceinline__ void ldsm4t(u32* r, u32 addr){
    asm volatile("ldmatrix.sync.aligned.m8n8.x4.trans.shared.b16 {%0,%1,%2,%3}, [%4];"
        : "=r"(r[0]),"=r"(r[1]),"=r"(r[2]),"=r"(r[3]) : "r"(addr));
}
__device__ __forceinline__ void mma_fp16(float* c, const u32* a, const u32* b){
    asm volatile("mma.sync.aligned.m16n8k16.row.col.f32.f16.f16.f32 "
        "{%0,%1,%2,%3}, {%4,%5,%6,%7}, {%8,%9}, {%0,%1,%2,%3};"
        : "+f"(c[0]),"+f"(c[1]),"+f"(c[2]),"+f"(c[3])
        : "r"(a[0]),"r"(a[1]),"r"(a[2]),"r"(a[3]), "r"(b[0]),"r"(b[1]));
}
__device__ __forceinline__ u32 pack_h2(float a, float b){
    __half2 H; H.x = __float2half_rn(a); H.y = __float2half_rn(b);
    return *(u32*)&H;
}
__device__ __forceinline__ void cp16(u32 dst, const void* src){
    asm volatile("cp.async.cg.shared.global [%0], [%1], 16;" :: "r"(dst), "l"(src));
}
#define CP_COMMIT() asm volatile("cp.async.commit_group;" ::: "memory")
#define CP_WAIT(n)  asm volatile("cp.async.wait_group %0;" :: "n"(n) : "memory")

// ---------------- fused prep: converts + mask dtype detect -------------------
// 2,097,152 quads total = 8192 blocks x 256 threads.
// Segments: x (1,048,576 quads) | Wqkv (786,432) | Wproj (262,144).
// Block 0 additionally classifies the mask buffer dtype (first 4096 bytes).
#define PREP_N1 (NM*ND/4)            // 1048576
#define PREP_N2 (NQKV*ND/4)          // 786432
#define PREP_N3 (ND*ND/4)            // 262144

__global__ void __launch_bounds__(256) prep_kernel(
    const float* __restrict__ x, const float* __restrict__ wq,
    const float* __restrict__ wp, const unsigned int* __restrict__ mask_w)
{
    int i = blockIdx.x * 256 + threadIdx.x;
    const float* src; __half* dst; int k;
    if (i < PREP_N1)                  { src = x;  dst = g_xf;  k = i; }
    else if (i < PREP_N1 + PREP_N2)   { src = wq; dst = g_wqf; k = i - PREP_N1; }
    else                              { src = wp; dst = g_wpf; k = i - PREP_N1 - PREP_N2; }
    float4 v = ((const float4*)src)[k];
    ((uint2*)dst)[k] = make_uint2(pack_h2(v.x, v.y), pack_h2(v.z, v.w));

    if (blockIdx.x == 0) {
        __shared__ int not_f, not_i;
        if (threadIdx.x == 0){ not_f = 0; not_i = 0; }
        __syncthreads();
        #pragma unroll
        for (int t = 0; t < 4; t++) {
            unsigned w = mask_w[threadIdx.x + 256*t];
            if (w != 0u && w != 0x3F800000u) atomicExch(&not_f, 1);
            if (w > 1u)                      atomicExch(&not_i, 1);
        }
        __syncthreads();
        if (threadIdx.x == 0)
            g_mask_mode = (not_f == 0) ? 2 : ((not_i == 0) ? 1 : 0);
    }
}

// ---------------- fp16 1-pass NT GEMM, 3-stage cp.async ----------------------
#define GSTRIDE 40
#define GMAT (128*GSTRIDE*2)   // 10240
#define GNCH (ND/32)           // 32
#define FSTAGE (2*GMAT)        // 20480
#define FSMEM  (3*FSTAGE)      // 61440

template<int QKV_EPI>
__global__ void __launch_bounds__(256) gemm_f16(
    const __half* __restrict__ A, const __half* __restrict__ B,
    const float* __restrict__ bias, float* __restrict__ Cout)
{
    extern __shared__ __align__(16) char sm[];
    const u32 smb = smem_u32(sm);
    const int tid = threadIdx.x, lane = tid & 31, wid = tid >> 5;
    const int wm = wid >> 2, wn = wid & 3;

    const __half* AP = A + (size_t)blockIdx.y * 128 * ND;
    const __half* BP = B + (size_t)blockIdx.x * 128 * ND;

    float C[4][4][4];
    #pragma unroll
    for (int i = 0; i < 4; i++)
        #pragma unroll
        for (int j = 0; j < 4; j++)
            #pragma unroll
            for (int e = 0; e < 4; e++) C[i][j][e] = 0.f;

#define F_ISSUE(k0, st) do { \
    _Pragma("unroll") \
    for (int t = 0; t < 2; t++) { \
        int u_ = tid + 256*t; int row = u_ >> 2; int cb = (u_ & 3) * 8; \
        size_t go = (size_t)row * ND + (k0) + cb; \
        u32 so = (st) + (u32)((row*GSTRIDE + cb)*2); \
        cp16(smb + so + 0*GMAT, AP + go); cp16(smb + so + 1*GMAT, BP + go); \
    } } while(0)

    F_ISSUE(0, 0u);        CP_COMMIT();
    F_ISSUE(32, FSTAGE);   CP_COMMIT();

    for (int c = 0; c < GNCH; c++) {
        if (c + 2 < GNCH) CP_WAIT(1); else CP_WAIT(0);
        __syncthreads();
        const u32 st = (u32)(c % 3) * FSTAGE;
        if (c + 2 < GNCH) { F_ISSUE((c + 2)*32, (u32)((c + 2) % 3) * FSTAGE); CP_COMMIT(); }

        #pragma unroll
        for (int kk = 0; kk < 2; kk++) {
            const u32 aoff = ((wm*64 + (lane & 15))*GSTRIDE + kk*16 + (lane >> 4)*8) * 2;
            const u32 boff = ((wn*32 + (lane & 7) + ((lane & 16) >> 1))*GSTRIDE + kk*16 + (lane & 8)) * 2;

            u32 ah[4][4], bh_[4][2];
            #pragma unroll
            for (int i = 0; i < 4; i++) ldsm4(ah[i], smb + st + 0*GMAT + aoff + i*16*GSTRIDE*2);
            #pragma unroll
            for (int jp = 0; jp < 2; jp++) {
                u32 t4[4];
                ldsm4(t4, smb + st + 1*GMAT + boff + jp*16*GSTRIDE*2);
                bh_[2*jp][0]=t4[0]; bh_[2*jp][1]=t4[1]; bh_[2*jp+1][0]=t4[2]; bh_[2*jp+1][1]=t4[3];
            }
            #pragma unroll
            for (int i = 0; i < 4; i++)
                #pragma unroll
                for (int j = 0; j < 4; j++) mma_fp16(C[i][j], ah[i], bh_[j]);
        }
    }
#undef F_ISSUE

    const int mb = blockIdx.y*128 + wm*64;
    const int nb = blockIdx.x*128 + wn*32;
    #pragma unroll
    for (int i = 0; i < 4; i++) {
        #pragma unroll
        for (int j = 0; j < 4; j++) {
            int n = nb + j*8 + 2*(lane & 3);
            float2 bz = *(const float2*)(bias + n);
            int m0 = mb + i*16 + (lane >> 2);
            int m1 = m0 + 8;
            if (QKV_EPI) {
                int h = n / 192, rem = n - h*192, part = rem >> 6, d = rem & 63;
                __half* dst = (part==0) ? g_Qf : (part==1 ? g_Kf : g_Vf);
                {
                    int bb = m0 >> 11, ss = m0 & (NS-1);
                    size_t base = (((size_t)bb*NH + h)*NS + ss)*DH + d;
                    *(u32*)&dst[base] = pack_h2(C[i][j][0] + bz.x, C[i][j][1] + bz.y);
                }
                {
                    int bb = m1 >> 11, ss = m1 & (NS-1);
                    size_t base = (((size_t)bb*NH + h)*NS + ss)*DH + d;
                    *(u32*)&dst[base] = pack_h2(C[i][j][2] + bz.x, C[i][j][3] + bz.y);
                }
            } else {
                *(float2*)&Cout[(size_t)m0*ND + n] = make_float2(C[i][j][0] + bz.x, C[i][j][1] + bz.y);
                *(float2*)&Cout[(size_t)m1*ND + n] = make_float2(C[i][j][2] + bz.x, C[i][j][3] + bz.y);
            }
        }
    }
}

// ---------------- attention: fp16, ALiBi-banded (threshold 10) ---------------
// Dropped tail mass / denominator ≈ e^-10/0.9 ≈ 5e-5 relative — negligible.
#define ASTR 72
#define ASTAGE 18432
#define AMSK  (3*ASTAGE)           // 55296
#define ASMEM (AMSK + NS*4)        // 63488
#define NCH (NS/64)                // 32

__global__ void __launch_bounds__(256) attn_mma(const void* __restrict__ maskp)
{
    extern __shared__ __align__(16) char sm[];
    const u32 smb = smem_u32(sm);
    float* mk = (float*)(sm + AMSK);
    const int tid = threadIdx.x, lane = tid & 31, wid = tid >> 5;
    const int qb = blockIdx.x, h = blockIdx.y, b = blockIdx.z;

    const size_t hb = ((size_t)(b*NH + h)) * NS * DH;
    const __half* Qp = g_Qf + hb + (size_t)qb*128*DH;
    const __half* Kp = g_Kf + hb;
    const __half* Vp = g_Vf + hb;

    const float slope = exp2f(-0.5f * (float)(h + 1));
    const int mode = g_mask_mode;

    // ALiBi band: chunk range [clo, chi], W = 10/slope
    const int W = (int)(10.f * exp2f(0.5f * (float)(h + 1)));
    const int lo = qb*128 - W, hi = qb*128 + 127 + W;
    int clo = lo < 0 ? 0 : (lo >> 6);
    int chi = hi >> 6; if (chi > NCH - 1) chi = NCH - 1;

    // stage Q through stage 0; banded mask -> mk
    #pragma unroll
    for (int t = 0; t < 4; t++) {
        int idx = tid + 256*t; int row = idx >> 3; int cb = (idx & 7) * 8;
        *(uint4*)(sm + (u32)((row*ASTR + cb)*2)) = *(const uint4*)(Qp + row*DH + cb);
    }
    {
        const int i0 = clo*64, i1 = chi*64 + 64;
        for (int i = i0 + tid; i < i1; i += 256) {
            bool mv;
            if      (mode == 0) mv = ((const unsigned char*)maskp)[b*NS + i] != 0;
            else if (mode == 1) mv = ((const int*)maskp)[b*NS + i] != 0;
            else                mv = ((const float*)maskp)[b*NS + i] != 0.f;
            mk[i] = mv ? 0.f : -1e30f;
        }
    }
    __syncthreads();

    u32 qh[4][4];
    #pragma unroll
    for (int kk = 0; kk < 4; kk++) {
        u32 off = ((wid*16 + (lane & 15))*ASTR + kk*16 + (lane >> 4)*8) * 2;
        ldsm4(qh[kk], smb + off);
    }
    __syncthreads();   // Q staging consumed; all stages reusable

#define ISSUE_ARR(ptr, aoff, stg, k0) do { \
    _Pragma("unroll") \
    for (int t = 0; t < 2; t++) { \
        int idx = tid + 256*t; int row = idx >> 3; int cb = (idx & 7) * 8; \
        cp16(smb + (stg) + (aoff) + (u32)((row*ASTR + cb)*2), \
             (ptr) + (size_t)((k0) + row)*DH + cb); \
    } } while(0)
#define ISSUE_CHUNK(k0, stg) do { \
    ISSUE_ARR(Kp, 0,    stg, k0); \
    ISSUE_ARR(Vp, 9216, stg, k0); \
    } while(0)

    float O[8][4];
    #pragma unroll
    for (int j = 0; j < 8; j++)
        #pragma unroll
        for (int e = 0; e < 4; e++) O[j][e] = 0.f;
    float dn0 = 0.f, dn1 = 0.f;
    const float qf0 = (float)(qb*128 + wid*16 + (lane >> 2));
    const float qf1 = qf0 + 8.f;

    ISSUE_CHUNK(clo*64, (u32)(clo % 3) * ASTAGE);
    CP_COMMIT();
    if (clo + 1 <= chi) {
        ISSUE_CHUNK((clo + 1)*64, (u32)((clo + 1) % 3) * ASTAGE);
        CP_COMMIT();
    }

    for (int c = clo; c <= chi; c++) {
        const int k0 = c * 64;
        if (c + 2 <= chi) CP_WAIT(1); else CP_WAIT(0);
        __syncthreads();
        const u32 stg = (u32)(c % 3) * ASTAGE;
        if (c + 2 <= chi) { ISSUE_CHUNK(k0 + 128, (u32)((c + 2) % 3) * ASTAGE); CP_COMMIT(); }

        // ---- S = Q K^T ----
        float S[8][4];
        #pragma unroll
        for (int j = 0; j < 8; j++)
            #pragma unroll
            for (int e = 0; e < 4; e++) S[j][e] = 0.f;
        #pragma unroll
        for (int kk = 0; kk < 4; kk++) {
            const u32 koff = stg + (((lane & 7) + ((lane & 16) >> 1))*ASTR + kk*16 + (lane & 8)) * 2;
            u32 kh4[4][4];
            #pragma unroll
            for (int jp = 0; jp < 4; jp++) ldsm4(kh4[jp], smb + koff + jp*16*ASTR*2);
            #pragma unroll
            for (int jp = 0; jp < 4; jp++) {
                mma_fp16(S[2*jp],   qh[kk], kh4[jp]);
                mma_fp16(S[2*jp+1], qh[kk], kh4[jp]+2);
            }
        }

        // ---- softmax + pack P fp16 ----
        u32 aPh[4][4];
        #pragma unroll
        for (int j = 0; j < 8; j++) {
            int kc = k0 + j*8 + 2*(lane & 3);
            float kf = (float)kc;
            float m0 = mk[kc], m1 = mk[kc + 1];
            float p0 = __expf(S[j][0]*ATTN_SCALE - slope*fabsf(qf0 - kf)       + m0);
            float p1 = __expf(S[j][1]*ATTN_SCALE - slope*fabsf(qf0 - kf - 1.f) + m1);
            float p2 = __expf(S[j][2]*ATTN_SCALE - slope*fabsf(qf1 - kf)       + m0);
            float p3 = __expf(S[j][3]*ATTN_SCALE - slope*fabsf(qf1 - kf - 1.f) + m1);
            dn0 += p0 + p1;
            dn1 += p2 + p3;
            int t = j >> 1, o = (j & 1) * 2;
            aPh[t][o]   = pack_h2(p0, p1);
            aPh[t][o+1] = pack_h2(p2, p3);
        }

        // ---- O += P V ----
        #pragma unroll
        for (int t = 0; t < 4; t++) {
            const u32 voff = stg + 9216 + ((t*16 + (lane & 15))*ASTR + (lane >> 4)*8) * 2;
            u32 vh4[4][4];
            #pragma unroll
            for (int jp = 0; jp < 4; jp++) ldsm4t(vh4[jp], smb + voff + jp*16*2);
            #pragma unroll
            for (int jp = 0; jp < 4; jp++) {
                mma_fp16(O[2*jp],   aPh[t], vh4[jp]);
                mma_fp16(O[2*jp+1], aPh[t], vh4[jp]+2);
            }
        }
    }
#undef ISSUE_ARR
#undef ISSUE_CHUNK

    #pragma unroll
    for (int m_ = 1; m_ < 4; m_ <<= 1) {
        dn0 += __shfl_xor_sync(0xffffffffu, dn0, m_);
        dn1 += __shfl_xor_sync(0xffffffffu, dn1, m_);
    }
    const float inv0 = 1.f / dn0, inv1 = 1.f / dn1;

    const int q0 = qb*128 + wid*16 + (lane >> 2);
    const int q1 = q0 + 8;
    #pragma unroll
    for (int j = 0; j < 8; j++) {
        int d = h*64 + j*8 + 2*(lane & 3);
        size_t b0 = ((size_t)b*NS + q0)*ND + d;
        *(u32*)&g_cf[b0] = pack_h2(O[j][0]*inv0, O[j][1]*inv0);
        size_t b1 = ((size_t)b*NS + q1)*ND + d;
        *(u32*)&g_cf[b1] = pack_h2(O[j][2]*inv1, O[j][3]*inv1);
    }
}

// ---------------- launch -----------------------------------------------------
extern "C" void kernel_launch(void* const* d_in, const int* in_sizes, int n_in,
                              void* d_out, int out_size)
{
    const float* x     = (const float*)d_in[0];
    const void*  mask  = d_in[1];
    const float* Wqkv  = (const float*)d_in[2];
    const float* bqkv  = (const float*)d_in[3];
    const float* Wproj = (const float*)d_in[4];
    const float* bproj = (const float*)d_in[5];
    float* out = (float*)d_out;

    (void)in_sizes; (void)n_in; (void)out_size;

    static bool inited = false;
    static __half *p_xf, *p_wqf, *p_wpf, *p_cf;
    if (!inited) {
        cudaFuncSetAttribute(gemm_f16<1>, cudaFuncAttributeMaxDynamicSharedMemorySize, FSMEM);
        cudaFuncSetAttribute(gemm_f16<0>, cudaFuncAttributeMaxDynamicSharedMemorySize, FSMEM);
        cudaFuncSetAttribute(attn_mma,    cudaFuncAttributeMaxDynamicSharedMemorySize, ASMEM);
        cudaGetSymbolAddress((void**)&p_xf, g_xf);
        cudaGetSymbolAddress((void**)&p_wqf, g_wqf);
        cudaGetSymbolAddress((void**)&p_wpf, g_wpf);
        cudaGetSymbolAddress((void**)&p_cf, g_cf);
        inited = true;
    }

    // fused prep: all fp32->fp16 converts + mask dtype detect (block 0)
    prep_kernel<<<(PREP_N1 + PREP_N2 + PREP_N3) / 256, 256>>>(
        x, Wqkv, Wproj, (const unsigned int*)mask);

    gemm_f16<1><<<dim3(NQKV/128, NM/128), 256, FSMEM>>>(
        p_xf, p_wqf, bqkv, nullptr);

    attn_mma<<<dim3(NS/128, NH, NB), 256, ASMEM>>>(mask);

    gemm_f16<0><<<dim3(ND/128, NM/128), 256, FSMEM>>>(
        p_cf, p_wpf, bproj, out);
}

// round 16
// speedup vs baseline: 12.0273x; 1.1206x over previous
#include <cuda_runtime.h>
#include <cuda_fp16.h>

// Problem constants
#define NB 2
#define NS 2048
#define ND 1024
#define NH 16
#define DH 64
#define NM (NB*NS)        // 4096
#define NQKV (3*ND)       // 3072
#define ATTN_SCALE 0.03125f

typedef unsigned long long u64;
typedef unsigned int u32;

// ---------------- scratch (device globals) -----------------------------------
__device__ int g_mask_mode;
__device__ __half g_xf[(size_t)NM*ND];       // x fp16
__device__ __half g_wqf[(size_t)NQKV*ND];    // Wqkv fp16
__device__ __half g_wpf[(size_t)ND*ND];      // Wproj fp16
__device__ __half g_cf[(size_t)NM*ND];       // ctx fp16
#define QKV_ELEMS (NB*NH*NS*DH)
__device__ __half g_Qf[QKV_ELEMS], g_Kf[QKV_ELEMS], g_Vf[QKV_ELEMS];

// ---------------- PTX helpers ------------------------------------------------
__device__ __forceinline__ u32 smem_u32(const void* p){
    u32 a; asm("{ .reg .u64 t; cvta.to.shared.u64 t, %1; cvt.u32.u64 %0, t; }" : "=r"(a) : "l"(p));
    return a;
}
__device__ __forceinline__ void ldsm4(u32* r, u32 addr){
    asm volatile("ldmatrix.sync.aligned.m8n8.x4.shared.b16 {%0,%1,%2,%3}, [%4];"
        : "=r"(r[0]),"=r"(r[1]),"=r"(r[2]),"=r"(r[3]) : "r"(addr));
}
__device__ __forceinline__ void ldsm4t(u32* r, u32 addr){
    asm volatile("ldmatrix.sync.aligned.m8n8.x4.trans.shared.b16 {%0,%1,%2,%3}, [%4];"
        : "=r"(r[0]),"=r"(r[1]),"=r"(r[2]),"=r"(r[3]) : "r"(addr));
}
__device__ __forceinline__ void mma_fp16(float* c, const u32* a, const u32* b){
    asm volatile("mma.sync.aligned.m16n8k16.row.col.f32.f16.f16.f32 "
        "{%0,%1,%2,%3}, {%4,%5,%6,%7}, {%8,%9}, {%0,%1,%2,%3};"
        : "+f"(c[0]),"+f"(c[1]),"+f"(c[2]),"+f"(c[3])
        : "r"(a[0]),"r"(a[1]),"r"(a[2]),"r"(a[3]), "r"(b[0]),"r"(b[1]));
}
__device__ __forceinline__ u32 pack_h2(float a, float b){
    __half2 H; H.x = __float2half_rn(a); H.y = __float2half_rn(b);
    return *(u32*)&H;
}
__device__ __forceinline__ void cp16(u32 dst, const void* src){
    asm volatile("cp.async.cg.shared.global [%0], [%1], 16;" :: "r"(dst), "l"(src));
}
#define CP_COMMIT() asm volatile("cp.async.commit_group;" ::: "memory")
#define CP_WAIT(n)  asm volatile("cp.async.wait_group %0;" :: "n"(n) : "memory")

// ---------------- fused prep: converts + mask dtype detect -------------------
#define PREP_N1 (NM*ND/4)            // 1048576
#define PREP_N2 (NQKV*ND/4)          // 786432
#define PREP_N3 (ND*ND/4)            // 262144

__global__ void __launch_bounds__(256) prep_kernel(
    const float* __restrict__ x, const float* __restrict__ wq,
    const float* __restrict__ wp, const unsigned int* __restrict__ mask_w)
{
    int i = blockIdx.x * 256 + threadIdx.x;
    const float* src; __half* dst; int k;
    if (i < PREP_N1)                  { src = x;  dst = g_xf;  k = i; }
    else if (i < PREP_N1 + PREP_N2)   { src = wq; dst = g_wqf; k = i - PREP_N1; }
    else                              { src = wp; dst = g_wpf; k = i - PREP_N1 - PREP_N2; }
    float4 v = ((const float4*)src)[k];
    ((uint2*)dst)[k] = make_uint2(pack_h2(v.x, v.y), pack_h2(v.z, v.w));

    if (blockIdx.x == 0) {
        __shared__ int not_f, not_i;
        if (threadIdx.x == 0){ not_f = 0; not_i = 0; }
        __syncthreads();
        #pragma unroll
        for (int t = 0; t < 4; t++) {
            unsigned w = mask_w[threadIdx.x + 256*t];
            if (w != 0u && w != 0x3F800000u) atomicExch(&not_f, 1);
            if (w > 1u)                      atomicExch(&not_i, 1);
        }
        __syncthreads();
        if (threadIdx.x == 0)
            g_mask_mode = (not_f == 0) ? 2 : ((not_i == 0) ? 1 : 0);
    }
}

// ---------------- fp16 1-pass NT GEMM, BK=64, 3-stage cp.async ---------------
// Padded stride 72 halves (144 B) — conflict-free ldmatrix (same as attention).
#define GSTR2 72
#define GMAT2 (128*GSTR2*2)    // 18432
#define GNCH2 (ND/64)          // 16
#define FSTAGE2 (2*GMAT2)      // 36864
#define FSMEM2  (3*FSTAGE2)    // 110592

template<int QKV_EPI>
__global__ void __launch_bounds__(256) gemm_f16(
    const __half* __restrict__ A, const __half* __restrict__ B,
    const float* __restrict__ bias, float* __restrict__ Cout)
{
    extern __shared__ __align__(16) char sm[];
    const u32 smb = smem_u32(sm);
    const int tid = threadIdx.x, lane = tid & 31, wid = tid >> 5;
    const int wm = wid >> 2, wn = wid & 3;

    const __half* AP = A + (size_t)blockIdx.y * 128 * ND;
    const __half* BP = B + (size_t)blockIdx.x * 128 * ND;

    float C[4][4][4];
    #pragma unroll
    for (int i = 0; i < 4; i++)
        #pragma unroll
        for (int j = 0; j < 4; j++)
            #pragma unroll
            for (int e = 0; e < 4; e++) C[i][j][e] = 0.f;

#define F_ISSUE(k0, st) do { \
    _Pragma("unroll") \
    for (int t = 0; t < 4; t++) { \
        int u_ = tid + 256*t; int row = u_ >> 3; int cb = (u_ & 7) * 8; \
        size_t go = (size_t)row * ND + (k0) + cb; \
        u32 so = (st) + (u32)((row*GSTR2 + cb)*2); \
        cp16(smb + so,          AP + go); \
        cp16(smb + so + GMAT2,  BP + go); \
    } } while(0)

    F_ISSUE(0, 0u);         CP_COMMIT();
    F_ISSUE(64, FSTAGE2);   CP_COMMIT();

    for (int c = 0; c < GNCH2; c++) {
        if (c + 2 < GNCH2) CP_WAIT(1); else CP_WAIT(0);
        __syncthreads();
        const u32 st = (u32)(c % 3) * FSTAGE2;
        if (c + 2 < GNCH2) { F_ISSUE((c + 2)*64, (u32)((c + 2) % 3) * FSTAGE2); CP_COMMIT(); }

        #pragma unroll
        for (int kk = 0; kk < 4; kk++) {
            const u32 aoff = ((wm*64 + (lane & 15))*GSTR2 + kk*16 + (lane >> 4)*8) * 2;
            const u32 boff = ((wn*32 + (lane & 7) + ((lane & 16) >> 1))*GSTR2 + kk*16 + (lane & 8)) * 2;

            u32 ah[4][4], bh_[4][2];
            #pragma unroll
            for (int i = 0; i < 4; i++) ldsm4(ah[i], smb + st + aoff + i*16*GSTR2*2);
            #pragma unroll
            for (int jp = 0; jp < 2; jp++) {
                u32 t4[4];
                ldsm4(t4, smb + st + GMAT2 + boff + jp*16*GSTR2*2);
                bh_[2*jp][0]=t4[0]; bh_[2*jp][1]=t4[1]; bh_[2*jp+1][0]=t4[2]; bh_[2*jp+1][1]=t4[3];
            }
            #pragma unroll
            for (int i = 0; i < 4; i++)
                #pragma unroll
                for (int j = 0; j < 4; j++) mma_fp16(C[i][j], ah[i], bh_[j]);
        }
    }
#undef F_ISSUE

    const int mb = blockIdx.y*128 + wm*64;
    const int nb = blockIdx.x*128 + wn*32;
    #pragma unroll
    for (int i = 0; i < 4; i++) {
        #pragma unroll
        for (int j = 0; j < 4; j++) {
            int n = nb + j*8 + 2*(lane & 3);
            float2 bz = *(const float2*)(bias + n);
            int m0 = mb + i*16 + (lane >> 2);
            int m1 = m0 + 8;
            if (QKV_EPI) {
                int h = n / 192, rem = n - h*192, part = rem >> 6, d = rem & 63;
                __half* dst = (part==0) ? g_Qf : (part==1 ? g_Kf : g_Vf);
                {
                    int bb = m0 >> 11, ss = m0 & (NS-1);
                    size_t base = (((size_t)bb*NH + h)*NS + ss)*DH + d;
                    *(u32*)&dst[base] = pack_h2(C[i][j][0] + bz.x, C[i][j][1] + bz.y);
                }
                {
                    int bb = m1 >> 11, ss = m1 & (NS-1);
                    size_t base = (((size_t)bb*NH + h)*NS + ss)*DH + d;
                    *(u32*)&dst[base] = pack_h2(C[i][j][2] + bz.x, C[i][j][3] + bz.y);
                }
            } else {
                *(float2*)&Cout[(size_t)m0*ND + n] = make_float2(C[i][j][0] + bz.x, C[i][j][1] + bz.y);
                *(float2*)&Cout[(size_t)m1*ND + n] = make_float2(C[i][j][2] + bz.x, C[i][j][3] + bz.y);
            }
        }
    }
}

// ---------------- attention: fp16, ALiBi-banded, LPT head order --------------
#define ASTR 72
#define ASTAGE 18432
#define AMSK  (3*ASTAGE)           // 55296
#define ASMEM (AMSK + NS*4)        // 63488
#define NCH (NS/64)                // 32

__global__ void __launch_bounds__(256) attn_mma(const void* __restrict__ maskp)
{
    extern __shared__ __align__(16) char sm[];
    const u32 smb = smem_u32(sm);
    float* mk = (float*)(sm + AMSK);
    const int tid = threadIdx.x, lane = tid & 31, wid = tid >> 5;
    // LPT: heavy heads (large h => wide band) scheduled first
    const int qb = blockIdx.x, h = (NH - 1) - blockIdx.y, b = blockIdx.z;

    const size_t hb = ((size_t)(b*NH + h)) * NS * DH;
    const __half* Qp = g_Qf + hb + (size_t)qb*128*DH;
    const __half* Kp = g_Kf + hb;
    const __half* Vp = g_Vf + hb;

    const float slope = exp2f(-0.5f * (float)(h + 1));
    const int mode = g_mask_mode;

    // ALiBi band: chunk range [clo, chi], W = 10/slope
    const int W = (int)(10.f * exp2f(0.5f * (float)(h + 1)));
    const int lo = qb*128 - W, hi = qb*128 + 127 + W;
    int clo = lo < 0 ? 0 : (lo >> 6);
    int chi = hi >> 6; if (chi > NCH - 1) chi = NCH - 1;

    // stage Q through stage 0; banded mask -> mk
    #pragma unroll
    for (int t = 0; t < 4; t++) {
        int idx = tid + 256*t; int row = idx >> 3; int cb = (idx & 7) * 8;
        *(uint4*)(sm + (u32)((row*ASTR + cb)*2)) = *(const uint4*)(Qp + row*DH + cb);
    }
    {
        const int i0 = clo*64, i1 = chi*64 + 64;
        for (int i = i0 + tid; i < i1; i += 256) {
            bool mv;
            if      (mode == 0) mv = ((const unsigned char*)maskp)[b*NS + i] != 0;
            else if (mode == 1) mv = ((const int*)maskp)[b*NS + i] != 0;
            else                mv = ((const float*)maskp)[b*NS + i] != 0.f;
            mk[i] = mv ? 0.f : -1e30f;
        }
    }
    __syncthreads();

    u32 qh[4][4];
    #pragma unroll
    for (int kk = 0; kk < 4; kk++) {
        u32 off = ((wid*16 + (lane & 15))*ASTR + kk*16 + (lane >> 4)*8) * 2;
        ldsm4(qh[kk], smb + off);
    }
    __syncthreads();   // Q staging consumed; all stages reusable

#define ISSUE_ARR(ptr, aoff, stg, k0) do { \
    _Pragma("unroll") \
    for (int t = 0; t < 2; t++) { \
        int idx = tid + 256*t; int row = idx >> 3; int cb = (idx & 7) * 8; \
        cp16(smb + (stg) + (aoff) + (u32)((row*ASTR + cb)*2), \
             (ptr) + (size_t)((k0) + row)*DH + cb); \
    } } while(0)
#define ISSUE_CHUNK(k0, stg) do { \
    ISSUE_ARR(Kp, 0,    stg, k0); \
    ISSUE_ARR(Vp, 9216, stg, k0); \
    } while(0)

    float O[8][4];
    #pragma unroll
    for (int j = 0; j < 8; j++)
        #pragma unroll
        for (int e = 0; e < 4; e++) O[j][e] = 0.f;
    float dn0 = 0.f, dn1 = 0.f;
    const float qf0 = (float)(qb*128 + wid*16 + (lane >> 2));
    const float qf1 = qf0 + 8.f;

    ISSUE_CHUNK(clo*64, (u32)(clo % 3) * ASTAGE);
    CP_COMMIT();
    if (clo + 1 <= chi) {
        ISSUE_CHUNK((clo + 1)*64, (u32)((clo + 1) % 3) * ASTAGE);
        CP_COMMIT();
    }

    for (int c = clo; c <= chi; c++) {
        const int k0 = c * 64;
        if (c + 2 <= chi) CP_WAIT(1); else CP_WAIT(0);
        __syncthreads();
        const u32 stg = (u32)(c % 3) * ASTAGE;
        if (c + 2 <= chi) { ISSUE_CHUNK(k0 + 128, (u32)((c + 2) % 3) * ASTAGE); CP_COMMIT(); }

        // ---- S = Q K^T ----
        float S[8][4];
        #pragma unroll
        for (int j = 0; j < 8; j++)
            #pragma unroll
            for (int e = 0; e < 4; e++) S[j][e] = 0.f;
        #pragma unroll
        for (int kk = 0; kk < 4; kk++) {
            const u32 koff = stg + (((lane & 7) + ((lane & 16) >> 1))*ASTR + kk*16 + (lane & 8)) * 2;
            u32 kh4[4][4];
            #pragma unroll
            for (int jp = 0; jp < 4; jp++) ldsm4(kh4[jp], smb + koff + jp*16*ASTR*2);
            #pragma unroll
            for (int jp = 0; jp < 4; jp++) {
                mma_fp16(S[2*jp],   qh[kk], kh4[jp]);
                mma_fp16(S[2*jp+1], qh[kk], kh4[jp]+2);
            }
        }

        // ---- softmax + pack P fp16 ----
        u32 aPh[4][4];
        #pragma unroll
        for (int j = 0; j < 8; j++) {
            int kc = k0 + j*8 + 2*(lane & 3);
            float kf = (float)kc;
            float m0 = mk[kc], m1 = mk[kc + 1];
            float p0 = __expf(S[j][0]*ATTN_SCALE - slope*fabsf(qf0 - kf)       + m0);
            float p1 = __expf(S[j][1]*ATTN_SCALE - slope*fabsf(qf0 - kf - 1.f) + m1);
            float p2 = __expf(S[j][2]*ATTN_SCALE - slope*fabsf(qf1 - kf)       + m0);
            float p3 = __expf(S[j][3]*ATTN_SCALE - slope*fabsf(qf1 - kf - 1.f) + m1);
            dn0 += p0 + p1;
            dn1 += p2 + p3;
            int t = j >> 1, o = (j & 1) * 2;
            aPh[t][o]   = pack_h2(p0, p1);
            aPh[t][o+1] = pack_h2(p2, p3);
        }

        // ---- O += P V ----
        #pragma unroll
        for (int t = 0; t < 4; t++) {
            const u32 voff = stg + 9216 + ((t*16 + (lane & 15))*ASTR + (lane >> 4)*8) * 2;
            u32 vh4[4][4];
            #pragma unroll
            for (int jp = 0; jp < 4; jp++) ldsm4t(vh4[jp], smb + voff + jp*16*2);
            #pragma unroll
            for (int jp = 0; jp < 4; jp++) {
                mma_fp16(O[2*jp],   aPh[t], vh4[jp]);
                mma_fp16(O[2*jp+1], aPh[t], vh4[jp]+2);
            }
        }
    }
#undef ISSUE_ARR
#undef ISSUE_CHUNK

    #pragma unroll
    for (int m_ = 1; m_ < 4; m_ <<= 1) {
        dn0 += __shfl_xor_sync(0xffffffffu, dn0, m_);
        dn1 += __shfl_xor_sync(0xffffffffu, dn1, m_);
    }
    const float inv0 = 1.f / dn0, inv1 = 1.f / dn1;

    const int q0 = qb*128 + wid*16 + (lane >> 2);
    const int q1 = q0 + 8;
    #pragma unroll
    for (int j = 0; j < 8; j++) {
        int d = h*64 + j*8 + 2*(lane & 3);
        size_t b0 = ((size_t)b*NS + q0)*ND + d;
        *(u32*)&g_cf[b0] = pack_h2(O[j][0]*inv0, O[j][1]*inv0);
        size_t b1 = ((size_t)b*NS + q1)*ND + d;
        *(u32*)&g_cf[b1] = pack_h2(O[j][2]*inv1, O[j][3]*inv1);
    }
}

// ---------------- launch -----------------------------------------------------
extern "C" void kernel_launch(void* const* d_in, const int* in_sizes, int n_in,
                              void* d_out, int out_size)
{
    const float* x     = (const float*)d_in[0];
    const void*  mask  = d_in[1];
    const float* Wqkv  = (const float*)d_in[2];
    const float* bqkv  = (const float*)d_in[3];
    const float* Wproj = (const float*)d_in[4];
    const float* bproj = (const float*)d_in[5];
    float* out = (float*)d_out;

    (void)in_sizes; (void)n_in; (void)out_size;

    static bool inited = false;
    static __half *p_xf, *p_wqf, *p_wpf, *p_cf;
    if (!inited) {
        cudaFuncSetAttribute(gemm_f16<1>, cudaFuncAttributeMaxDynamicSharedMemorySize, FSMEM2);
        cudaFuncSetAttribute(gemm_f16<0>, cudaFuncAttributeMaxDynamicSharedMemorySize, FSMEM2);
        cudaFuncSetAttribute(attn_mma,    cudaFuncAttributeMaxDynamicSharedMemorySize, ASMEM);
        cudaGetSymbolAddress((void**)&p_xf, g_xf);
        cudaGetSymbolAddress((void**)&p_wqf, g_wqf);
        cudaGetSymbolAddress((void**)&p_wpf, g_wpf);
        cudaGetSymbolAddress((void**)&p_cf, g_cf);
        inited = true;
    }

    prep_kernel<<<(PREP_N1 + PREP_N2 + PREP_N3) / 256, 256>>>(
        x, Wqkv, Wproj, (const unsigned int*)mask);

    gemm_f16<1><<<dim3(NQKV/128, NM/128), 256, FSMEM2>>>(
        p_xf, p_wqf, bqkv, nullptr);

    attn_mma<<<dim3(NS/128, NH, NB), 256, ASMEM>>>(mask);

    gemm_f16<0><<<dim3(ND/128, NM/128), 256, FSMEM2>>>(
        p_cf, p_wpf, bproj, out);
}

// round 17
// speedup vs baseline: 12.1415x; 1.0095x over previous
#include <cuda_runtime.h>
#include <cuda_fp16.h>

// Problem constants
#define NB 2
#define NS 2048
#define ND 1024
#define NH 16
#define DH 64
#define NM (NB*NS)        // 4096
#define NQKV (3*ND)       // 3072
#define ATTN_SCALE 0.03125f

typedef unsigned long long u64;
typedef unsigned int u32;

// ---------------- scratch (device globals) -----------------------------------
__device__ int g_mask_mode;
__device__ __half g_xf[(size_t)NM*ND];       // x fp16
__device__ __half g_wqf[(size_t)NQKV*ND];    // Wqkv fp16
__device__ __half g_wpf[(size_t)ND*ND];      // Wproj fp16
__device__ __half g_cf[(size_t)NM*ND];       // ctx fp16
#define QKV_ELEMS (NB*NH*NS*DH)
__device__ __half g_Qf[QKV_ELEMS], g_Kf[QKV_ELEMS], g_Vf[QKV_ELEMS];

// ---------------- PTX helpers ------------------------------------------------
__device__ __forceinline__ u32 smem_u32(const void* p){
    u32 a; asm("{ .reg .u64 t; cvta.to.shared.u64 t, %1; cvt.u32.u64 %0, t; }" : "=r"(a) : "l"(p));
    return a;
}
__device__ __forceinline__ void ldsm4(u32* r, u32 addr){
    asm volatile("ldmatrix.sync.aligned.m8n8.x4.shared.b16 {%0,%1,%2,%3}, [%4];"
        : "=r"(r[0]),"=r"(r[1]),"=r"(r[2]),"=r"(r[3]) : "r"(addr));
}
__device__ __forceinline__ void ldsm4t(u32* r, u32 addr){
    asm volatile("ldmatrix.sync.aligned.m8n8.x4.trans.shared.b16 {%0,%1,%2,%3}, [%4];"
        : "=r"(r[0]),"=r"(r[1]),"=r"(r[2]),"=r"(r[3]) : "r"(addr));
}
__device__ __forceinline__ void mma_fp16(float* c, const u32* a, const u32* b){
    asm volatile("mma.sync.aligned.m16n8k16.row.col.f32.f16.f16.f32 "
        "{%0,%1,%2,%3}, {%4,%5,%6,%7}, {%8,%9}, {%0,%1,%2,%3};"
        : "+f"(c[0]),"+f"(c[1]),"+f"(c[2]),"+f"(c[3])
        : "r"(a[0]),"r"(a[1]),"r"(a[2]),"r"(a[3]), "r"(b[0]),"r"(b[1]));
}
__device__ __forceinline__ u32 pack_h2(float a, float b){
    __half2 H; H.x = __float2half_rn(a); H.y = __float2half_rn(b);
    return *(u32*)&H;
}
__device__ __forceinline__ void cp16(u32 dst, const void* src){
    asm volatile("cp.async.cg.shared.global [%0], [%1], 16;" :: "r"(dst), "l"(src));
}
#define CP_COMMIT() asm volatile("cp.async.commit_group;" ::: "memory")
#define CP_WAIT(n)  asm volatile("cp.async.wait_group %0;" :: "n"(n) : "memory")

// ---------------- fused prep: converts + mask dtype detect -------------------
#define PREP_N1 (NM*ND/4)            // 1048576
#define PREP_N2 (NQKV*ND/4)          // 786432
#define PREP_N3 (ND*ND/4)            // 262144

__global__ void __launch_bounds__(256) prep_kernel(
    const float* __restrict__ x, const float* __restrict__ wq,
    const float* __restrict__ wp, const unsigned int* __restrict__ mask_w)
{
    int i = blockIdx.x * 256 + threadIdx.x;
    const float* src; __half* dst; int k;
    if (i < PREP_N1)                  { src = x;  dst = g_xf;  k = i; }
    else if (i < PREP_N1 + PREP_N2)   { src = wq; dst = g_wqf; k = i - PREP_N1; }
    else                              { src = wp; dst = g_wpf; k = i - PREP_N1 - PREP_N2; }
    float4 v = ((const float4*)src)[k];
    ((uint2*)dst)[k] = make_uint2(pack_h2(v.x, v.y), pack_h2(v.z, v.w));

    if (blockIdx.x == 0) {
        __shared__ int not_f, not_i;
        if (threadIdx.x == 0){ not_f = 0; not_i = 0; }
        __syncthreads();
        #pragma unroll
        for (int t = 0; t < 4; t++) {
            unsigned w = mask_w[threadIdx.x + 256*t];
            if (w != 0u && w != 0x3F800000u) atomicExch(&not_f, 1);
            if (w > 1u)                      atomicExch(&not_i, 1);
        }
        __syncthreads();
        if (threadIdx.x == 0)
            g_mask_mode = (not_f == 0) ? 2 : ((not_i == 0) ? 1 : 0);
    }
}

// ---------------- fp16 GEMM: 512 thr / 16 warps, warp tile 32x32, BK=64 ------
#define GSTR2 72
#define GMAT2 (128*GSTR2*2)    // 18432
#define GNCH2 (ND/64)          // 16
#define FSTAGE2 (2*GMAT2)      // 36864
#define FSMEM2  (3*FSTAGE2)    // 110592

template<int QKV_EPI>
__global__ void __launch_bounds__(512, 2) gemm_f16(
    const __half* __restrict__ A, const __half* __restrict__ B,
    const float* __restrict__ bias, float* __restrict__ Cout)
{
    extern __shared__ __align__(16) char sm[];
    const u32 smb = smem_u32(sm);
    const int tid = threadIdx.x, lane = tid & 31, wid = tid >> 5;
    const int wm = wid >> 2, wn = wid & 3;   // 4x4 warp grid, warp tile 32x32

    const __half* AP = A + (size_t)blockIdx.y * 128 * ND;
    const __half* BP = B + (size_t)blockIdx.x * 128 * ND;

    float C[2][4][4];
    #pragma unroll
    for (int i = 0; i < 2; i++)
        #pragma unroll
        for (int j = 0; j < 4; j++)
            #pragma unroll
            for (int e = 0; e < 4; e++) C[i][j][e] = 0.f;

#define F_ISSUE(k0, st) do { \
    _Pragma("unroll") \
    for (int t = 0; t < 2; t++) { \
        int u_ = tid + 512*t; int row = u_ >> 3; int cb = (u_ & 7) * 8; \
        size_t go = (size_t)row * ND + (k0) + cb; \
        u32 so = (st) + (u32)((row*GSTR2 + cb)*2); \
        cp16(smb + so,          AP + go); \
        cp16(smb + so + GMAT2,  BP + go); \
    } } while(0)

    F_ISSUE(0, 0u);         CP_COMMIT();
    F_ISSUE(64, FSTAGE2);   CP_COMMIT();

    for (int c = 0; c < GNCH2; c++) {
        if (c + 2 < GNCH2) CP_WAIT(1); else CP_WAIT(0);
        __syncthreads();
        const u32 st = (u32)(c % 3) * FSTAGE2;
        if (c + 2 < GNCH2) { F_ISSUE((c + 2)*64, (u32)((c + 2) % 3) * FSTAGE2); CP_COMMIT(); }

        #pragma unroll
        for (int kk = 0; kk < 4; kk++) {
            const u32 aoff = ((wm*32 + (lane & 15))*GSTR2 + kk*16 + (lane >> 4)*8) * 2;
            const u32 boff = ((wn*32 + (lane & 7) + ((lane & 16) >> 1))*GSTR2 + kk*16 + (lane & 8)) * 2;

            u32 ah[2][4], bh_[4][2];
            #pragma unroll
            for (int i = 0; i < 2; i++) ldsm4(ah[i], smb + st + aoff + i*16*GSTR2*2);
            #pragma unroll
            for (int jp = 0; jp < 2; jp++) {
                u32 t4[4];
                ldsm4(t4, smb + st + GMAT2 + boff + jp*16*GSTR2*2);
                bh_[2*jp][0]=t4[0]; bh_[2*jp][1]=t4[1]; bh_[2*jp+1][0]=t4[2]; bh_[2*jp+1][1]=t4[3];
            }
            #pragma unroll
            for (int i = 0; i < 2; i++)
                #pragma unroll
                for (int j = 0; j < 4; j++) mma_fp16(C[i][j], ah[i], bh_[j]);
        }
    }
#undef F_ISSUE

    const int mb = blockIdx.y*128 + wm*32;
    const int nb = blockIdx.x*128 + wn*32;
    #pragma unroll
    for (int i = 0; i < 2; i++) {
        #pragma unroll
        for (int j = 0; j < 4; j++) {
            int n = nb + j*8 + 2*(lane & 3);
            float2 bz = *(const float2*)(bias + n);
            int m0 = mb + i*16 + (lane >> 2);
            int m1 = m0 + 8;
            if (QKV_EPI) {
                int h = n / 192, rem = n - h*192, part = rem >> 6, d = rem & 63;
                __half* dst = (part==0) ? g_Qf : (part==1 ? g_Kf : g_Vf);
                {
                    int bb = m0 >> 11, ss = m0 & (NS-1);
                    size_t base = (((size_t)bb*NH + h)*NS + ss)*DH + d;
                    *(u32*)&dst[base] = pack_h2(C[i][j][0] + bz.x, C[i][j][1] + bz.y);
                }
                {
                    int bb = m1 >> 11, ss = m1 & (NS-1);
                    size_t base = (((size_t)bb*NH + h)*NS + ss)*DH + d;
                    *(u32*)&dst[base] = pack_h2(C[i][j][2] + bz.x, C[i][j][3] + bz.y);
                }
            } else {
                *(float2*)&Cout[(size_t)m0*ND + n] = make_float2(C[i][j][0] + bz.x, C[i][j][1] + bz.y);
                *(float2*)&Cout[(size_t)m1*ND + n] = make_float2(C[i][j][2] + bz.x, C[i][j][3] + bz.y);
            }
        }
    }
}

// ---------------- attention: fp16, ALiBi-banded, LPT head order --------------
#define ASTR 72
#define ASTAGE 18432
#define AMSK  (3*ASTAGE)           // 55296
#define ASMEM (AMSK + NS*4)        // 63488
#define NCH (NS/64)                // 32

__global__ void __launch_bounds__(256) attn_mma(const void* __restrict__ maskp)
{
    extern __shared__ __align__(16) char sm[];
    const u32 smb = smem_u32(sm);
    float* mk = (float*)(sm + AMSK);
    const int tid = threadIdx.x, lane = tid & 31, wid = tid >> 5;
    const int qb = blockIdx.x, h = (NH - 1) - blockIdx.y, b = blockIdx.z;

    const size_t hb = ((size_t)(b*NH + h)) * NS * DH;
    const __half* Qp = g_Qf + hb + (size_t)qb*128*DH;
    const __half* Kp = g_Kf + hb;
    const __half* Vp = g_Vf + hb;

    const float slope = exp2f(-0.5f * (float)(h + 1));
    const int mode = g_mask_mode;

    const int W = (int)(10.f * exp2f(0.5f * (float)(h + 1)));
    const int lo = qb*128 - W, hi = qb*128 + 127 + W;
    int clo = lo < 0 ? 0 : (lo >> 6);
    int chi = hi >> 6; if (chi > NCH - 1) chi = NCH - 1;

    #pragma unroll
    for (int t = 0; t < 4; t++) {
        int idx = tid + 256*t; int row = idx >> 3; int cb = (idx & 7) * 8;
        *(uint4*)(sm + (u32)((row*ASTR + cb)*2)) = *(const uint4*)(Qp + row*DH + cb);
    }
    {
        const int i0 = clo*64, i1 = chi*64 + 64;
        for (int i = i0 + tid; i < i1; i += 256) {
            bool mv;
            if      (mode == 0) mv = ((const unsigned char*)maskp)[b*NS + i] != 0;
            else if (mode == 1) mv = ((const int*)maskp)[b*NS + i] != 0;
            else                mv = ((const float*)maskp)[b*NS + i] != 0.f;
            mk[i] = mv ? 0.f : -1e30f;
        }
    }
    __syncthreads();

    u32 qh[4][4];
    #pragma unroll
    for (int kk = 0; kk < 4; kk++) {
        u32 off = ((wid*16 + (lane & 15))*ASTR + kk*16 + (lane >> 4)*8) * 2;
        ldsm4(qh[kk], smb + off);
    }
    __syncthreads();

#define ISSUE_ARR(ptr, aoff, stg, k0) do { \
    _Pragma("unroll") \
    for (int t = 0; t < 2; t++) { \
        int idx = tid + 256*t; int row = idx >> 3; int cb = (idx & 7) * 8; \
        cp16(smb + (stg) + (aoff) + (u32)((row*ASTR + cb)*2), \
             (ptr) + (size_t)((k0) + row)*DH + cb); \
    } } while(0)
#define ISSUE_CHUNK(k0, stg) do { \
    ISSUE_ARR(Kp, 0,    stg, k0); \
    ISSUE_ARR(Vp, 9216, stg, k0); \
    } while(0)

    float O[8][4];
    #pragma unroll
    for (int j = 0; j < 8; j++)
        #pragma unroll
        for (int e = 0; e < 4; e++) O[j][e] = 0.f;
    float dn0 = 0.f, dn1 = 0.f;
    const float qf0 = (float)(qb*128 + wid*16 + (lane >> 2));
    const float qf1 = qf0 + 8.f;

    ISSUE_CHUNK(clo*64, (u32)(clo % 3) * ASTAGE);
    CP_COMMIT();
    if (clo + 1 <= chi) {
        ISSUE_CHUNK((clo + 1)*64, (u32)((clo + 1) % 3) * ASTAGE);
        CP_COMMIT();
    }

    for (int c = clo; c <= chi; c++) {
        const int k0 = c * 64;
        if (c + 2 <= chi) CP_WAIT(1); else CP_WAIT(0);
        __syncthreads();
        const u32 stg = (u32)(c % 3) * ASTAGE;
        if (c + 2 <= chi) { ISSUE_CHUNK(k0 + 128, (u32)((c + 2) % 3) * ASTAGE); CP_COMMIT(); }

        float S[8][4];
        #pragma unroll
        for (int j = 0; j < 8; j++)
            #pragma unroll
            for (int e = 0; e < 4; e++) S[j][e] = 0.f;
        #pragma unroll
        for (int kk = 0; kk < 4; kk++) {
            const u32 koff = stg + (((lane & 7) + ((lane & 16) >> 1))*ASTR + kk*16 + (lane & 8)) * 2;
            u32 kh4[4][4];
            #pragma unroll
            for (int jp = 0; jp < 4; jp++) ldsm4(kh4[jp], smb + koff + jp*16*ASTR*2);
            #pragma unroll
            for (int jp = 0; jp < 4; jp++) {
                mma_fp16(S[2*jp],   qh[kk], kh4[jp]);
                mma_fp16(S[2*jp+1], qh[kk], kh4[jp]+2);
            }
        }

        u32 aPh[4][4];
        #pragma unroll
        for (int j = 0; j < 8; j++) {
            int kc = k0 + j*8 + 2*(lane & 3);
            float kf = (float)kc;
            float m0 = mk[kc], m1 = mk[kc + 1];
            float p0 = __expf(S[j][0]*ATTN_SCALE - slope*fabsf(qf0 - kf)       + m0);
            float p1 = __expf(S[j][1]*ATTN_SCALE - slope*fabsf(qf0 - kf - 1.f) + m1);
            float p2 = __expf(S[j][2]*ATTN_SCALE - slope*fabsf(qf1 - kf)       + m0);
            float p3 = __expf(S[j][3]*ATTN_SCALE - slope*fabsf(qf1 - kf - 1.f) + m1);
            dn0 += p0 + p1;
            dn1 += p2 + p3;
            int t = j >> 1, o = (j & 1) * 2;
            aPh[t][o]   = pack_h2(p0, p1);
            aPh[t][o+1] = pack_h2(p2, p3);
        }

        #pragma unroll
        for (int t = 0; t < 4; t++) {
            const u32 voff = stg + 9216 + ((t*16 + (lane & 15))*ASTR + (lane >> 4)*8) * 2;
            u32 vh4[4][4];
            #pragma unroll
            for (int jp = 0; jp < 4; jp++) ldsm4t(vh4[jp], smb + voff + jp*16*2);
            #pragma unroll
            for (int jp = 0; jp < 4; jp++) {
                mma_fp16(O[2*jp],   aPh[t], vh4[jp]);
                mma_fp16(O[2*jp+1], aPh[t], vh4[jp]+2);
            }
        }
    }
#undef ISSUE_ARR
#undef ISSUE_CHUNK

    #pragma unroll
    for (int m_ = 1; m_ < 4; m_ <<= 1) {
        dn0 += __shfl_xor_sync(0xffffffffu, dn0, m_);
        dn1 += __shfl_xor_sync(0xffffffffu, dn1, m_);
    }
    const float inv0 = 1.f / dn0, inv1 = 1.f / dn1;

    const int q0 = qb*128 + wid*16 + (lane >> 2);
    const int q1 = q0 + 8;
    #pragma unroll
    for (int j = 0; j < 8; j++) {
        int d = h*64 + j*8 + 2*(lane & 3);
        size_t b0 = ((size_t)b*NS + q0)*ND + d;
        *(u32*)&g_cf[b0] = pack_h2(O[j][0]*inv0, O[j][1]*inv0);
        size_t b1 = ((size_t)b*NS + q1)*ND + d;
        *(u32*)&g_cf[b1] = pack_h2(O[j][2]*inv1, O[j][3]*inv1);
    }
}

// ---------------- launch -----------------------------------------------------
extern "C" void kernel_launch(void* const* d_in, const int* in_sizes, int n_in,
                              void* d_out, int out_size)
{
    const float* x     = (const float*)d_in[0];
    const void*  mask  = d_in[1];
    const float* Wqkv  = (const float*)d_in[2];
    const float* bqkv  = (const float*)d_in[3];
    const float* Wproj = (const float*)d_in[4];
    const float* bproj = (const float*)d_in[5];
    float* out = (float*)d_out;

    (void)in_sizes; (void)n_in; (void)out_size;

    static bool inited = false;
    static __half *p_xf, *p_wqf, *p_wpf, *p_cf;
    if (!inited) {
        cudaFuncSetAttribute(gemm_f16<1>, cudaFuncAttributeMaxDynamicSharedMemorySize, FSMEM2);
        cudaFuncSetAttribute(gemm_f16<0>, cudaFuncAttributeMaxDynamicSharedMemorySize, FSMEM2);
        cudaFuncSetAttribute(attn_mma,    cudaFuncAttributeMaxDynamicSharedMemorySize, ASMEM);
        cudaGetSymbolAddress((void**)&p_xf, g_xf);
        cudaGetSymbolAddress((void**)&p_wqf, g_wqf);
        cudaGetSymbolAddress((void**)&p_wpf, g_wpf);
        cudaGetSymbolAddress((void**)&p_cf, g_cf);
        inited = true;
    }

    prep_kernel<<<(PREP_N1 + PREP_N2 + PREP_N3) / 256, 256>>>(
        x, Wqkv, Wproj, (const unsigned int*)mask);

    gemm_f16<1><<<dim3(NQKV/128, NM/128), 512, FSMEM2>>>(
        p_xf, p_wqf, bqkv, nullptr);

    attn_mma<<<dim3(NS/128, NH, NB), 256, ASMEM>>>(mask);

    gemm_f16<0><<<dim3(ND/128, NM/128), 512, FSMEM2>>>(
        p_cf, p_wpf, bproj, out);
}